// round 3
// baseline (speedup 1.0000x reference)
#include <cuda_runtime.h>
#include <cstdint>

#define T_ 4
#define B_ 32
#define C_ 512
#define N_ 256
#define H_ 8
#define D_ 64
#define BCN_ (B_*C_*N_)        // 4,194,304
#define TBCN_ (T_*BCN_)        // 16,777,216

// ---- scratch (device globals: allocation-free per harness rules) ----
__device__ float g_xs[TBCN_];
__device__ float g_q[TBCN_];
__device__ float g_k[TBCN_];
__device__ float g_v[TBCN_];
__device__ float g_kv[T_*B_*H_*D_*D_];   // 4,194,304
__device__ float g_s[TBCN_];

typedef unsigned long long u64;

// packed fp32x2 FMA: two independent rn-rounded fp32 FMAs per issue slot.
__device__ __forceinline__ void fma2(u64 &d, u64 a, u64 b) {
    asm("fma.rn.f32x2 %0, %1, %2, %0;" : "+l"(d) : "l"(a), "l"(b));
}
__device__ __forceinline__ u64 pack2(float x, float y) {
    u64 r; asm("mov.b64 %0, {%1, %2};" : "=l"(r) : "f"(x), "f"(y)); return r;
}
__device__ __forceinline__ float2 unpack2(u64 v) {
    float2 f; asm("mov.b64 {%0, %1}, %2;" : "=f"(f.x), "=f"(f.y) : "l"(v)); return f;
}

struct QKVArgs {
    const float* w[3];
    const float* gm[3];
    const float* bt[3];
    const float* mu[3];
    const float* var[3];
};

// LIF step exactly mirroring reference rounding: v = v + (x - v)/2; s = (v - vth >= 0); hard reset.
__device__ __forceinline__ float lif_step(float& v, float x, float vth) {
    v += (x - v) * 0.5f;
    float s = (v >= vth) ? 1.0f : 0.0f;
    if (s != 0.0f) v = 0.0f;
    return s;
}

// 4x4 outer-product micro-tile via 8 packed FMA2s.
// A: u64[4][2] accumulators (rows i, col-pairs {0,1},{2,3})
#define FMA16_P(A, pa0, pa1, pa2, pa3, b01, b23) do { \
    fma2(A[0][0], pa0, b01); fma2(A[0][1], pa0, b23); \
    fma2(A[1][0], pa1, b01); fma2(A[1][1], pa1, b23); \
    fma2(A[2][0], pa2, b01); fma2(A[2][1], pa2, b23); \
    fma2(A[3][0], pa3, b01); fma2(A[3][1], pa3, b23); \
} while (0)

// ============================================================
// K1: proj_lif on x -> binary xs.  One thread = 4 (b,c,n) elems.
// ============================================================
__global__ void lif_x_kernel(const float* __restrict__ x) {
    int i = blockIdx.x * blockDim.x + threadIdx.x;   // over BCN_/4
    const float4* x4 = (const float4*)x;
    float4* o4 = (float4*)g_xs;
    float vx = 0.f, vy = 0.f, vz = 0.f, vw = 0.f;
    #pragma unroll
    for (int t = 0; t < T_; t++) {
        float4 xv = x4[(size_t)t * (BCN_/4) + i];
        float4 s;
        s.x = lif_step(vx, xv.x, 1.0f);
        s.y = lif_step(vy, xv.y, 1.0f);
        s.z = lif_step(vz, xv.z, 1.0f);
        s.w = lif_step(vw, xv.w, 1.0f);
        o4[(size_t)t * (BCN_/4) + i] = s;
    }
}

// ============================================================
// K2: q/k/v branch: Y = W @ xs per (t,b), BN, LIF over T.
// grid.x = 4(ntile) * 8(otile) * 32(b) = 1024, grid.y = branch.
// Block 256 thr, 64x64 tile, all 4 timesteps accumulated together.
// ============================================================
__global__ __launch_bounds__(256) void qkv_kernel(QKVArgs args) {
    __shared__ float  Ws[32][68];        // [k][o] transposed, padded
    __shared__ float4 Xs[T_][32][16];    // [t][k][n4]

    int br = blockIdx.y;
    int bx = blockIdx.x;
    int ntile = bx & 3, otile = (bx >> 2) & 7, b = bx >> 5;
    int tid = threadIdx.x;
    int ty = tid >> 4, tx = tid & 15;
    int oB = otile * 64, nB = ntile * 64;
    const float* __restrict__ W = args.w[br];

    u64 acc[T_][4][2];
    #pragma unroll
    for (int t = 0; t < T_; t++)
        #pragma unroll
        for (int i = 0; i < 4; i++) { acc[t][i][0] = 0ull; acc[t][i][1] = 0ull; }

    for (int kc = 0; kc < C_; kc += 32) {
        #pragma unroll
        for (int r = 0; r < 2; r++) {              // W tile: 64o x 32k = 512 float4
            int i = tid + r * 256;
            int o = i >> 3, kq = i & 7;
            float4 wv = *(const float4*)(W + (size_t)(oB + o) * C_ + kc + kq * 4);
            Ws[kq*4+0][o] = wv.x; Ws[kq*4+1][o] = wv.y;
            Ws[kq*4+2][o] = wv.z; Ws[kq*4+3][o] = wv.w;
        }
        #pragma unroll
        for (int r = 0; r < 8; r++) {              // X tiles: 4t x 32k x 64n = 2048 float4
            int i = tid + r * 256;
            int t = i >> 9, rem = i & 511, k = rem >> 4, n4 = rem & 15;
            Xs[t][k][n4] = *(const float4*)(g_xs +
                ((size_t)(t * B_ + b) * C_ + (kc + k)) * N_ + nB + n4 * 4);
        }
        __syncthreads();
        #pragma unroll 4
        for (int k = 0; k < 32; k++) {
            float4 a4 = *(const float4*)(&Ws[k][ty * 4]);
            u64 pa0 = pack2(a4.x, a4.x), pa1 = pack2(a4.y, a4.y);
            u64 pa2 = pack2(a4.z, a4.z), pa3 = pack2(a4.w, a4.w);
            #pragma unroll
            for (int t = 0; t < T_; t++) {
                float4 b4 = Xs[t][k][tx];
                u64 b01 = pack2(b4.x, b4.y), b23 = pack2(b4.z, b4.w);
                FMA16_P(acc[t], pa0, pa1, pa2, pa3, b01, b23);
            }
        }
        __syncthreads();
    }

    // BN params per output row (mirror reference: (y - m) * (g / sqrt(v+eps)) + b)
    float scl[4], mean[4], beta[4];
    #pragma unroll
    for (int i = 0; i < 4; i++) {
        int o = oB + ty * 4 + i;
        scl[i]  = args.gm[br][o] / sqrtf(args.var[br][o] + 1e-5f);
        mean[i] = args.mu[br][o];
        beta[i] = args.bt[br][o];
    }
    float* outp = (br == 0) ? g_q : (br == 1) ? g_k : g_v;

    float vm[4][4];
    #pragma unroll
    for (int i = 0; i < 4; i++)
        #pragma unroll
        for (int j = 0; j < 4; j++) vm[i][j] = 0.f;

    #pragma unroll
    for (int t = 0; t < T_; t++) {
        #pragma unroll
        for (int i = 0; i < 4; i++) {
            float2 c01 = unpack2(acc[t][i][0]);
            float2 c23 = unpack2(acc[t][i][1]);
            float4 sp;
            float y;
            y = (c01.x - mean[i]) * scl[i] + beta[i]; sp.x = lif_step(vm[i][0], y, 1.0f);
            y = (c01.y - mean[i]) * scl[i] + beta[i]; sp.y = lif_step(vm[i][1], y, 1.0f);
            y = (c23.x - mean[i]) * scl[i] + beta[i]; sp.z = lif_step(vm[i][2], y, 1.0f);
            y = (c23.y - mean[i]) * scl[i] + beta[i]; sp.w = lif_step(vm[i][3], y, 1.0f);
            *(float4*)(outp + ((size_t)(t * B_ + b) * C_ + oB + ty * 4 + i) * N_ + nB + tx * 4) = sp;
        }
    }
}

// ============================================================
// K3a: kv[d,e] = sum_n k[n,d] * v[n,e] per (t,b,h).  1024 blocks.
// ============================================================
__global__ __launch_bounds__(256) void kv_kernel() {
    __shared__ float Ks[64][68];   // [n][d] transposed
    __shared__ float Vs[64][68];   // [n][e] transposed

    int tbh = blockIdx.x;                  // ((t*B+b)*H + h)
    int tb = tbh >> 3, hh = tbh & 7;
    size_t base = ((size_t)tb * C_ + hh * D_) * N_;
    int tid = threadIdx.x, ty = tid >> 4, tx = tid & 15;

    u64 acc[4][2];
    #pragma unroll
    for (int i = 0; i < 4; i++) { acc[i][0] = 0ull; acc[i][1] = 0ull; }

    for (int nc = 0; nc < N_; nc += 64) {
        #pragma unroll
        for (int r = 0; r < 4; r++) {
            int i = tid + r * 256;         // 0..1023 : 64d x 16 n4
            int dd = i >> 4, n4 = i & 15;
            float4 kq = *(const float4*)(g_k + base + (size_t)dd * N_ + nc + n4 * 4);
            Ks[n4*4+0][dd] = kq.x; Ks[n4*4+1][dd] = kq.y;
            Ks[n4*4+2][dd] = kq.z; Ks[n4*4+3][dd] = kq.w;
            float4 vq = *(const float4*)(g_v + base + (size_t)dd * N_ + nc + n4 * 4);
            Vs[n4*4+0][dd] = vq.x; Vs[n4*4+1][dd] = vq.y;
            Vs[n4*4+2][dd] = vq.z; Vs[n4*4+3][dd] = vq.w;
        }
        __syncthreads();
        #pragma unroll 4
        for (int n = 0; n < 64; n++) {
            float4 a4 = *(const float4*)(&Ks[n][ty * 4]);
            float4 b4 = *(const float4*)(&Vs[n][tx * 4]);
            u64 pa0 = pack2(a4.x, a4.x), pa1 = pack2(a4.y, a4.y);
            u64 pa2 = pack2(a4.z, a4.z), pa3 = pack2(a4.w, a4.w);
            u64 b01 = pack2(b4.x, b4.y), b23 = pack2(b4.z, b4.w);
            FMA16_P(acc, pa0, pa1, pa2, pa3, b01, b23);
        }
        __syncthreads();
    }
    float* o = g_kv + (size_t)tbh * D_ * D_;
    #pragma unroll
    for (int i = 0; i < 4; i++) {
        float2 c01 = unpack2(acc[i][0]);
        float2 c23 = unpack2(acc[i][1]);
        float4 w4 = make_float4(c01.x, c01.y, c23.x, c23.y);
        *(float4*)(o + (ty * 4 + i) * D_ + tx * 4) = w4;
    }
}

// ============================================================
// K3b: a = (q @ kv) * 0.125, LIF(0.5) over T, write attn spikes.
// grid = 4(ntile) * 8(h) * 32(b) = 1024 blocks; t looped inside.
// mapping: ty -> e (output channel), tx -> n (coalesced writes).
// ============================================================
__global__ __launch_bounds__(256) void attn_kernel() {
    __shared__ float4 Qs[64][16];    // [dd][n4]  (natural layout of g_q)
    __shared__ float4 KVs[64][16];   // [dd][e4]

    int bx = blockIdx.x;
    int ntile = bx & 3, hh = (bx >> 2) & 7, b = bx >> 5;
    int tid = threadIdx.x, ty = tid >> 4, tx = tid & 15;
    int nB = ntile * 64;

    float vm[4][4];
    #pragma unroll
    for (int i = 0; i < 4; i++)
        #pragma unroll
        for (int j = 0; j < 4; j++) vm[i][j] = 0.f;

    for (int t = 0; t < T_; t++) {
        int tb = t * B_ + b;
        #pragma unroll
        for (int r = 0; r < 4; r++) {
            int i = tid + r * 256;
            int dd = i >> 4, q4 = i & 15;
            Qs[dd][q4]  = *(const float4*)(g_q + ((size_t)tb * C_ + hh * D_ + dd) * N_ + nB + q4 * 4);
            KVs[dd][q4] = *(const float4*)(g_kv + ((size_t)tb * H_ + hh) * D_ * D_ + (size_t)dd * D_ + q4 * 4);
        }
        __syncthreads();
        u64 acc[4][2];
        #pragma unroll
        for (int i = 0; i < 4; i++) { acc[i][0] = 0ull; acc[i][1] = 0ull; }
        #pragma unroll 4
        for (int dd = 0; dd < 64; dd++) {
            float4 a4 = KVs[dd][ty];   // e dim
            float4 b4 = Qs[dd][tx];    // n dim
            u64 pa0 = pack2(a4.x, a4.x), pa1 = pack2(a4.y, a4.y);
            u64 pa2 = pack2(a4.z, a4.z), pa3 = pack2(a4.w, a4.w);
            u64 b01 = pack2(b4.x, b4.y), b23 = pack2(b4.z, b4.w);
            FMA16_P(acc, pa0, pa1, pa2, pa3, b01, b23);
        }
        #pragma unroll
        for (int i = 0; i < 4; i++) {
            float2 c01 = unpack2(acc[i][0]);
            float2 c23 = unpack2(acc[i][1]);
            float4 sp;
            sp.x = lif_step(vm[i][0], c01.x * 0.125f, 0.5f);
            sp.y = lif_step(vm[i][1], c01.y * 0.125f, 0.5f);
            sp.z = lif_step(vm[i][2], c23.x * 0.125f, 0.5f);
            sp.w = lif_step(vm[i][3], c23.y * 0.125f, 0.5f);
            *(float4*)(g_s + ((size_t)tb * C_ + hh * D_ + ty * 4 + i) * N_ + nB + tx * 4) = sp;
        }
        __syncthreads();
    }
}

// ============================================================
// K4: y = BN(p_w @ s + bias).  grid = 4 * 8 * 128(tb) = 4096 blocks.
// ============================================================
__global__ __launch_bounds__(256) void proj_kernel(
    const float* __restrict__ pw, const float* __restrict__ pbias,
    const float* __restrict__ pg, const float* __restrict__ pb,
    const float* __restrict__ pm, const float* __restrict__ pv,
    float* __restrict__ out)
{
    __shared__ float  Ws[32][68];
    __shared__ float4 Ss[32][16];

    int bx = blockIdx.x;
    int ntile = bx & 3, otile = (bx >> 2) & 7, tb = bx >> 5;   // tb in [0,128)
    int tid = threadIdx.x, ty = tid >> 4, tx = tid & 15;
    int oB = otile * 64, nB = ntile * 64;

    u64 acc[4][2];
    #pragma unroll
    for (int i = 0; i < 4; i++) { acc[i][0] = 0ull; acc[i][1] = 0ull; }

    for (int kc = 0; kc < C_; kc += 32) {
        #pragma unroll
        for (int r = 0; r < 2; r++) {
            int i = tid + r * 256;
            int o = i >> 3, kq = i & 7;
            float4 wv = *(const float4*)(pw + (size_t)(oB + o) * C_ + kc + kq * 4);
            Ws[kq*4+0][o] = wv.x; Ws[kq*4+1][o] = wv.y;
            Ws[kq*4+2][o] = wv.z; Ws[kq*4+3][o] = wv.w;
        }
        #pragma unroll
        for (int r = 0; r < 2; r++) {
            int i = tid + r * 256;     // 32k x 16 n4 = 512 float4
            int k = i >> 4, n4 = i & 15;
            Ss[k][n4] = *(const float4*)(g_s + ((size_t)tb * C_ + kc + k) * N_ + nB + n4 * 4);
        }
        __syncthreads();
        #pragma unroll 4
        for (int k = 0; k < 32; k++) {
            float4 a4 = *(const float4*)(&Ws[k][ty * 4]);
            float4 b4 = Ss[k][tx];
            u64 pa0 = pack2(a4.x, a4.x), pa1 = pack2(a4.y, a4.y);
            u64 pa2 = pack2(a4.z, a4.z), pa3 = pack2(a4.w, a4.w);
            u64 b01 = pack2(b4.x, b4.y), b23 = pack2(b4.z, b4.w);
            FMA16_P(acc, pa0, pa1, pa2, pa3, b01, b23);
        }
        __syncthreads();
    }

    #pragma unroll
    for (int i = 0; i < 4; i++) {
        int o = oB + ty * 4 + i;
        float scale = pg[o] / sqrtf(pv[o] + 1e-5f);
        float bias  = pbias[o], mu = pm[o], bb = pb[o];
        float2 c01 = unpack2(acc[i][0]);
        float2 c23 = unpack2(acc[i][1]);
        float4 w4;
        w4.x = ((c01.x + bias) - mu) * scale + bb;
        w4.y = ((c01.y + bias) - mu) * scale + bb;
        w4.z = ((c23.x + bias) - mu) * scale + bb;
        w4.w = ((c23.y + bias) - mu) * scale + bb;
        *(float4*)(out + ((size_t)tb * C_ + o) * N_ + nB + tx * 4) = w4;
    }
}

// ============================================================
extern "C" void kernel_launch(void* const* d_in, const int* in_sizes, int n_in,
                              void* d_out, int out_size) {
    (void)in_sizes; (void)n_in; (void)out_size;
    const float* x = (const float*)d_in[0];
    QKVArgs a;
    a.w[0]  = (const float*)d_in[1];  a.gm[0] = (const float*)d_in[2];
    a.bt[0] = (const float*)d_in[3];  a.mu[0] = (const float*)d_in[4];
    a.var[0]= (const float*)d_in[5];
    a.w[1]  = (const float*)d_in[6];  a.gm[1] = (const float*)d_in[7];
    a.bt[1] = (const float*)d_in[8];  a.mu[1] = (const float*)d_in[9];
    a.var[1]= (const float*)d_in[10];
    a.w[2]  = (const float*)d_in[11]; a.gm[2] = (const float*)d_in[12];
    a.bt[2] = (const float*)d_in[13]; a.mu[2] = (const float*)d_in[14];
    a.var[2]= (const float*)d_in[15];
    const float* pw    = (const float*)d_in[16];
    const float* pbias = (const float*)d_in[17];
    const float* pg    = (const float*)d_in[18];
    const float* pb    = (const float*)d_in[19];
    const float* pm    = (const float*)d_in[20];
    const float* pv    = (const float*)d_in[21];

    lif_x_kernel<<<BCN_ / 4 / 256, 256>>>(x);
    qkv_kernel<<<dim3(1024, 3, 1), 256>>>(a);
    kv_kernel<<<1024, 256>>>();
    attn_kernel<<<1024, 256>>>();
    proj_kernel<<<4096, 256>>>(pw, pbias, pg, pb, pm, pv, (float*)d_out);
}

// round 5
// speedup vs baseline: 1.5185x; 1.5185x over previous
#include <cuda_runtime.h>
#include <cuda_bf16.h>
#include <cstdint>

#define T_ 4
#define B_ 32
#define C_ 512
#define N_ 256
#define H_ 8
#define D_ 64
#define BCN_ (B_*C_*N_)
#define TBCN_ (T_*BCN_)

typedef unsigned long long u64;

// ---- scratch ----
__device__ float g_q[TBCN_];
__device__ float g_k[TBCN_];
__device__ float g_v[TBCN_];
__device__ float g_kv[T_*B_*H_*D_*D_];
__device__ __nv_bfloat16 g_xsT[TBCN_];        // [t][b][n][c] spikes bf16 (K-major)
__device__ __nv_bfloat16 g_sT[TBCN_];         // [t*b][n][c] attn spikes bf16
__device__ __nv_bfloat16 g_wl[4*3*C_*C_];     // [mat][limb][o][c] weight limbs

// ================= helpers =================
__device__ __forceinline__ uint32_t smem_u32(const void* p) {
    uint32_t a;
    asm("{ .reg .u64 t; cvta.to.shared.u64 t, %1; cvt.u32.u64 %0, t; }" : "=r"(a) : "l"(p));
    return a;
}

#define CP16(dst, src) \
    asm volatile("cp.async.cg.shared.global [%0], [%1], 16;" :: "r"(dst), "l"(src))
#define CP_COMMIT() asm volatile("cp.async.commit_group;" ::: "memory")
#define CP_WAIT(n)  asm volatile("cp.async.wait_group %0;" :: "n"(n) : "memory")

__device__ __forceinline__ void ldm_x4(uint32_t r[4], uint32_t addr) {
    asm volatile("ldmatrix.sync.aligned.m8n8.x4.shared.b16 {%0,%1,%2,%3}, [%4];"
        : "=r"(r[0]), "=r"(r[1]), "=r"(r[2]), "=r"(r[3]) : "r"(addr));
}
__device__ __forceinline__ void mma16816(float c[4], const uint32_t a[4], const uint32_t* b) {
    asm volatile("mma.sync.aligned.m16n8k16.row.col.f32.bf16.bf16.f32 "
        "{%0,%1,%2,%3}, {%4,%5,%6,%7}, {%8,%9}, {%0,%1,%2,%3};"
        : "+f"(c[0]), "+f"(c[1]), "+f"(c[2]), "+f"(c[3])
        : "r"(a[0]), "r"(a[1]), "r"(a[2]), "r"(a[3]), "r"(b[0]), "r"(b[1]));
}

// packed fp32x2 (SIMT kv/attn)
__device__ __forceinline__ void fma2(u64 &d, u64 a, u64 b) {
    asm("fma.rn.f32x2 %0, %1, %2, %0;" : "+l"(d) : "l"(a), "l"(b));
}
__device__ __forceinline__ u64 pack2(float x, float y) {
    u64 r; asm("mov.b64 %0, {%1, %2};" : "=l"(r) : "f"(x), "f"(y)); return r;
}
__device__ __forceinline__ float2 unpack2(u64 v) {
    float2 f; asm("mov.b64 {%0, %1}, %2;" : "=f"(f.x), "=f"(f.y) : "l"(v)); return f;
}
#define FMA16_P(A, pa0, pa1, pa2, pa3, b01, b23) do { \
    fma2(A[0][0], pa0, b01); fma2(A[0][1], pa0, b23); \
    fma2(A[1][0], pa1, b01); fma2(A[1][1], pa1, b23); \
    fma2(A[2][0], pa2, b01); fma2(A[2][1], pa2, b23); \
    fma2(A[3][0], pa3, b01); fma2(A[3][1], pa3, b23); \
} while (0)

__device__ __forceinline__ float lif_step(float& v, float x, float vth) {
    v += (x - v) * 0.5f;
    float s = (v >= vth) ? 1.0f : 0.0f;
    if (s != 0.0f) v = 0.0f;
    return s;
}
__device__ __forceinline__ uint32_t bfpair(float lo, float hi) {
    return (uint32_t)__bfloat16_as_ushort(__float2bfloat16(lo)) |
           ((uint32_t)__bfloat16_as_ushort(__float2bfloat16(hi)) << 16);
}

// ============================================================
// K0: fp32 weights -> 3 bf16 limbs, natural [mat][limb][o][c]
// ============================================================
__global__ void wsplit_kernel(const float* __restrict__ qw, const float* __restrict__ kw,
                              const float* __restrict__ vw, const float* __restrict__ pw) {
    int i = blockIdx.x * 256 + threadIdx.x;
    int mat = i >> 18, idx = i & 262143;
    const float* W = (mat == 0) ? qw : (mat == 1) ? kw : (mat == 2) ? vw : pw;
    float w = W[idx];
    __nv_bfloat16 h1 = __float2bfloat16(w);
    float r1 = w - __bfloat162float(h1);
    __nv_bfloat16 h2 = __float2bfloat16(r1);
    float r2 = r1 - __bfloat162float(h2);
    __nv_bfloat16 h3 = __float2bfloat16(r2);
    size_t base = (size_t)(mat * 3) * 262144 + idx;
    g_wl[base] = h1;
    g_wl[base + 262144] = h2;
    g_wl[base + 524288] = h3;
}

// ============================================================
// K1: LIF(x) -> bf16 spikes, transposed [t][b][n][c]
// grid: ch(8) x nt(4) x b(32) = 1024, 256 thr
// ============================================================
__global__ __launch_bounds__(256) void lifx_kernel(const float* __restrict__ x) {
    __shared__ __nv_bfloat16 Sb[64][72];
    int bx = blockIdx.x;
    int ch = bx & 7, nt = (bx >> 3) & 3, b = bx >> 5;
    int tid = threadIdx.x;
    int c_l = tid >> 2, ng = tid & 3;
    int n_o = tid >> 2, u0 = tid & 3;
    float vm[16];
    #pragma unroll
    for (int j = 0; j < 16; j++) vm[j] = 0.f;

    for (int t = 0; t < T_; t++) {
        const float* xp = x + (((size_t)(t * B_ + b)) * C_ + ch * 64 + c_l) * N_ + nt * 64 + ng * 16;
        #pragma unroll
        for (int q = 0; q < 4; q++) {
            float4 xv = *(const float4*)(xp + q * 4);
            Sb[c_l][ng*16 + q*4 + 0] = __float2bfloat16(lif_step(vm[q*4+0], xv.x, 1.0f));
            Sb[c_l][ng*16 + q*4 + 1] = __float2bfloat16(lif_step(vm[q*4+1], xv.y, 1.0f));
            Sb[c_l][ng*16 + q*4 + 2] = __float2bfloat16(lif_step(vm[q*4+2], xv.z, 1.0f));
            Sb[c_l][ng*16 + q*4 + 3] = __float2bfloat16(lif_step(vm[q*4+3], xv.w, 1.0f));
        }
        __syncthreads();
        // write [n][c]: row n = nt*64+n_o, c chunk = ch*64 + u*8
        char* outb = (char*)(g_xsT + ((size_t)(t*B_ + b) * N_ + nt*64 + n_o) * C_ + ch*64);
        #pragma unroll
        for (int hf = 0; hf < 2; hf++) {
            int u = u0 + hf * 4;
            uint32_t rp[4];
            #pragma unroll
            for (int p = 0; p < 4; p++) {
                float lo = __bfloat162float(Sb[u*8 + p*2][n_o]);
                float hi = __bfloat162float(Sb[u*8 + p*2 + 1][n_o]);
                rp[p] = bfpair(lo, hi);
            }
            *(uint4*)(outb + u*16) = make_uint4(rp[0], rp[1], rp[2], rp[3]);
        }
        __syncthreads();
    }
}

// ============================================================
// Shared GEMM machinery: 128x128 block, 8 warps (4m x 2n), warp 32x64.
// A = weight limbs [3][128][K], B = spikes [128 n][K] (K-major, "col").
// smem: k16 double-buffered stages, stride 24 halves (48B, 16B-aligned,
// conflict-free ldmatrix: 12-bank row step, cycle 8 distinct).
// ============================================================
struct SmemTiles {
    __align__(16) __nv_bfloat16 As[2][3][128][24];
    __align__(16) __nv_bfloat16 Bs[2][128][24];
};

__device__ __forceinline__ void load_stage_A(uint32_t asb, int s, int kc, int wmat, int mt, int tid) {
    #pragma unroll
    for (int r = 0; r < 3; r++) {
        int idx = tid + r * 256;
        int l = idx >> 8, rem = idx & 255;
        int o = rem >> 1, h = rem & 1;
        const __nv_bfloat16* src = g_wl + ((size_t)(wmat*3 + l) * 512 + mt*128 + o) * 512 + kc + h*8;
        uint32_t dst = asb + (uint32_t)((((s*3 + l)*128 + o)*24 + h*8) * 2);
        CP16(dst, src);
    }
}
__device__ __forceinline__ void load_stage_B(uint32_t bsb, int s, int kc,
                                             const __nv_bfloat16* srcT, int rowbase, int tid) {
    int n = tid >> 1, h = tid & 1;
    const __nv_bfloat16* src = srcT + ((size_t)(rowbase + n)) * 512 + kc + h*8;
    uint32_t dst = bsb + (uint32_t)(((s*128 + n)*24 + h*8) * 2);
    CP16(dst, src);
}

// compute one K=512 x 3-limb GEMM pass into acc[2][8][4]
__device__ __forceinline__ void gemm_pass(uint32_t asb, uint32_t bsb, float acc[2][8][4],
                                          int wmat, int mt, const __nv_bfloat16* srcT, int rowbase,
                                          int tid, int wm, int wn, int lane) {
    load_stage_A(asb, 0, 0, wmat, mt, tid);
    load_stage_B(bsb, 0, 0, srcT, rowbase, tid);
    CP_COMMIT();
    // per-lane ldmatrix address components
    int a_row = lane & 15, a_col = (lane >> 4) * 8;
    int b_row = wn + (lane & 7) + ((lane >> 4) << 3), b_col = lane & 8;

    for (int c = 0; c < 32; c++) {
        int s = c & 1, ns = s ^ 1;
        __syncthreads();
        if (c < 31) {
            load_stage_A(asb, ns, (c+1)*16, wmat, mt, tid);
            load_stage_B(bsb, ns, (c+1)*16, srcT, rowbase, tid);
            CP_COMMIT();
            CP_WAIT(1);
        } else {
            CP_WAIT(0);
        }
        __syncthreads();
        uint32_t bfr[8][2];
        #pragma unroll
        for (int jp = 0; jp < 4; jp++) {
            uint32_t r4[4];
            uint32_t addr = bsb + (uint32_t)((((s*128) + b_row + jp*16)*24 + b_col) * 2);
            ldm_x4(r4, addr);
            bfr[jp*2][0] = r4[0];   bfr[jp*2][1] = r4[1];
            bfr[jp*2+1][0] = r4[2]; bfr[jp*2+1][1] = r4[3];
        }
        #pragma unroll
        for (int l = 0; l < 3; l++) {
            #pragma unroll
            for (int i = 0; i < 2; i++) {
                uint32_t a4[4];
                uint32_t addr = asb + (uint32_t)(((((s*3 + l)*128) + wm + i*16 + a_row)*24 + a_col) * 2);
                ldm_x4(a4, addr);
                #pragma unroll
                for (int j = 0; j < 8; j++)
                    mma16816(acc[i][j], a4, bfr[j]);
            }
        }
    }
}

// ============================================================
// K2: qkv GEMM + BN + LIF.  grid.x = nt2*mt4*b32 = 256, grid.y = br3.
// ============================================================
__global__ __launch_bounds__(256, 1) void qkv_mma_kernel(
    const float* __restrict__ qg, const float* __restrict__ qb, const float* __restrict__ qm, const float* __restrict__ qv,
    const float* __restrict__ kg, const float* __restrict__ kb, const float* __restrict__ km, const float* __restrict__ kvv,
    const float* __restrict__ vg, const float* __restrict__ vb, const float* __restrict__ vmn, const float* __restrict__ vvv)
{
    __shared__ SmemTiles st;
    uint32_t asb = smem_u32(st.As), bsb = smem_u32(st.Bs);
    int tid = threadIdx.x, lane = tid & 31, wid = tid >> 5;
    int wm = (wid & 3) * 32, wn = (wid >> 2) * 64;
    int bx = blockIdx.x, br = blockIdx.y;
    int nt = bx & 1, mt = (bx >> 1) & 3, b = bx >> 3;

    const float* G  = (br == 0) ? qg : (br == 1) ? kg : vg;
    const float* Bt = (br == 0) ? qb : (br == 1) ? kb : vb;
    const float* M  = (br == 0) ? qm : (br == 1) ? km : vmn;
    const float* V  = (br == 0) ? qv : (br == 1) ? kvv : vvv;
    float* outp = (br == 0) ? g_q : (br == 1) ? g_k : g_v;

    float scl[2][2], mean[2][2], beta[2][2];
    #pragma unroll
    for (int i = 0; i < 2; i++)
        #pragma unroll
        for (int rh = 0; rh < 2; rh++) {
            int o = mt*128 + wm + i*16 + rh*8 + (lane >> 2);
            scl[i][rh]  = G[o] / sqrtf(V[o] + 1e-5f);
            mean[i][rh] = M[o];
            beta[i][rh] = Bt[o];
        }

    float vm[2][2][8][2];
    #pragma unroll
    for (int i = 0; i < 2; i++)
        #pragma unroll
        for (int rh = 0; rh < 2; rh++)
            #pragma unroll
            for (int j = 0; j < 8; j++) { vm[i][rh][j][0] = 0.f; vm[i][rh][j][1] = 0.f; }

    for (int t = 0; t < T_; t++) {
        float acc[2][8][4];
        #pragma unroll
        for (int i = 0; i < 2; i++)
            #pragma unroll
            for (int j = 0; j < 8; j++)
                #pragma unroll
                for (int p = 0; p < 4; p++) acc[i][j][p] = 0.f;

        int rowbase = (t*B_ + b) * 256 + nt*128;
        gemm_pass(asb, bsb, acc, br, mt, g_xsT, rowbase, tid, wm, wn, lane);

        #pragma unroll
        for (int i = 0; i < 2; i++) {
            #pragma unroll
            for (int j = 0; j < 8; j++) {
                #pragma unroll
                for (int rh = 0; rh < 2; rh++) {
                    float y0 = (acc[i][j][rh*2+0] - mean[i][rh]) * scl[i][rh] + beta[i][rh];
                    float y1 = (acc[i][j][rh*2+1] - mean[i][rh]) * scl[i][rh] + beta[i][rh];
                    float s0 = lif_step(vm[i][rh][j][0], y0, 1.0f);
                    float s1 = lif_step(vm[i][rh][j][1], y1, 1.0f);
                    int o = mt*128 + wm + i*16 + rh*8 + (lane >> 2);
                    int n = nt*128 + wn + j*8 + 2*(lane & 3);
                    *(float2*)(outp + ((size_t)(t*B_ + b) * C_ + o) * N_ + n) = make_float2(s0, s1);
                }
            }
        }
        __syncthreads();
    }
}

// ============================================================
// K3a: kv[d,e] = sum_n k[n,d]*v[n,e] per (t,b,h). SIMT exact.
// ============================================================
__global__ __launch_bounds__(256) void kv_kernel() {
    __shared__ float Ks[64][68];
    __shared__ float Vs[64][68];
    int tbh = blockIdx.x;
    int tb = tbh >> 3, hh = tbh & 7;
    size_t base = ((size_t)tb * C_ + hh * D_) * N_;
    int tid = threadIdx.x, ty = tid >> 4, tx = tid & 15;

    u64 acc[4][2];
    #pragma unroll
    for (int i = 0; i < 4; i++) { acc[i][0] = 0ull; acc[i][1] = 0ull; }

    for (int nc = 0; nc < N_; nc += 64) {
        #pragma unroll
        for (int r = 0; r < 4; r++) {
            int i = tid + r * 256;
            int dd = i >> 4, n4 = i & 15;
            float4 kq = *(const float4*)(g_k + base + (size_t)dd * N_ + nc + n4 * 4);
            Ks[n4*4+0][dd] = kq.x; Ks[n4*4+1][dd] = kq.y;
            Ks[n4*4+2][dd] = kq.z; Ks[n4*4+3][dd] = kq.w;
            float4 vq = *(const float4*)(g_v + base + (size_t)dd * N_ + nc + n4 * 4);
            Vs[n4*4+0][dd] = vq.x; Vs[n4*4+1][dd] = vq.y;
            Vs[n4*4+2][dd] = vq.z; Vs[n4*4+3][dd] = vq.w;
        }
        __syncthreads();
        #pragma unroll 4
        for (int n = 0; n < 64; n++) {
            float4 a4 = *(const float4*)(&Ks[n][ty * 4]);
            float4 b4 = *(const float4*)(&Vs[n][tx * 4]);
            u64 pa0 = pack2(a4.x, a4.x), pa1 = pack2(a4.y, a4.y);
            u64 pa2 = pack2(a4.z, a4.z), pa3 = pack2(a4.w, a4.w);
            u64 b01 = pack2(b4.x, b4.y), b23 = pack2(b4.z, b4.w);
            FMA16_P(acc, pa0, pa1, pa2, pa3, b01, b23);
        }
        __syncthreads();
    }
    float* o = g_kv + (size_t)tbh * D_ * D_;
    #pragma unroll
    for (int i = 0; i < 4; i++) {
        float2 c01 = unpack2(acc[i][0]);
        float2 c23 = unpack2(acc[i][1]);
        *(float4*)(o + (ty * 4 + i) * D_ + tx * 4) = make_float4(c01.x, c01.y, c23.x, c23.y);
    }
}

// ============================================================
// K3b: a = (q @ kv)*0.125, LIF(0.5), emit bf16 spikes [tb][n][c].
// ============================================================
__global__ __launch_bounds__(256) void attn_kernel() {
    __shared__ float4 Qs[64][16];
    __shared__ float4 KVs[64][16];
    __shared__ __nv_bfloat16 Sb2[64][72];

    int bx = blockIdx.x;
    int ntile = bx & 3, hh = (bx >> 2) & 7, b = bx >> 5;
    int tid = threadIdx.x, ty = tid >> 4, tx = tid & 15;
    int nB = ntile * 64;
    int n_o = tid >> 2, u0 = tid & 3;

    float vm[4][4];
    #pragma unroll
    for (int i = 0; i < 4; i++)
        #pragma unroll
        for (int j = 0; j < 4; j++) vm[i][j] = 0.f;

    for (int t = 0; t < T_; t++) {
        int tb = t * B_ + b;
        #pragma unroll
        for (int r = 0; r < 4; r++) {
            int i = tid + r * 256;
            int dd = i >> 4, q4 = i & 15;
            Qs[dd][q4]  = *(const float4*)(g_q + ((size_t)tb * C_ + hh * D_ + dd) * N_ + nB + q4 * 4);
            KVs[dd][q4] = *(const float4*)(g_kv + ((size_t)tb * H_ + hh) * D_ * D_ + (size_t)dd * D_ + q4 * 4);
        }
        __syncthreads();
        u64 acc[4][2];
        #pragma unroll
        for (int i = 0; i < 4; i++) { acc[i][0] = 0ull; acc[i][1] = 0ull; }
        #pragma unroll 4
        for (int dd = 0; dd < 64; dd++) {
            float4 a4 = KVs[dd][ty];
            float4 b4 = Qs[dd][tx];
            u64 pa0 = pack2(a4.x, a4.x), pa1 = pack2(a4.y, a4.y);
            u64 pa2 = pack2(a4.z, a4.z), pa3 = pack2(a4.w, a4.w);
            u64 b01 = pack2(b4.x, b4.y), b23 = pack2(b4.z, b4.w);
            FMA16_P(acc, pa0, pa1, pa2, pa3, b01, b23);
        }
        #pragma unroll
        for (int i = 0; i < 4; i++) {
            float2 c01 = unpack2(acc[i][0]);
            float2 c23 = unpack2(acc[i][1]);
            Sb2[ty*4+i][tx*4+0] = __float2bfloat16(lif_step(vm[i][0], c01.x * 0.125f, 0.5f));
            Sb2[ty*4+i][tx*4+1] = __float2bfloat16(lif_step(vm[i][1], c01.y * 0.125f, 0.5f));
            Sb2[ty*4+i][tx*4+2] = __float2bfloat16(lif_step(vm[i][2], c23.x * 0.125f, 0.5f));
            Sb2[ty*4+i][tx*4+3] = __float2bfloat16(lif_step(vm[i][3], c23.y * 0.125f, 0.5f));
        }
        __syncthreads();
        char* outb = (char*)(g_sT + ((size_t)tb * N_ + nB + n_o) * C_ + hh*64);
        #pragma unroll
        for (int hf = 0; hf < 2; hf++) {
            int u = u0 + hf * 4;
            uint32_t rp[4];
            #pragma unroll
            for (int p = 0; p < 4; p++) {
                float lo = __bfloat162float(Sb2[u*8 + p*2][n_o]);
                float hi = __bfloat162float(Sb2[u*8 + p*2 + 1][n_o]);
                rp[p] = bfpair(lo, hi);
            }
            *(uint4*)(outb + u*16) = make_uint4(rp[0], rp[1], rp[2], rp[3]);
        }
        __syncthreads();
    }
}

// ============================================================
// K4: proj GEMM + bias + BN -> d_out.  grid = nt2*mt4*tb128 = 1024.
// ============================================================
__global__ __launch_bounds__(256, 1) void proj_mma_kernel(
    const float* __restrict__ pbias, const float* __restrict__ pg, const float* __restrict__ pb,
    const float* __restrict__ pm, const float* __restrict__ pv, float* __restrict__ out)
{
    __shared__ SmemTiles st;
    uint32_t asb = smem_u32(st.As), bsb = smem_u32(st.Bs);
    int tid = threadIdx.x, lane = tid & 31, wid = tid >> 5;
    int wm = (wid & 3) * 32, wn = (wid >> 2) * 64;
    int bx = blockIdx.x;
    int nt = bx & 1, mt = (bx >> 1) & 3, tb = bx >> 3;

    float scl[2][2], mean[2][2], beta[2][2], bias[2][2];
    #pragma unroll
    for (int i = 0; i < 2; i++)
        #pragma unroll
        for (int rh = 0; rh < 2; rh++) {
            int o = mt*128 + wm + i*16 + rh*8 + (lane >> 2);
            scl[i][rh]  = pg[o] / sqrtf(pv[o] + 1e-5f);
            mean[i][rh] = pm[o];
            beta[i][rh] = pb[o];
            bias[i][rh] = pbias[o];
        }

    float acc[2][8][4];
    #pragma unroll
    for (int i = 0; i < 2; i++)
        #pragma unroll
        for (int j = 0; j < 8; j++)
            #pragma unroll
            for (int p = 0; p < 4; p++) acc[i][j][p] = 0.f;

    int rowbase = tb * 256 + nt*128;
    gemm_pass(asb, bsb, acc, 3, mt, g_sT, rowbase, tid, wm, wn, lane);

    #pragma unroll
    for (int i = 0; i < 2; i++) {
        #pragma unroll
        for (int j = 0; j < 8; j++) {
            #pragma unroll
            for (int rh = 0; rh < 2; rh++) {
                float y0 = ((acc[i][j][rh*2+0] + bias[i][rh]) - mean[i][rh]) * scl[i][rh] + beta[i][rh];
                float y1 = ((acc[i][j][rh*2+1] + bias[i][rh]) - mean[i][rh]) * scl[i][rh] + beta[i][rh];
                int o = mt*128 + wm + i*16 + rh*8 + (lane >> 2);
                int n = nt*128 + wn + j*8 + 2*(lane & 3);
                *(float2*)(out + ((size_t)tb * C_ + o) * N_ + n) = make_float2(y0, y1);
            }
        }
    }
}

// ============================================================
extern "C" void kernel_launch(void* const* d_in, const int* in_sizes, int n_in,
                              void* d_out, int out_size) {
    (void)in_sizes; (void)n_in; (void)out_size;
    const float* x  = (const float*)d_in[0];
    const float* qw = (const float*)d_in[1];
    const float* qg = (const float*)d_in[2];
    const float* qb = (const float*)d_in[3];
    const float* qm = (const float*)d_in[4];
    const float* qv = (const float*)d_in[5];
    const float* kw = (const float*)d_in[6];
    const float* kg = (const float*)d_in[7];
    const float* kb = (const float*)d_in[8];
    const float* km = (const float*)d_in[9];
    const float* kvv= (const float*)d_in[10];
    const float* vw = (const float*)d_in[11];
    const float* vg = (const float*)d_in[12];
    const float* vb = (const float*)d_in[13];
    const float* vm = (const float*)d_in[14];
    const float* vv = (const float*)d_in[15];
    const float* pw    = (const float*)d_in[16];
    const float* pbias = (const float*)d_in[17];
    const float* pg    = (const float*)d_in[18];
    const float* pb    = (const float*)d_in[19];
    const float* pm    = (const float*)d_in[20];
    const float* pv    = (const float*)d_in[21];

    wsplit_kernel<<<4096, 256>>>(qw, kw, vw, pw);
    lifx_kernel<<<1024, 256>>>(x);
    qkv_mma_kernel<<<dim3(256, 3), 256>>>(qg, qb, qm, qv, kg, kb, km, kvv, vg, vb, vm, vv);
    kv_kernel<<<1024, 256>>>();
    attn_kernel<<<1024, 256>>>();
    proj_mma_kernel<<<1024, 256>>>(pbias, pg, pb, pm, pv, (float*)d_out);
}

// round 6
// speedup vs baseline: 1.8601x; 1.2249x over previous
#include <cuda_runtime.h>
#include <cuda_fp16.h>
#include <cstdint>

#define T_ 4
#define B_ 32
#define C_ 512
#define N_ 256
#define H_ 8
#define D_ 64
#define BCN_ (B_*C_*N_)
#define TBCN_ (T_*BCN_)

typedef unsigned long long u64;

// ---- scratch ----
__device__ float g_q[TBCN_];
__device__ float g_k[TBCN_];
__device__ float g_v[TBCN_];
__device__ float g_kv[T_*B_*H_*D_*D_];
__device__ __half g_xsT[TBCN_];        // [t][b][n][c] spikes fp16 (K-major)
__device__ __half g_sT[TBCN_];         // [t*b][n][c] attn spikes fp16
__device__ __half g_wl[4*2*C_*C_];     // [mat][limb][o][c] fp16 weight limbs

// ================= helpers =================
__device__ __forceinline__ uint32_t smem_u32(const void* p) {
    uint32_t a;
    asm("{ .reg .u64 t; cvta.to.shared.u64 t, %1; cvt.u32.u64 %0, t; }" : "=r"(a) : "l"(p));
    return a;
}

#define CP16(dst, src) \
    asm volatile("cp.async.cg.shared.global [%0], [%1], 16;" :: "r"(dst), "l"(src))
#define CP_COMMIT() asm volatile("cp.async.commit_group;" ::: "memory")
#define CP_WAIT(n)  asm volatile("cp.async.wait_group %0;" :: "n"(n) : "memory")

__device__ __forceinline__ void ldm_x4(uint32_t r[4], uint32_t addr) {
    asm volatile("ldmatrix.sync.aligned.m8n8.x4.shared.b16 {%0,%1,%2,%3}, [%4];"
        : "=r"(r[0]), "=r"(r[1]), "=r"(r[2]), "=r"(r[3]) : "r"(addr));
}
__device__ __forceinline__ void mma16816(float c[4], const uint32_t a[4], const uint32_t* b) {
    asm volatile("mma.sync.aligned.m16n8k16.row.col.f32.f16.f16.f32 "
        "{%0,%1,%2,%3}, {%4,%5,%6,%7}, {%8,%9}, {%0,%1,%2,%3};"
        : "+f"(c[0]), "+f"(c[1]), "+f"(c[2]), "+f"(c[3])
        : "r"(a[0]), "r"(a[1]), "r"(a[2]), "r"(a[3]), "r"(b[0]), "r"(b[1]));
}

// packed fp32x2 (SIMT kv/attn)
__device__ __forceinline__ void fma2(u64 &d, u64 a, u64 b) {
    asm("fma.rn.f32x2 %0, %1, %2, %0;" : "+l"(d) : "l"(a), "l"(b));
}
__device__ __forceinline__ u64 pack2(float x, float y) {
    u64 r; asm("mov.b64 %0, {%1, %2};" : "=l"(r) : "f"(x), "f"(y)); return r;
}
__device__ __forceinline__ float2 unpack2(u64 v) {
    float2 f; asm("mov.b64 {%0, %1}, %2;" : "=f"(f.x), "=f"(f.y) : "l"(v)); return f;
}
#define FMA16_P(A, pa0, pa1, pa2, pa3, b01, b23) do { \
    fma2(A[0][0], pa0, b01); fma2(A[0][1], pa0, b23); \
    fma2(A[1][0], pa1, b01); fma2(A[1][1], pa1, b23); \
    fma2(A[2][0], pa2, b01); fma2(A[2][1], pa2, b23); \
    fma2(A[3][0], pa3, b01); fma2(A[3][1], pa3, b23); \
} while (0)

__device__ __forceinline__ float lif_step(float& v, float x, float vth) {
    v += (x - v) * 0.5f;
    float s = (v >= vth) ? 1.0f : 0.0f;
    if (s != 0.0f) v = 0.0f;
    return s;
}
__device__ __forceinline__ uint32_t hpair(float lo, float hi) {
    return (uint32_t)__half_as_ushort(__float2half_rn(lo)) |
           ((uint32_t)__half_as_ushort(__float2half_rn(hi)) << 16);
}

// ============================================================
// K0: fp32 weights -> 2 fp16 limbs, natural [mat][limb][o][c]
// ============================================================
__global__ void wsplit_kernel(const float* __restrict__ qw, const float* __restrict__ kw,
                              const float* __restrict__ vw, const float* __restrict__ pw) {
    int i = blockIdx.x * 256 + threadIdx.x;
    int mat = i >> 18, idx = i & 262143;
    const float* W = (mat == 0) ? qw : (mat == 1) ? kw : (mat == 2) ? vw : pw;
    float w = W[idx];
    __half h1 = __float2half_rn(w);
    float r1 = w - __half2float(h1);
    __half h2 = __float2half_rn(r1);
    size_t base = (size_t)(mat * 2) * 262144 + idx;
    g_wl[base] = h1;
    g_wl[base + 262144] = h2;
}

// ============================================================
// K1: LIF(x) -> fp16 spikes, transposed [t][b][n][c]
// grid: ch(8) x nt(4) x b(32) = 1024, 256 thr
// ============================================================
__global__ __launch_bounds__(256) void lifx_kernel(const float* __restrict__ x) {
    __shared__ __half Sb[64][72];
    int bx = blockIdx.x;
    int ch = bx & 7, nt = (bx >> 3) & 3, b = bx >> 5;
    int tid = threadIdx.x;
    int c_l = tid >> 2, ng = tid & 3;
    int n_o = tid >> 2, u0 = tid & 3;
    float vm[16];
    #pragma unroll
    for (int j = 0; j < 16; j++) vm[j] = 0.f;

    for (int t = 0; t < T_; t++) {
        const float* xp = x + (((size_t)(t * B_ + b)) * C_ + ch * 64 + c_l) * N_ + nt * 64 + ng * 16;
        #pragma unroll
        for (int q = 0; q < 4; q++) {
            float4 xv = *(const float4*)(xp + q * 4);
            Sb[c_l][ng*16 + q*4 + 0] = __float2half_rn(lif_step(vm[q*4+0], xv.x, 1.0f));
            Sb[c_l][ng*16 + q*4 + 1] = __float2half_rn(lif_step(vm[q*4+1], xv.y, 1.0f));
            Sb[c_l][ng*16 + q*4 + 2] = __float2half_rn(lif_step(vm[q*4+2], xv.z, 1.0f));
            Sb[c_l][ng*16 + q*4 + 3] = __float2half_rn(lif_step(vm[q*4+3], xv.w, 1.0f));
        }
        __syncthreads();
        char* outb = (char*)(g_xsT + ((size_t)(t*B_ + b) * N_ + nt*64 + n_o) * C_ + ch*64);
        #pragma unroll
        for (int hf = 0; hf < 2; hf++) {
            int u = u0 + hf * 4;
            uint32_t rp[4];
            #pragma unroll
            for (int p = 0; p < 4; p++) {
                float lo = __half2float(Sb[u*8 + p*2][n_o]);
                float hi = __half2float(Sb[u*8 + p*2 + 1][n_o]);
                rp[p] = hpair(lo, hi);
            }
            *(uint4*)(outb + u*16) = make_uint4(rp[0], rp[1], rp[2], rp[3]);
        }
        __syncthreads();
    }
}

// ============================================================
// Shared GEMM machinery: 128x128 block, 8 warps (4m x 2n), warp 32x64.
// A = weight limbs [2][128][K], B = spikes [128 n][K] (K-major, "col").
// smem k16 double-buffered, stride 24 halves (conflict-free ldmatrix).
// ============================================================
struct SmemTiles {
    __align__(16) __half As[2][2][128][24];
    __align__(16) __half Bs[2][128][24];
};

__device__ __forceinline__ void load_stage_A(uint32_t asb, int s, int kc, int wmat, int mt, int tid) {
    #pragma unroll
    for (int r = 0; r < 2; r++) {
        int idx = tid + r * 256;
        int l = idx >> 8, rem = idx & 255;
        int o = rem >> 1, h = rem & 1;
        const __half* src = g_wl + ((size_t)(wmat*2 + l) * 512 + mt*128 + o) * 512 + kc + h*8;
        uint32_t dst = asb + (uint32_t)((((s*2 + l)*128 + o)*24 + h*8) * 2);
        CP16(dst, src);
    }
}
__device__ __forceinline__ void load_stage_B(uint32_t bsb, int s, int kc,
                                             const __half* srcT, int rowbase, int tid) {
    int n = tid >> 1, h = tid & 1;
    const __half* src = srcT + ((size_t)(rowbase + n)) * 512 + kc + h*8;
    uint32_t dst = bsb + (uint32_t)(((s*128 + n)*24 + h*8) * 2);
    CP16(dst, src);
}

// one K=512 x 2-limb GEMM pass into acc[2][8][4]
__device__ __forceinline__ void gemm_pass(uint32_t asb, uint32_t bsb, float acc[2][8][4],
                                          int wmat, int mt, const __half* srcT, int rowbase,
                                          int tid, int wm, int wn, int lane) {
    load_stage_A(asb, 0, 0, wmat, mt, tid);
    load_stage_B(bsb, 0, 0, srcT, rowbase, tid);
    CP_COMMIT();
    int a_row = lane & 15, a_col = (lane >> 4) * 8;
    int b_row = wn + (lane & 7) + ((lane >> 4) << 3), b_col = lane & 8;

    for (int c = 0; c < 32; c++) {
        int s = c & 1, ns = s ^ 1;
        __syncthreads();
        if (c < 31) {
            load_stage_A(asb, ns, (c+1)*16, wmat, mt, tid);
            load_stage_B(bsb, ns, (c+1)*16, srcT, rowbase, tid);
            CP_COMMIT();
            CP_WAIT(1);
        } else {
            CP_WAIT(0);
        }
        __syncthreads();
        uint32_t bfr[8][2];
        #pragma unroll
        for (int jp = 0; jp < 4; jp++) {
            uint32_t r4[4];
            uint32_t addr = bsb + (uint32_t)((((s*128) + b_row + jp*16)*24 + b_col) * 2);
            ldm_x4(r4, addr);
            bfr[jp*2][0] = r4[0];   bfr[jp*2][1] = r4[1];
            bfr[jp*2+1][0] = r4[2]; bfr[jp*2+1][1] = r4[3];
        }
        #pragma unroll
        for (int l = 0; l < 2; l++) {
            #pragma unroll
            for (int i = 0; i < 2; i++) {
                uint32_t a4[4];
                uint32_t addr = asb + (uint32_t)(((((s*2 + l)*128) + wm + i*16 + a_row)*24 + a_col) * 2);
                ldm_x4(a4, addr);
                #pragma unroll
                for (int j = 0; j < 8; j++)
                    mma16816(acc[i][j], a4, bfr[j]);
            }
        }
    }
}

// ============================================================
// K2: qkv GEMM + BN + LIF.  grid.x = nt2*mt4*b32 = 256, grid.y = br3.
// ============================================================
__global__ __launch_bounds__(256, 1) void qkv_mma_kernel(
    const float* __restrict__ qg, const float* __restrict__ qb, const float* __restrict__ qm, const float* __restrict__ qv,
    const float* __restrict__ kg, const float* __restrict__ kb, const float* __restrict__ km, const float* __restrict__ kvv,
    const float* __restrict__ vg, const float* __restrict__ vb, const float* __restrict__ vmn, const float* __restrict__ vvv)
{
    __shared__ SmemTiles st;
    uint32_t asb = smem_u32(st.As), bsb = smem_u32(st.Bs);
    int tid = threadIdx.x, lane = tid & 31, wid = tid >> 5;
    int wm = (wid & 3) * 32, wn = (wid >> 2) * 64;
    int bx = blockIdx.x, br = blockIdx.y;
    int nt = bx & 1, mt = (bx >> 1) & 3, b = bx >> 3;

    const float* G  = (br == 0) ? qg : (br == 1) ? kg : vg;
    const float* Bt = (br == 0) ? qb : (br == 1) ? kb : vb;
    const float* M  = (br == 0) ? qm : (br == 1) ? km : vmn;
    const float* V  = (br == 0) ? qv : (br == 1) ? kvv : vvv;
    float* outp = (br == 0) ? g_q : (br == 1) ? g_k : g_v;

    float scl[2][2], mean[2][2], beta[2][2];
    #pragma unroll
    for (int i = 0; i < 2; i++)
        #pragma unroll
        for (int rh = 0; rh < 2; rh++) {
            int o = mt*128 + wm + i*16 + rh*8 + (lane >> 2);
            scl[i][rh]  = G[o] / sqrtf(V[o] + 1e-5f);
            mean[i][rh] = M[o];
            beta[i][rh] = Bt[o];
        }

    float vm[2][2][8][2];
    #pragma unroll
    for (int i = 0; i < 2; i++)
        #pragma unroll
        for (int rh = 0; rh < 2; rh++)
            #pragma unroll
            for (int j = 0; j < 8; j++) { vm[i][rh][j][0] = 0.f; vm[i][rh][j][1] = 0.f; }

    for (int t = 0; t < T_; t++) {
        float acc[2][8][4];
        #pragma unroll
        for (int i = 0; i < 2; i++)
            #pragma unroll
            for (int j = 0; j < 8; j++)
                #pragma unroll
                for (int p = 0; p < 4; p++) acc[i][j][p] = 0.f;

        int rowbase = (t*B_ + b) * 256 + nt*128;
        gemm_pass(asb, bsb, acc, br, mt, g_xsT, rowbase, tid, wm, wn, lane);

        #pragma unroll
        for (int i = 0; i < 2; i++) {
            #pragma unroll
            for (int j = 0; j < 8; j++) {
                #pragma unroll
                for (int rh = 0; rh < 2; rh++) {
                    float y0 = (acc[i][j][rh*2+0] - mean[i][rh]) * scl[i][rh] + beta[i][rh];
                    float y1 = (acc[i][j][rh*2+1] - mean[i][rh]) * scl[i][rh] + beta[i][rh];
                    float s0 = lif_step(vm[i][rh][j][0], y0, 1.0f);
                    float s1 = lif_step(vm[i][rh][j][1], y1, 1.0f);
                    int o = mt*128 + wm + i*16 + rh*8 + (lane >> 2);
                    int n = nt*128 + wn + j*8 + 2*(lane & 3);
                    *(float2*)(outp + ((size_t)(t*B_ + b) * C_ + o) * N_ + n) = make_float2(s0, s1);
                }
            }
        }
        __syncthreads();
    }
}

// ============================================================
// K3a: kv[d,e] = sum_n k[n,d]*v[n,e] per (t,b,h). SIMT exact.
// ============================================================
__global__ __launch_bounds__(256) void kv_kernel() {
    __shared__ float Ks[64][68];
    __shared__ float Vs[64][68];
    int tbh = blockIdx.x;
    int tb = tbh >> 3, hh = tbh & 7;
    size_t base = ((size_t)tb * C_ + hh * D_) * N_;
    int tid = threadIdx.x, ty = tid >> 4, tx = tid & 15;

    u64 acc[4][2];
    #pragma unroll
    for (int i = 0; i < 4; i++) { acc[i][0] = 0ull; acc[i][1] = 0ull; }

    for (int nc = 0; nc < N_; nc += 64) {
        #pragma unroll
        for (int r = 0; r < 4; r++) {
            int i = tid + r * 256;
            int dd = i >> 4, n4 = i & 15;
            float4 kq = *(const float4*)(g_k + base + (size_t)dd * N_ + nc + n4 * 4);
            Ks[n4*4+0][dd] = kq.x; Ks[n4*4+1][dd] = kq.y;
            Ks[n4*4+2][dd] = kq.z; Ks[n4*4+3][dd] = kq.w;
            float4 vq = *(const float4*)(g_v + base + (size_t)dd * N_ + nc + n4 * 4);
            Vs[n4*4+0][dd] = vq.x; Vs[n4*4+1][dd] = vq.y;
            Vs[n4*4+2][dd] = vq.z; Vs[n4*4+3][dd] = vq.w;
        }
        __syncthreads();
        #pragma unroll 4
        for (int n = 0; n < 64; n++) {
            float4 a4 = *(const float4*)(&Ks[n][ty * 4]);
            float4 b4 = *(const float4*)(&Vs[n][tx * 4]);
            u64 pa0 = pack2(a4.x, a4.x), pa1 = pack2(a4.y, a4.y);
            u64 pa2 = pack2(a4.z, a4.z), pa3 = pack2(a4.w, a4.w);
            u64 b01 = pack2(b4.x, b4.y), b23 = pack2(b4.z, b4.w);
            FMA16_P(acc, pa0, pa1, pa2, pa3, b01, b23);
        }
        __syncthreads();
    }
    float* o = g_kv + (size_t)tbh * D_ * D_;
    #pragma unroll
    for (int i = 0; i < 4; i++) {
        float2 c01 = unpack2(acc[i][0]);
        float2 c23 = unpack2(acc[i][1]);
        *(float4*)(o + (ty * 4 + i) * D_ + tx * 4) = make_float4(c01.x, c01.y, c23.x, c23.y);
    }
}

// ============================================================
// K3b: a = (q @ kv)*0.125, LIF(0.5), emit fp16 spikes [tb][n][c].
// ============================================================
__global__ __launch_bounds__(256) void attn_kernel() {
    __shared__ float4 Qs[64][16];
    __shared__ float4 KVs[64][16];
    __shared__ __half Sb2[64][72];

    int bx = blockIdx.x;
    int ntile = bx & 3, hh = (bx >> 2) & 7, b = bx >> 5;
    int tid = threadIdx.x, ty = tid >> 4, tx = tid & 15;
    int nB = ntile * 64;
    int n_o = tid >> 2, u0 = tid & 3;

    float vm[4][4];
    #pragma unroll
    for (int i = 0; i < 4; i++)
        #pragma unroll
        for (int j = 0; j < 4; j++) vm[i][j] = 0.f;

    for (int t = 0; t < T_; t++) {
        int tb = t * B_ + b;
        #pragma unroll
        for (int r = 0; r < 4; r++) {
            int i = tid + r * 256;
            int dd = i >> 4, q4 = i & 15;
            Qs[dd][q4]  = *(const float4*)(g_q + ((size_t)tb * C_ + hh * D_ + dd) * N_ + nB + q4 * 4);
            KVs[dd][q4] = *(const float4*)(g_kv + ((size_t)tb * H_ + hh) * D_ * D_ + (size_t)dd * D_ + q4 * 4);
        }
        __syncthreads();
        u64 acc[4][2];
        #pragma unroll
        for (int i = 0; i < 4; i++) { acc[i][0] = 0ull; acc[i][1] = 0ull; }
        #pragma unroll 4
        for (int dd = 0; dd < 64; dd++) {
            float4 a4 = KVs[dd][ty];
            float4 b4 = Qs[dd][tx];
            u64 pa0 = pack2(a4.x, a4.x), pa1 = pack2(a4.y, a4.y);
            u64 pa2 = pack2(a4.z, a4.z), pa3 = pack2(a4.w, a4.w);
            u64 b01 = pack2(b4.x, b4.y), b23 = pack2(b4.z, b4.w);
            FMA16_P(acc, pa0, pa1, pa2, pa3, b01, b23);
        }
        #pragma unroll
        for (int i = 0; i < 4; i++) {
            float2 c01 = unpack2(acc[i][0]);
            float2 c23 = unpack2(acc[i][1]);
            Sb2[ty*4+i][tx*4+0] = __float2half_rn(lif_step(vm[i][0], c01.x * 0.125f, 0.5f));
            Sb2[ty*4+i][tx*4+1] = __float2half_rn(lif_step(vm[i][1], c01.y * 0.125f, 0.5f));
            Sb2[ty*4+i][tx*4+2] = __float2half_rn(lif_step(vm[i][2], c23.x * 0.125f, 0.5f));
            Sb2[ty*4+i][tx*4+3] = __float2half_rn(lif_step(vm[i][3], c23.y * 0.125f, 0.5f));
        }
        __syncthreads();
        char* outb = (char*)(g_sT + ((size_t)tb * N_ + nB + n_o) * C_ + hh*64);
        #pragma unroll
        for (int hf = 0; hf < 2; hf++) {
            int u = u0 + hf * 4;
            uint32_t rp[4];
            #pragma unroll
            for (int p = 0; p < 4; p++) {
                float lo = __half2float(Sb2[u*8 + p*2][n_o]);
                float hi = __half2float(Sb2[u*8 + p*2 + 1][n_o]);
                rp[p] = hpair(lo, hi);
            }
            *(uint4*)(outb + u*16) = make_uint4(rp[0], rp[1], rp[2], rp[3]);
        }
        __syncthreads();
    }
}

// ============================================================
// K4: proj GEMM + bias + BN -> d_out.  grid = nt2*mt4*tb128 = 1024.
// ============================================================
__global__ __launch_bounds__(256, 1) void proj_mma_kernel(
    const float* __restrict__ pbias, const float* __restrict__ pg, const float* __restrict__ pb,
    const float* __restrict__ pm, const float* __restrict__ pv, float* __restrict__ out)
{
    __shared__ SmemTiles st;
    uint32_t asb = smem_u32(st.As), bsb = smem_u32(st.Bs);
    int tid = threadIdx.x, lane = tid & 31, wid = tid >> 5;
    int wm = (wid & 3) * 32, wn = (wid >> 2) * 64;
    int bx = blockIdx.x;
    int nt = bx & 1, mt = (bx >> 1) & 3, tb = bx >> 3;

    float scl[2][2], mean[2][2], beta[2][2], bias[2][2];
    #pragma unroll
    for (int i = 0; i < 2; i++)
        #pragma unroll
        for (int rh = 0; rh < 2; rh++) {
            int o = mt*128 + wm + i*16 + rh*8 + (lane >> 2);
            scl[i][rh]  = pg[o] / sqrtf(pv[o] + 1e-5f);
            mean[i][rh] = pm[o];
            beta[i][rh] = pb[o];
            bias[i][rh] = pbias[o];
        }

    float acc[2][8][4];
    #pragma unroll
    for (int i = 0; i < 2; i++)
        #pragma unroll
        for (int j = 0; j < 8; j++)
            #pragma unroll
            for (int p = 0; p < 4; p++) acc[i][j][p] = 0.f;

    int rowbase = tb * 256 + nt*128;
    gemm_pass(asb, bsb, acc, 3, mt, g_sT, rowbase, tid, wm, wn, lane);

    #pragma unroll
    for (int i = 0; i < 2; i++) {
        #pragma unroll
        for (int j = 0; j < 8; j++) {
            #pragma unroll
            for (int rh = 0; rh < 2; rh++) {
                float y0 = ((acc[i][j][rh*2+0] + bias[i][rh]) - mean[i][rh]) * scl[i][rh] + beta[i][rh];
                float y1 = ((acc[i][j][rh*2+1] + bias[i][rh]) - mean[i][rh]) * scl[i][rh] + beta[i][rh];
                int o = mt*128 + wm + i*16 + rh*8 + (lane >> 2);
                int n = nt*128 + wn + j*8 + 2*(lane & 3);
                *(float2*)(out + ((size_t)tb * C_ + o) * N_ + n) = make_float2(y0, y1);
            }
        }
    }
}

// ============================================================
extern "C" void kernel_launch(void* const* d_in, const int* in_sizes, int n_in,
                              void* d_out, int out_size) {
    (void)in_sizes; (void)n_in; (void)out_size;
    const float* x  = (const float*)d_in[0];
    const float* qw = (const float*)d_in[1];
    const float* qg = (const float*)d_in[2];
    const float* qb = (const float*)d_in[3];
    const float* qm = (const float*)d_in[4];
    const float* qv = (const float*)d_in[5];
    const float* kw = (const float*)d_in[6];
    const float* kg = (const float*)d_in[7];
    const float* kb = (const float*)d_in[8];
    const float* km = (const float*)d_in[9];
    const float* kvv= (const float*)d_in[10];
    const float* vw = (const float*)d_in[11];
    const float* vg = (const float*)d_in[12];
    const float* vb = (const float*)d_in[13];
    const float* vm = (const float*)d_in[14];
    const float* vv = (const float*)d_in[15];
    const float* pw    = (const float*)d_in[16];
    const float* pbias = (const float*)d_in[17];
    const float* pg    = (const float*)d_in[18];
    const float* pb    = (const float*)d_in[19];
    const float* pm    = (const float*)d_in[20];
    const float* pv    = (const float*)d_in[21];

    wsplit_kernel<<<4096, 256>>>(qw, kw, vw, pw);
    lifx_kernel<<<1024, 256>>>(x);
    qkv_mma_kernel<<<dim3(256, 3), 256>>>(qg, qb, qm, qv, kg, kb, km, kvv, vg, vb, vm, vv);
    kv_kernel<<<1024, 256>>>();
    attn_kernel<<<1024, 256>>>();
    proj_mma_kernel<<<1024, 256>>>(pbias, pg, pb, pm, pv, (float*)d_out);
}

// round 7
// speedup vs baseline: 2.0994x; 1.1287x over previous
#include <cuda_runtime.h>
#include <cuda_fp16.h>
#include <cstdint>

#define T_ 4
#define B_ 32
#define C_ 512
#define N_ 256
#define H_ 8
#define D_ 64
#define BCN_ (B_*C_*N_)
#define TBCN_ (T_*BCN_)

// ---- scratch ----
__device__ __half g_qh[TBCN_];         // [tb][c][n] fp16 spikes
__device__ __half g_kh[TBCN_];
__device__ __half g_vh[TBCN_];
__device__ __half g_qT[TBCN_];         // [tb][n][c] fp16 spikes
__device__ __half g_xsT[TBCN_];        // [t][b][n][c] spikes fp16 (K-major)
__device__ __half g_sT[TBCN_];         // [tb][n][c] attn spikes fp16
__device__ __half g_kvT[T_*B_*H_*D_*D_]; // [tbh][e][d], pre-scaled by 0.125
__device__ __half g_wl[4*2*C_*C_];     // [mat][limb][o][c] fp16 weight limbs

// ================= helpers =================
__device__ __forceinline__ uint32_t smem_u32(const void* p) {
    uint32_t a;
    asm("{ .reg .u64 t; cvta.to.shared.u64 t, %1; cvt.u32.u64 %0, t; }" : "=r"(a) : "l"(p));
    return a;
}

#define CP16(dst, src) \
    asm volatile("cp.async.cg.shared.global [%0], [%1], 16;" :: "r"(dst), "l"(src))
#define CP_COMMIT() asm volatile("cp.async.commit_group;" ::: "memory")
#define CP_WAIT(n)  asm volatile("cp.async.wait_group %0;" :: "n"(n) : "memory")

__device__ __forceinline__ void ldm_x4(uint32_t r[4], uint32_t addr) {
    asm volatile("ldmatrix.sync.aligned.m8n8.x4.shared.b16 {%0,%1,%2,%3}, [%4];"
        : "=r"(r[0]), "=r"(r[1]), "=r"(r[2]), "=r"(r[3]) : "r"(addr));
}
__device__ __forceinline__ void mma16816(float c[4], const uint32_t a[4], const uint32_t* b) {
    asm volatile("mma.sync.aligned.m16n8k16.row.col.f32.f16.f16.f32 "
        "{%0,%1,%2,%3}, {%4,%5,%6,%7}, {%8,%9}, {%0,%1,%2,%3};"
        : "+f"(c[0]), "+f"(c[1]), "+f"(c[2]), "+f"(c[3])
        : "r"(a[0]), "r"(a[1]), "r"(a[2]), "r"(a[3]), "r"(b[0]), "r"(b[1]));
}

__device__ __forceinline__ float lif_step(float& v, float x, float vth) {
    v += (x - v) * 0.5f;
    float s = (v >= vth) ? 1.0f : 0.0f;
    if (s != 0.0f) v = 0.0f;
    return s;
}
__device__ __forceinline__ uint32_t hpair(float lo, float hi) {
    return (uint32_t)__half_as_ushort(__float2half_rn(lo)) |
           ((uint32_t)__half_as_ushort(__float2half_rn(hi)) << 16);
}

// ============================================================
// K0: fp32 weights -> 2 fp16 limbs, natural [mat][limb][o][c]
// ============================================================
__global__ void wsplit_kernel(const float* __restrict__ qw, const float* __restrict__ kw,
                              const float* __restrict__ vw, const float* __restrict__ pw) {
    int i = blockIdx.x * 256 + threadIdx.x;
    int mat = i >> 18, idx = i & 262143;
    const float* W = (mat == 0) ? qw : (mat == 1) ? kw : (mat == 2) ? vw : pw;
    float w = W[idx];
    __half h1 = __float2half_rn(w);
    float r1 = w - __half2float(h1);
    __half h2 = __float2half_rn(r1);
    size_t base = (size_t)(mat * 2) * 262144 + idx;
    g_wl[base] = h1;
    g_wl[base + 262144] = h2;
}

// ============================================================
// K1: LIF(x) -> fp16 spikes, transposed [t][b][n][c]
// grid: ch(8) x nt(4) x b(32) = 1024, 256 thr
// ============================================================
__global__ __launch_bounds__(256) void lifx_kernel(const float* __restrict__ x) {
    __shared__ __half Sb[64][72];
    int bx = blockIdx.x;
    int ch = bx & 7, nt = (bx >> 3) & 3, b = bx >> 5;
    int tid = threadIdx.x;
    int c_l = tid >> 2, ng = tid & 3;
    int n_o = tid >> 2, u0 = tid & 3;
    float vm[16];
    #pragma unroll
    for (int j = 0; j < 16; j++) vm[j] = 0.f;

    for (int t = 0; t < T_; t++) {
        const float* xp = x + (((size_t)(t * B_ + b)) * C_ + ch * 64 + c_l) * N_ + nt * 64 + ng * 16;
        #pragma unroll
        for (int q = 0; q < 4; q++) {
            float4 xv = *(const float4*)(xp + q * 4);
            Sb[c_l][ng*16 + q*4 + 0] = __float2half_rn(lif_step(vm[q*4+0], xv.x, 1.0f));
            Sb[c_l][ng*16 + q*4 + 1] = __float2half_rn(lif_step(vm[q*4+1], xv.y, 1.0f));
            Sb[c_l][ng*16 + q*4 + 2] = __float2half_rn(lif_step(vm[q*4+2], xv.z, 1.0f));
            Sb[c_l][ng*16 + q*4 + 3] = __float2half_rn(lif_step(vm[q*4+3], xv.w, 1.0f));
        }
        __syncthreads();
        char* outb = (char*)(g_xsT + ((size_t)(t*B_ + b) * N_ + nt*64 + n_o) * C_ + ch*64);
        #pragma unroll
        for (int hf = 0; hf < 2; hf++) {
            int u = u0 + hf * 4;
            uint32_t rp[4];
            #pragma unroll
            for (int p = 0; p < 4; p++) {
                float lo = __half2float(Sb[u*8 + p*2][n_o]);
                float hi = __half2float(Sb[u*8 + p*2 + 1][n_o]);
                rp[p] = hpair(lo, hi);
            }
            *(uint4*)(outb + u*16) = make_uint4(rp[0], rp[1], rp[2], rp[3]);
        }
        __syncthreads();
    }
}

// ============================================================
// Shared GEMM machinery (qkv/proj): 128x128 block, 8 warps.
// ============================================================
struct SmemTiles {
    __align__(16) __half As[2][2][128][24];
    __align__(16) __half Bs[2][128][24];
};

__device__ __forceinline__ void load_stage_A(uint32_t asb, int s, int kc, int wmat, int mt, int tid) {
    #pragma unroll
    for (int r = 0; r < 2; r++) {
        int idx = tid + r * 256;
        int l = idx >> 8, rem = idx & 255;
        int o = rem >> 1, h = rem & 1;
        const __half* src = g_wl + ((size_t)(wmat*2 + l) * 512 + mt*128 + o) * 512 + kc + h*8;
        uint32_t dst = asb + (uint32_t)((((s*2 + l)*128 + o)*24 + h*8) * 2);
        CP16(dst, src);
    }
}
__device__ __forceinline__ void load_stage_B(uint32_t bsb, int s, int kc,
                                             const __half* srcT, int rowbase, int tid) {
    int n = tid >> 1, h = tid & 1;
    const __half* src = srcT + ((size_t)(rowbase + n)) * 512 + kc + h*8;
    uint32_t dst = bsb + (uint32_t)(((s*128 + n)*24 + h*8) * 2);
    CP16(dst, src);
}

__device__ __forceinline__ void gemm_pass(uint32_t asb, uint32_t bsb, float acc[2][8][4],
                                          int wmat, int mt, const __half* srcT, int rowbase,
                                          int tid, int wm, int wn, int lane) {
    load_stage_A(asb, 0, 0, wmat, mt, tid);
    load_stage_B(bsb, 0, 0, srcT, rowbase, tid);
    CP_COMMIT();
    int a_row = lane & 15, a_col = (lane >> 4) * 8;
    int b_row = wn + (lane & 7) + ((lane >> 4) << 3), b_col = lane & 8;

    for (int c = 0; c < 32; c++) {
        int s = c & 1, ns = s ^ 1;
        __syncthreads();
        if (c < 31) {
            load_stage_A(asb, ns, (c+1)*16, wmat, mt, tid);
            load_stage_B(bsb, ns, (c+1)*16, srcT, rowbase, tid);
            CP_COMMIT();
            CP_WAIT(1);
        } else {
            CP_WAIT(0);
        }
        __syncthreads();
        uint32_t bfr[8][2];
        #pragma unroll
        for (int jp = 0; jp < 4; jp++) {
            uint32_t r4[4];
            uint32_t addr = bsb + (uint32_t)((((s*128) + b_row + jp*16)*24 + b_col) * 2);
            ldm_x4(r4, addr);
            bfr[jp*2][0] = r4[0];   bfr[jp*2][1] = r4[1];
            bfr[jp*2+1][0] = r4[2]; bfr[jp*2+1][1] = r4[3];
        }
        #pragma unroll
        for (int l = 0; l < 2; l++) {
            #pragma unroll
            for (int i = 0; i < 2; i++) {
                uint32_t a4[4];
                uint32_t addr = asb + (uint32_t)(((((s*2 + l)*128) + wm + i*16 + a_row)*24 + a_col) * 2);
                ldm_x4(a4, addr);
                #pragma unroll
                for (int j = 0; j < 8; j++)
                    mma16816(acc[i][j], a4, bfr[j]);
            }
        }
    }
}

// ============================================================
// K2: qkv GEMM + BN + LIF -> fp16 spikes [tb][c][n].
// grid.x = nt2*mt4*b32 = 256, grid.y = br3.
// ============================================================
__global__ __launch_bounds__(256, 1) void qkv_mma_kernel(
    const float* __restrict__ qg, const float* __restrict__ qb, const float* __restrict__ qm, const float* __restrict__ qv,
    const float* __restrict__ kg, const float* __restrict__ kb, const float* __restrict__ km, const float* __restrict__ kvv,
    const float* __restrict__ vg, const float* __restrict__ vb, const float* __restrict__ vmn, const float* __restrict__ vvv)
{
    __shared__ SmemTiles st;
    uint32_t asb = smem_u32(st.As), bsb = smem_u32(st.Bs);
    int tid = threadIdx.x, lane = tid & 31, wid = tid >> 5;
    int wm = (wid & 3) * 32, wn = (wid >> 2) * 64;
    int bx = blockIdx.x, br = blockIdx.y;
    int nt = bx & 1, mt = (bx >> 1) & 3, b = bx >> 3;

    const float* G  = (br == 0) ? qg : (br == 1) ? kg : vg;
    const float* Bt = (br == 0) ? qb : (br == 1) ? kb : vb;
    const float* M  = (br == 0) ? qm : (br == 1) ? km : vmn;
    const float* V  = (br == 0) ? qv : (br == 1) ? kvv : vvv;
    __half* outp = (br == 0) ? g_qh : (br == 1) ? g_kh : g_vh;

    float scl[2][2], mean[2][2], beta[2][2];
    #pragma unroll
    for (int i = 0; i < 2; i++)
        #pragma unroll
        for (int rh = 0; rh < 2; rh++) {
            int o = mt*128 + wm + i*16 + rh*8 + (lane >> 2);
            scl[i][rh]  = G[o] / sqrtf(V[o] + 1e-5f);
            mean[i][rh] = M[o];
            beta[i][rh] = Bt[o];
        }

    float vm[2][2][8][2];
    #pragma unroll
    for (int i = 0; i < 2; i++)
        #pragma unroll
        for (int rh = 0; rh < 2; rh++)
            #pragma unroll
            for (int j = 0; j < 8; j++) { vm[i][rh][j][0] = 0.f; vm[i][rh][j][1] = 0.f; }

    for (int t = 0; t < T_; t++) {
        float acc[2][8][4];
        #pragma unroll
        for (int i = 0; i < 2; i++)
            #pragma unroll
            for (int j = 0; j < 8; j++)
                #pragma unroll
                for (int p = 0; p < 4; p++) acc[i][j][p] = 0.f;

        int rowbase = (t*B_ + b) * 256 + nt*128;
        gemm_pass(asb, bsb, acc, br, mt, g_xsT, rowbase, tid, wm, wn, lane);

        #pragma unroll
        for (int i = 0; i < 2; i++) {
            #pragma unroll
            for (int j = 0; j < 8; j++) {
                #pragma unroll
                for (int rh = 0; rh < 2; rh++) {
                    float y0 = (acc[i][j][rh*2+0] - mean[i][rh]) * scl[i][rh] + beta[i][rh];
                    float y1 = (acc[i][j][rh*2+1] - mean[i][rh]) * scl[i][rh] + beta[i][rh];
                    float s0 = lif_step(vm[i][rh][j][0], y0, 1.0f);
                    float s1 = lif_step(vm[i][rh][j][1], y1, 1.0f);
                    int o = mt*128 + wm + i*16 + rh*8 + (lane >> 2);
                    int n = nt*128 + wn + j*8 + 2*(lane & 3);
                    *(uint32_t*)(outp + ((size_t)(t*B_ + b) * C_ + o) * N_ + n) = hpair(s0, s1);
                }
            }
        }
        __syncthreads();
    }
}

// ============================================================
// K2b: transpose q spikes [tb][c][n] -> [tb][n][c] fp16.
// grid: ct(8) x ntt(4) x tb(128) = 4096, 256 thr
// ============================================================
__global__ __launch_bounds__(256) void qtrans_kernel() {
    __shared__ __half Sb[64][72];
    int bx = blockIdx.x;
    int ct = bx & 7, ntt = (bx >> 3) & 3, tb = bx >> 5;
    int tid = threadIdx.x;
    int c_l = tid >> 2, ng = tid & 3;
    int n_o = tid >> 2, u0 = tid & 3;

    const __half* src = g_qh + ((size_t)tb * C_ + ct*64 + c_l) * N_ + ntt*64;
    #pragma unroll
    for (int hf = 0; hf < 2; hf++) {
        int cchunk = ng*2 + hf;
        *(uint4*)(&Sb[c_l][cchunk*8]) = *(const uint4*)(src + cchunk*8);
    }
    __syncthreads();
    char* outb = (char*)(g_qT + ((size_t)tb * N_ + ntt*64 + n_o) * C_ + ct*64);
    #pragma unroll
    for (int hf = 0; hf < 2; hf++) {
        int u = u0 + hf * 4;
        uint32_t rp[4];
        #pragma unroll
        for (int p = 0; p < 4; p++) {
            float lo = __half2float(Sb[u*8 + p*2][n_o]);
            float hi = __half2float(Sb[u*8 + p*2 + 1][n_o]);
            rp[p] = hpair(lo, hi);
        }
        *(uint4*)(outb + u*16) = make_uint4(rp[0], rp[1], rp[2], rp[3]);
    }
}

// ============================================================
// K3a: kvT[e][d] = 0.125 * sum_n v[n,e]*k[n,d], fp16 MMA, exact.
// grid = 1024 (t,b,h), 128 thr (4 warps, 32x32 tiles).
// ============================================================
__global__ __launch_bounds__(128) void kvh_kernel() {
    __shared__ __align__(16) __half Ah[64][136];   // v rows e, K=n chunk
    __shared__ __align__(16) __half Bh[64][136];   // k rows d
    uint32_t ahb = smem_u32(Ah), bhb = smem_u32(Bh);
    int tbh = blockIdx.x;
    int tb = tbh >> 3, hh = tbh & 7;
    int tid = threadIdx.x, lane = tid & 31, wid = tid >> 5;
    int em = (wid & 1) * 32, dn = (wid >> 1) * 32;

    const __half* vsrc = g_vh + ((size_t)tb * C_ + hh*64) * N_;
    const __half* ksrc = g_kh + ((size_t)tb * C_ + hh*64) * N_;

    float acc[2][4][4];
    #pragma unroll
    for (int i = 0; i < 2; i++)
        #pragma unroll
        for (int j = 0; j < 4; j++)
            #pragma unroll
            for (int p = 0; p < 4; p++) acc[i][j][p] = 0.f;

    int a_row = lane & 15, a_col = (lane >> 4) * 8;
    int b_row0 = dn + (lane & 7) + ((lane >> 4) << 3), b_col = lane & 8;

    for (int ch = 0; ch < 2; ch++) {
        #pragma unroll
        for (int r = 0; r < 4; r++) {
            int idx = tid + r * 128;           // 0..511
            int row = idx >> 3, cchunk = idx & 7;
            CP16(ahb + (uint32_t)((row*136 + cchunk*8) * 2), vsrc + (size_t)row * N_ + ch*128 + cchunk*8);
            CP16(bhb + (uint32_t)((row*136 + cchunk*8) * 2), ksrc + (size_t)row * N_ + ch*128 + cchunk*8);
        }
        CP_COMMIT(); CP_WAIT(0);
        __syncthreads();
        #pragma unroll
        for (int ks = 0; ks < 8; ks++) {
            int kc = ks * 16;
            uint32_t bfr[4][2];
            #pragma unroll
            for (int jp = 0; jp < 2; jp++) {
                uint32_t r4[4];
                ldm_x4(r4, bhb + (uint32_t)(((b_row0 + jp*16)*136 + kc + b_col) * 2));
                bfr[jp*2][0] = r4[0];   bfr[jp*2][1] = r4[1];
                bfr[jp*2+1][0] = r4[2]; bfr[jp*2+1][1] = r4[3];
            }
            #pragma unroll
            for (int i = 0; i < 2; i++) {
                uint32_t a4[4];
                ldm_x4(a4, ahb + (uint32_t)(((em + i*16 + a_row)*136 + kc + a_col) * 2));
                #pragma unroll
                for (int j = 0; j < 4; j++)
                    mma16816(acc[i][j], a4, bfr[j]);
            }
        }
        __syncthreads();
    }

    #pragma unroll
    for (int i = 0; i < 2; i++) {
        #pragma unroll
        for (int j = 0; j < 4; j++) {
            int e0 = em + i*16 + (lane >> 2);
            int d0 = dn + j*8 + 2*(lane & 3);
            *(uint32_t*)(g_kvT + ((size_t)tbh*64 + e0) * 64 + d0) =
                hpair(acc[i][j][0] * 0.125f, acc[i][j][1] * 0.125f);
            *(uint32_t*)(g_kvT + ((size_t)tbh*64 + e0 + 8) * 64 + d0) =
                hpair(acc[i][j][2] * 0.125f, acc[i][j][3] * 0.125f);
        }
    }
}

// ============================================================
// K3b: a[n][e] = qT @ kvT^T (scale folded), LIF(0.5) over t,
// write fp16 spikes g_sT [tb][n][c].  grid = nt2*h8*b32 = 512, 256 thr.
// ============================================================
__global__ __launch_bounds__(256) void attn_mma_kernel() {
    __shared__ __align__(16) __half Aq[128][72];
    __shared__ __align__(16) __half Bkv[64][72];
    uint32_t aqb = smem_u32(Aq), bkb = smem_u32(Bkv);
    int bx = blockIdx.x;
    int nt = bx & 1, hh = (bx >> 1) & 7, b = bx >> 4;
    int tid = threadIdx.x, lane = tid & 31, wid = tid >> 5;
    int nb = (wid & 3) * 32, eb = (wid >> 2) * 32;

    int a_row = lane & 15, a_col = (lane >> 4) * 8;
    int b_row0 = eb + (lane & 7) + ((lane >> 4) << 3), b_col = lane & 8;

    float vm[2][4][4];
    #pragma unroll
    for (int i = 0; i < 2; i++)
        #pragma unroll
        for (int j = 0; j < 4; j++)
            #pragma unroll
            for (int p = 0; p < 4; p++) vm[i][j][p] = 0.f;

    for (int t = 0; t < T_; t++) {
        int tb = t * B_ + b, tbh = tb * 8 + hh;
        #pragma unroll
        for (int r = 0; r < 4; r++) {
            int idx = tid + r * 256;          // 0..1023: 128 rows x 8 chunks
            int row = idx >> 3, cchunk = idx & 7;
            CP16(aqb + (uint32_t)((row*72 + cchunk*8) * 2),
                 g_qT + ((size_t)tb * N_ + nt*128 + row) * C_ + hh*64 + cchunk*8);
        }
        #pragma unroll
        for (int r = 0; r < 2; r++) {
            int idx = tid + r * 256;          // 0..511: 64 rows x 8 chunks
            int row = idx >> 3, cchunk = idx & 7;
            CP16(bkb + (uint32_t)((row*72 + cchunk*8) * 2),
                 g_kvT + ((size_t)tbh*64 + row) * 64 + cchunk*8);
        }
        CP_COMMIT(); CP_WAIT(0);
        __syncthreads();

        float acc[2][4][4];
        #pragma unroll
        for (int i = 0; i < 2; i++)
            #pragma unroll
            for (int j = 0; j < 4; j++)
                #pragma unroll
                for (int p = 0; p < 4; p++) acc[i][j][p] = 0.f;

        #pragma unroll
        for (int ks = 0; ks < 4; ks++) {
            int kc = ks * 16;
            uint32_t bfr[4][2];
            #pragma unroll
            for (int jp = 0; jp < 2; jp++) {
                uint32_t r4[4];
                ldm_x4(r4, bkb + (uint32_t)(((b_row0 + jp*16)*72 + kc + b_col) * 2));
                bfr[jp*2][0] = r4[0];   bfr[jp*2][1] = r4[1];
                bfr[jp*2+1][0] = r4[2]; bfr[jp*2+1][1] = r4[3];
            }
            #pragma unroll
            for (int i = 0; i < 2; i++) {
                uint32_t a4[4];
                ldm_x4(a4, aqb + (uint32_t)(((nb + i*16 + a_row)*72 + kc + a_col) * 2));
                #pragma unroll
                for (int j = 0; j < 4; j++)
                    mma16816(acc[i][j], a4, bfr[j]);
            }
        }

        #pragma unroll
        for (int i = 0; i < 2; i++) {
            #pragma unroll
            for (int j = 0; j < 4; j++) {
                int n0 = nb + i*16 + (lane >> 2);
                int e0 = eb + j*8 + 2*(lane & 3);
                float s0 = lif_step(vm[i][j][0], acc[i][j][0], 0.5f);
                float s1 = lif_step(vm[i][j][1], acc[i][j][1], 0.5f);
                float s2 = lif_step(vm[i][j][2], acc[i][j][2], 0.5f);
                float s3 = lif_step(vm[i][j][3], acc[i][j][3], 0.5f);
                *(uint32_t*)(g_sT + ((size_t)tb * N_ + nt*128 + n0) * C_ + hh*64 + e0) = hpair(s0, s1);
                *(uint32_t*)(g_sT + ((size_t)tb * N_ + nt*128 + n0 + 8) * C_ + hh*64 + e0) = hpair(s2, s3);
            }
        }
        __syncthreads();
    }
}

// ============================================================
// K4: proj GEMM + bias + BN -> d_out.  grid = nt2*mt4*tb128 = 1024.
// ============================================================
__global__ __launch_bounds__(256, 1) void proj_mma_kernel(
    const float* __restrict__ pbias, const float* __restrict__ pg, const float* __restrict__ pb,
    const float* __restrict__ pm, const float* __restrict__ pv, float* __restrict__ out)
{
    __shared__ SmemTiles st;
    uint32_t asb = smem_u32(st.As), bsb = smem_u32(st.Bs);
    int tid = threadIdx.x, lane = tid & 31, wid = tid >> 5;
    int wm = (wid & 3) * 32, wn = (wid >> 2) * 64;
    int bx = blockIdx.x;
    int nt = bx & 1, mt = (bx >> 1) & 3, tb = bx >> 3;

    float scl[2][2], mean[2][2], beta[2][2], bias[2][2];
    #pragma unroll
    for (int i = 0; i < 2; i++)
        #pragma unroll
        for (int rh = 0; rh < 2; rh++) {
            int o = mt*128 + wm + i*16 + rh*8 + (lane >> 2);
            scl[i][rh]  = pg[o] / sqrtf(pv[o] + 1e-5f);
            mean[i][rh] = pm[o];
            beta[i][rh] = pb[o];
            bias[i][rh] = pbias[o];
        }

    float acc[2][8][4];
    #pragma unroll
    for (int i = 0; i < 2; i++)
        #pragma unroll
        for (int j = 0; j < 8; j++)
            #pragma unroll
            for (int p = 0; p < 4; p++) acc[i][j][p] = 0.f;

    int rowbase = tb * 256 + nt*128;
    gemm_pass(asb, bsb, acc, 3, mt, g_sT, rowbase, tid, wm, wn, lane);

    #pragma unroll
    for (int i = 0; i < 2; i++) {
        #pragma unroll
        for (int j = 0; j < 8; j++) {
            #pragma unroll
            for (int rh = 0; rh < 2; rh++) {
                float y0 = ((acc[i][j][rh*2+0] + bias[i][rh]) - mean[i][rh]) * scl[i][rh] + beta[i][rh];
                float y1 = ((acc[i][j][rh*2+1] + bias[i][rh]) - mean[i][rh]) * scl[i][rh] + beta[i][rh];
                int o = mt*128 + wm + i*16 + rh*8 + (lane >> 2);
                int n = nt*128 + wn + j*8 + 2*(lane & 3);
                *(float2*)(out + ((size_t)tb * C_ + o) * N_ + n) = make_float2(y0, y1);
            }
        }
    }
}

// ============================================================
extern "C" void kernel_launch(void* const* d_in, const int* in_sizes, int n_in,
                              void* d_out, int out_size) {
    (void)in_sizes; (void)n_in; (void)out_size;
    const float* x  = (const float*)d_in[0];
    const float* qw = (const float*)d_in[1];
    const float* qg = (const float*)d_in[2];
    const float* qb = (const float*)d_in[3];
    const float* qm = (const float*)d_in[4];
    const float* qv = (const float*)d_in[5];
    const float* kw = (const float*)d_in[6];
    const float* kg = (const float*)d_in[7];
    const float* kb = (const float*)d_in[8];
    const float* km = (const float*)d_in[9];
    const float* kvv= (const float*)d_in[10];
    const float* vw = (const float*)d_in[11];
    const float* vg = (const float*)d_in[12];
    const float* vb = (const float*)d_in[13];
    const float* vm = (const float*)d_in[14];
    const float* vv = (const float*)d_in[15];
    const float* pw    = (const float*)d_in[16];
    const float* pbias = (const float*)d_in[17];
    const float* pg    = (const float*)d_in[18];
    const float* pb    = (const float*)d_in[19];
    const float* pm    = (const float*)d_in[20];
    const float* pv    = (const float*)d_in[21];

    wsplit_kernel<<<4096, 256>>>(qw, kw, vw, pw);
    lifx_kernel<<<1024, 256>>>(x);
    qkv_mma_kernel<<<dim3(256, 3), 256>>>(qg, qb, qm, qv, kg, kb, km, kvv, vg, vb, vm, vv);
    qtrans_kernel<<<4096, 256>>>();
    kvh_kernel<<<1024, 128>>>();
    attn_mma_kernel<<<512, 256>>>();
    proj_mma_kernel<<<1024, 256>>>(pbias, pg, pb, pm, pv, (float*)d_out);
}

// round 8
// speedup vs baseline: 2.5742x; 1.2262x over previous
#include <cuda_runtime.h>
#include <cuda_fp16.h>
#include <cstdint>

#define T_ 4
#define B_ 32
#define C_ 512
#define N_ 256
#define H_ 8
#define D_ 64
#define BCN_ (B_*C_*N_)
#define TBCN_ (T_*BCN_)

// ---- scratch ----
__device__ __half g_qh[TBCN_];         // [tb][c][n] fp16 spikes
__device__ __half g_kh[TBCN_];
__device__ __half g_vh[TBCN_];
__device__ __half g_qT[TBCN_];         // [tb][n][c] fp16 spikes
__device__ __half g_xsT[TBCN_];        // [t][b][n][c] spikes fp16 (K-major)
__device__ __half g_sT[TBCN_];         // [tb][n][c] attn spikes fp16
__device__ __half g_kvT[T_*B_*H_*D_*D_]; // [tbh][e][d], pre-scaled by 0.125
__device__ __half g_wl[4*2*C_*C_];     // [mat][limb][o][c] fp16 weight limbs

// ================= helpers =================
__device__ __forceinline__ uint32_t smem_u32(const void* p) {
    uint32_t a;
    asm("{ .reg .u64 t; cvta.to.shared.u64 t, %1; cvt.u32.u64 %0, t; }" : "=r"(a) : "l"(p));
    return a;
}

#define CP16(dst, src) \
    asm volatile("cp.async.cg.shared.global [%0], [%1], 16;" :: "r"(dst), "l"(src))
#define CP_COMMIT() asm volatile("cp.async.commit_group;" ::: "memory")
#define CP_WAIT(n)  asm volatile("cp.async.wait_group %0;" :: "n"(n) : "memory")

__device__ __forceinline__ void ldm_x4(uint32_t r[4], uint32_t addr) {
    asm volatile("ldmatrix.sync.aligned.m8n8.x4.shared.b16 {%0,%1,%2,%3}, [%4];"
        : "=r"(r[0]), "=r"(r[1]), "=r"(r[2]), "=r"(r[3]) : "r"(addr));
}
__device__ __forceinline__ void mma16816(float c[4], const uint32_t a[4], const uint32_t* b) {
    asm volatile("mma.sync.aligned.m16n8k16.row.col.f32.f16.f16.f32 "
        "{%0,%1,%2,%3}, {%4,%5,%6,%7}, {%8,%9}, {%0,%1,%2,%3};"
        : "+f"(c[0]), "+f"(c[1]), "+f"(c[2]), "+f"(c[3])
        : "r"(a[0]), "r"(a[1]), "r"(a[2]), "r"(a[3]), "r"(b[0]), "r"(b[1]));
}

__device__ __forceinline__ float lif_step(float& v, float x, float vth) {
    v += (x - v) * 0.5f;
    float s = (v >= vth) ? 1.0f : 0.0f;
    if (s != 0.0f) v = 0.0f;
    return s;
}
__device__ __forceinline__ uint32_t hpair(float lo, float hi) {
    return (uint32_t)__half_as_ushort(__float2half_rn(lo)) |
           ((uint32_t)__half_as_ushort(__float2half_rn(hi)) << 16);
}

// ============================================================
// K0: fp32 weights -> 2 fp16 limbs, natural [mat][limb][o][c]
// ============================================================
__global__ void wsplit_kernel(const float* __restrict__ qw, const float* __restrict__ kw,
                              const float* __restrict__ vw, const float* __restrict__ pw) {
    int i = blockIdx.x * 256 + threadIdx.x;
    int mat = i >> 18, idx = i & 262143;
    const float* W = (mat == 0) ? qw : (mat == 1) ? kw : (mat == 2) ? vw : pw;
    float w = W[idx];
    __half h1 = __float2half_rn(w);
    float r1 = w - __half2float(h1);
    __half h2 = __float2half_rn(r1);
    size_t base = (size_t)(mat * 2) * 262144 + idx;
    g_wl[base] = h1;
    g_wl[base + 262144] = h2;
}

// ============================================================
// K1: LIF(x) -> fp16 spikes, transposed [t][b][n][c]
// ============================================================
__global__ __launch_bounds__(256) void lifx_kernel(const float* __restrict__ x) {
    __shared__ __half Sb[64][72];
    int bx = blockIdx.x;
    int ch = bx & 7, nt = (bx >> 3) & 3, b = bx >> 5;
    int tid = threadIdx.x;
    int c_l = tid >> 2, ng = tid & 3;
    int n_o = tid >> 2, u0 = tid & 3;
    float vm[16];
    #pragma unroll
    for (int j = 0; j < 16; j++) vm[j] = 0.f;

    for (int t = 0; t < T_; t++) {
        const float* xp = x + (((size_t)(t * B_ + b)) * C_ + ch * 64 + c_l) * N_ + nt * 64 + ng * 16;
        #pragma unroll
        for (int q = 0; q < 4; q++) {
            float4 xv = *(const float4*)(xp + q * 4);
            Sb[c_l][ng*16 + q*4 + 0] = __float2half_rn(lif_step(vm[q*4+0], xv.x, 1.0f));
            Sb[c_l][ng*16 + q*4 + 1] = __float2half_rn(lif_step(vm[q*4+1], xv.y, 1.0f));
            Sb[c_l][ng*16 + q*4 + 2] = __float2half_rn(lif_step(vm[q*4+2], xv.z, 1.0f));
            Sb[c_l][ng*16 + q*4 + 3] = __float2half_rn(lif_step(vm[q*4+3], xv.w, 1.0f));
        }
        __syncthreads();
        char* outb = (char*)(g_xsT + ((size_t)(t*B_ + b) * N_ + nt*64 + n_o) * C_ + ch*64);
        #pragma unroll
        for (int hf = 0; hf < 2; hf++) {
            int u = u0 + hf * 4;
            uint32_t rp[4];
            #pragma unroll
            for (int p = 0; p < 4; p++) {
                float lo = __half2float(Sb[u*8 + p*2][n_o]);
                float hi = __half2float(Sb[u*8 + p*2 + 1][n_o]);
                rp[p] = hpair(lo, hi);
            }
            *(uint4*)(outb + u*16) = make_uint4(rp[0], rp[1], rp[2], rp[3]);
        }
        __syncthreads();
    }
}

// ============================================================
// GEMM machinery (qkv/proj): 128x128 block, 8 warps, 3-stage
// cp.async pipeline, ONE __syncthreads per k16 chunk.
// Dynamic smem: As[3][2][128][24] (36864B) + Bs[3][128][24] (18432B).
// ============================================================
#define A_STAGE_BYTES (2*128*24*2)
#define GEMM_SMEM (3*A_STAGE_BYTES + 3*128*24*2)

__device__ __forceinline__ void load_stage_A(uint32_t asb, int s, int kc, int wmat, int mt, int tid) {
    #pragma unroll
    for (int r = 0; r < 2; r++) {
        int idx = tid + r * 256;
        int l = idx >> 8, rem = idx & 255;
        int o = rem >> 1, h = rem & 1;
        const __half* src = g_wl + ((size_t)(wmat*2 + l) * 512 + mt*128 + o) * 512 + kc + h*8;
        uint32_t dst = asb + (uint32_t)((((s*2 + l)*128 + o)*24 + h*8) * 2);
        CP16(dst, src);
    }
}
__device__ __forceinline__ void load_stage_B(uint32_t bsb, int s, int kc,
                                             const __half* srcT, int rowbase, int tid) {
    int n = tid >> 1, h = tid & 1;
    const __half* src = srcT + ((size_t)(rowbase + n)) * 512 + kc + h*8;
    uint32_t dst = bsb + (uint32_t)(((s*128 + n)*24 + h*8) * 2);
    CP16(dst, src);
}

__device__ __forceinline__ void gemm_pass(uint32_t asb, uint32_t bsb, float acc[2][8][4],
                                          int wmat, int mt, const __half* srcT, int rowbase,
                                          int tid, int wm, int wn, int lane) {
    load_stage_A(asb, 0, 0, wmat, mt, tid);
    load_stage_B(bsb, 0, 0, srcT, rowbase, tid);
    CP_COMMIT();
    load_stage_A(asb, 1, 16, wmat, mt, tid);
    load_stage_B(bsb, 1, 16, srcT, rowbase, tid);
    CP_COMMIT();

    int a_row = lane & 15, a_col = (lane >> 4) * 8;
    int b_row = wn + (lane & 7) + ((lane >> 4) << 3), b_col = lane & 8;

    int s = 0;
    for (int c = 0; c < 32; c++) {
        CP_WAIT(1);              // stage c arrived (c+1 may be in flight)
        __syncthreads();         // all warps done with stage (c+2)%3's old data
        if (c + 2 < 32) {
            int ns = s + 2; if (ns >= 3) ns -= 3;
            load_stage_A(asb, ns, (c+2)*16, wmat, mt, tid);
            load_stage_B(bsb, ns, (c+2)*16, srcT, rowbase, tid);
        }
        CP_COMMIT();             // empty group in tail keeps numbering

        uint32_t bfr[8][2];
        #pragma unroll
        for (int jp = 0; jp < 4; jp++) {
            uint32_t r4[4];
            uint32_t addr = bsb + (uint32_t)((((s*128) + b_row + jp*16)*24 + b_col) * 2);
            ldm_x4(r4, addr);
            bfr[jp*2][0] = r4[0];   bfr[jp*2][1] = r4[1];
            bfr[jp*2+1][0] = r4[2]; bfr[jp*2+1][1] = r4[3];
        }
        #pragma unroll
        for (int l = 0; l < 2; l++) {
            #pragma unroll
            for (int i = 0; i < 2; i++) {
                uint32_t a4[4];
                uint32_t addr = asb + (uint32_t)(((((s*2 + l)*128) + wm + i*16 + a_row)*24 + a_col) * 2);
                ldm_x4(a4, addr);
                #pragma unroll
                for (int j = 0; j < 8; j++)
                    mma16816(acc[i][j], a4, bfr[j]);
            }
        }
        if (++s >= 3) s = 0;
    }
}

// ============================================================
// K2: qkv GEMM + BN + LIF -> fp16 spikes [tb][c][n].
// grid.x = nt2*mt4*b32 = 256, grid.y = br3.
// ============================================================
__global__ __launch_bounds__(256, 1) void qkv_mma_kernel(
    const float* __restrict__ qg, const float* __restrict__ qb, const float* __restrict__ qm, const float* __restrict__ qv,
    const float* __restrict__ kg, const float* __restrict__ kb, const float* __restrict__ km, const float* __restrict__ kvv,
    const float* __restrict__ vg, const float* __restrict__ vb, const float* __restrict__ vmn, const float* __restrict__ vvv)
{
    extern __shared__ char dynsmem[];
    uint32_t asb = smem_u32(dynsmem), bsb = asb + 3*A_STAGE_BYTES;
    int tid = threadIdx.x, lane = tid & 31, wid = tid >> 5;
    int wm = (wid & 3) * 32, wn = (wid >> 2) * 64;
    int bx = blockIdx.x, br = blockIdx.y;
    int nt = bx & 1, mt = (bx >> 1) & 3, b = bx >> 3;

    const float* G  = (br == 0) ? qg : (br == 1) ? kg : vg;
    const float* Bt = (br == 0) ? qb : (br == 1) ? kb : vb;
    const float* M  = (br == 0) ? qm : (br == 1) ? km : vmn;
    const float* V  = (br == 0) ? qv : (br == 1) ? kvv : vvv;
    __half* outp = (br == 0) ? g_qh : (br == 1) ? g_kh : g_vh;

    float scl[2][2], mean[2][2], beta[2][2];
    #pragma unroll
    for (int i = 0; i < 2; i++)
        #pragma unroll
        for (int rh = 0; rh < 2; rh++) {
            int o = mt*128 + wm + i*16 + rh*8 + (lane >> 2);
            scl[i][rh]  = G[o] / sqrtf(V[o] + 1e-5f);
            mean[i][rh] = M[o];
            beta[i][rh] = Bt[o];
        }

    float vm[2][2][8][2];
    #pragma unroll
    for (int i = 0; i < 2; i++)
        #pragma unroll
        for (int rh = 0; rh < 2; rh++)
            #pragma unroll
            for (int j = 0; j < 8; j++) { vm[i][rh][j][0] = 0.f; vm[i][rh][j][1] = 0.f; }

    for (int t = 0; t < T_; t++) {
        float acc[2][8][4];
        #pragma unroll
        for (int i = 0; i < 2; i++)
            #pragma unroll
            for (int j = 0; j < 8; j++)
                #pragma unroll
                for (int p = 0; p < 4; p++) acc[i][j][p] = 0.f;

        int rowbase = (t*B_ + b) * 256 + nt*128;
        gemm_pass(asb, bsb, acc, br, mt, g_xsT, rowbase, tid, wm, wn, lane);

        #pragma unroll
        for (int i = 0; i < 2; i++) {
            #pragma unroll
            for (int j = 0; j < 8; j++) {
                #pragma unroll
                for (int rh = 0; rh < 2; rh++) {
                    float y0 = (acc[i][j][rh*2+0] - mean[i][rh]) * scl[i][rh] + beta[i][rh];
                    float y1 = (acc[i][j][rh*2+1] - mean[i][rh]) * scl[i][rh] + beta[i][rh];
                    float s0 = lif_step(vm[i][rh][j][0], y0, 1.0f);
                    float s1 = lif_step(vm[i][rh][j][1], y1, 1.0f);
                    int o = mt*128 + wm + i*16 + rh*8 + (lane >> 2);
                    int n = nt*128 + wn + j*8 + 2*(lane & 3);
                    *(uint32_t*)(outp + ((size_t)(t*B_ + b) * C_ + o) * N_ + n) = hpair(s0, s1);
                }
            }
        }
        __syncthreads();   // smem safe for next pass's prologue
    }
}

// ============================================================
// K2b: transpose q spikes [tb][c][n] -> [tb][n][c] fp16.
// ============================================================
__global__ __launch_bounds__(256) void qtrans_kernel() {
    __shared__ __half Sb[64][72];
    int bx = blockIdx.x;
    int ct = bx & 7, ntt = (bx >> 3) & 3, tb = bx >> 5;
    int tid = threadIdx.x;
    int c_l = tid >> 2, ng = tid & 3;
    int n_o = tid >> 2, u0 = tid & 3;

    const __half* src = g_qh + ((size_t)tb * C_ + ct*64 + c_l) * N_ + ntt*64;
    #pragma unroll
    for (int hf = 0; hf < 2; hf++) {
        int cchunk = ng*2 + hf;
        *(uint4*)(&Sb[c_l][cchunk*8]) = *(const uint4*)(src + cchunk*8);
    }
    __syncthreads();
    char* outb = (char*)(g_qT + ((size_t)tb * N_ + ntt*64 + n_o) * C_ + ct*64);
    #pragma unroll
    for (int hf = 0; hf < 2; hf++) {
        int u = u0 + hf * 4;
        uint32_t rp[4];
        #pragma unroll
        for (int p = 0; p < 4; p++) {
            float lo = __half2float(Sb[u*8 + p*2][n_o]);
            float hi = __half2float(Sb[u*8 + p*2 + 1][n_o]);
            rp[p] = hpair(lo, hi);
        }
        *(uint4*)(outb + u*16) = make_uint4(rp[0], rp[1], rp[2], rp[3]);
    }
}

// ============================================================
// K3a: kvT[e][d] = 0.125 * sum_n v[n,e]*k[n,d], fp16 MMA, exact.
// ============================================================
__global__ __launch_bounds__(128) void kvh_kernel() {
    __shared__ __align__(16) __half Ah[64][136];
    __shared__ __align__(16) __half Bh[64][136];
    uint32_t ahb = smem_u32(Ah), bhb = smem_u32(Bh);
    int tbh = blockIdx.x;
    int tb = tbh >> 3, hh = tbh & 7;
    int tid = threadIdx.x, lane = tid & 31, wid = tid >> 5;
    int em = (wid & 1) * 32, dn = (wid >> 1) * 32;

    const __half* vsrc = g_vh + ((size_t)tb * C_ + hh*64) * N_;
    const __half* ksrc = g_kh + ((size_t)tb * C_ + hh*64) * N_;

    float acc[2][4][4];
    #pragma unroll
    for (int i = 0; i < 2; i++)
        #pragma unroll
        for (int j = 0; j < 4; j++)
            #pragma unroll
            for (int p = 0; p < 4; p++) acc[i][j][p] = 0.f;

    int a_row = lane & 15, a_col = (lane >> 4) * 8;
    int b_row0 = dn + (lane & 7) + ((lane >> 4) << 3), b_col = lane & 8;

    for (int ch = 0; ch < 2; ch++) {
        #pragma unroll
        for (int r = 0; r < 4; r++) {
            int idx = tid + r * 128;
            int row = idx >> 3, cchunk = idx & 7;
            CP16(ahb + (uint32_t)((row*136 + cchunk*8) * 2), vsrc + (size_t)row * N_ + ch*128 + cchunk*8);
            CP16(bhb + (uint32_t)((row*136 + cchunk*8) * 2), ksrc + (size_t)row * N_ + ch*128 + cchunk*8);
        }
        CP_COMMIT(); CP_WAIT(0);
        __syncthreads();
        #pragma unroll
        for (int ks = 0; ks < 8; ks++) {
            int kc = ks * 16;
            uint32_t bfr[4][2];
            #pragma unroll
            for (int jp = 0; jp < 2; jp++) {
                uint32_t r4[4];
                ldm_x4(r4, bhb + (uint32_t)(((b_row0 + jp*16)*136 + kc + b_col) * 2));
                bfr[jp*2][0] = r4[0];   bfr[jp*2][1] = r4[1];
                bfr[jp*2+1][0] = r4[2]; bfr[jp*2+1][1] = r4[3];
            }
            #pragma unroll
            for (int i = 0; i < 2; i++) {
                uint32_t a4[4];
                ldm_x4(a4, ahb + (uint32_t)(((em + i*16 + a_row)*136 + kc + a_col) * 2));
                #pragma unroll
                for (int j = 0; j < 4; j++)
                    mma16816(acc[i][j], a4, bfr[j]);
            }
        }
        __syncthreads();
    }

    #pragma unroll
    for (int i = 0; i < 2; i++) {
        #pragma unroll
        for (int j = 0; j < 4; j++) {
            int e0 = em + i*16 + (lane >> 2);
            int d0 = dn + j*8 + 2*(lane & 3);
            *(uint32_t*)(g_kvT + ((size_t)tbh*64 + e0) * 64 + d0) =
                hpair(acc[i][j][0] * 0.125f, acc[i][j][1] * 0.125f);
            *(uint32_t*)(g_kvT + ((size_t)tbh*64 + e0 + 8) * 64 + d0) =
                hpair(acc[i][j][2] * 0.125f, acc[i][j][3] * 0.125f);
        }
    }
}

// ============================================================
// K3b: a[n][e] = qT @ kvT^T (scale folded), LIF(0.5) over t,
// write fp16 spikes g_sT [tb][n][c].
// ============================================================
__global__ __launch_bounds__(256) void attn_mma_kernel() {
    __shared__ __align__(16) __half Aq[128][72];
    __shared__ __align__(16) __half Bkv[64][72];
    uint32_t aqb = smem_u32(Aq), bkb = smem_u32(Bkv);
    int bx = blockIdx.x;
    int nt = bx & 1, hh = (bx >> 1) & 7, b = bx >> 4;
    int tid = threadIdx.x, lane = tid & 31, wid = tid >> 5;
    int nb = (wid & 3) * 32, eb = (wid >> 2) * 32;

    int a_row = lane & 15, a_col = (lane >> 4) * 8;
    int b_row0 = eb + (lane & 7) + ((lane >> 4) << 3), b_col = lane & 8;

    float vm[2][4][4];
    #pragma unroll
    for (int i = 0; i < 2; i++)
        #pragma unroll
        for (int j = 0; j < 4; j++)
            #pragma unroll
            for (int p = 0; p < 4; p++) vm[i][j][p] = 0.f;

    for (int t = 0; t < T_; t++) {
        int tb = t * B_ + b, tbh = tb * 8 + hh;
        #pragma unroll
        for (int r = 0; r < 4; r++) {
            int idx = tid + r * 256;
            int row = idx >> 3, cchunk = idx & 7;
            CP16(aqb + (uint32_t)((row*72 + cchunk*8) * 2),
                 g_qT + ((size_t)tb * N_ + nt*128 + row) * C_ + hh*64 + cchunk*8);
        }
        #pragma unroll
        for (int r = 0; r < 2; r++) {
            int idx = tid + r * 256;
            int row = idx >> 3, cchunk = idx & 7;
            CP16(bkb + (uint32_t)((row*72 + cchunk*8) * 2),
                 g_kvT + ((size_t)tbh*64 + row) * 64 + cchunk*8);
        }
        CP_COMMIT(); CP_WAIT(0);
        __syncthreads();

        float acc[2][4][4];
        #pragma unroll
        for (int i = 0; i < 2; i++)
            #pragma unroll
            for (int j = 0; j < 4; j++)
                #pragma unroll
                for (int p = 0; p < 4; p++) acc[i][j][p] = 0.f;

        #pragma unroll
        for (int ks = 0; ks < 4; ks++) {
            int kc = ks * 16;
            uint32_t bfr[4][2];
            #pragma unroll
            for (int jp = 0; jp < 2; jp++) {
                uint32_t r4[4];
                ldm_x4(r4, bkb + (uint32_t)(((b_row0 + jp*16)*72 + kc + b_col) * 2));
                bfr[jp*2][0] = r4[0];   bfr[jp*2][1] = r4[1];
                bfr[jp*2+1][0] = r4[2]; bfr[jp*2+1][1] = r4[3];
            }
            #pragma unroll
            for (int i = 0; i < 2; i++) {
                uint32_t a4[4];
                ldm_x4(a4, aqb + (uint32_t)(((nb + i*16 + a_row)*72 + kc + a_col) * 2));
                #pragma unroll
                for (int j = 0; j < 4; j++)
                    mma16816(acc[i][j], a4, bfr[j]);
            }
        }

        #pragma unroll
        for (int i = 0; i < 2; i++) {
            #pragma unroll
            for (int j = 0; j < 4; j++) {
                int n0 = nb + i*16 + (lane >> 2);
                int e0 = eb + j*8 + 2*(lane & 3);
                float s0 = lif_step(vm[i][j][0], acc[i][j][0], 0.5f);
                float s1 = lif_step(vm[i][j][1], acc[i][j][1], 0.5f);
                float s2 = lif_step(vm[i][j][2], acc[i][j][2], 0.5f);
                float s3 = lif_step(vm[i][j][3], acc[i][j][3], 0.5f);
                *(uint32_t*)(g_sT + ((size_t)tb * N_ + nt*128 + n0) * C_ + hh*64 + e0) = hpair(s0, s1);
                *(uint32_t*)(g_sT + ((size_t)tb * N_ + nt*128 + n0 + 8) * C_ + hh*64 + e0) = hpair(s2, s3);
            }
        }
        __syncthreads();
    }
}

// ============================================================
// K4: proj GEMM + bias + BN -> d_out.
// ============================================================
__global__ __launch_bounds__(256, 1) void proj_mma_kernel(
    const float* __restrict__ pbias, const float* __restrict__ pg, const float* __restrict__ pb,
    const float* __restrict__ pm, const float* __restrict__ pv, float* __restrict__ out)
{
    extern __shared__ char dynsmem[];
    uint32_t asb = smem_u32(dynsmem), bsb = asb + 3*A_STAGE_BYTES;
    int tid = threadIdx.x, lane = tid & 31, wid = tid >> 5;
    int wm = (wid & 3) * 32, wn = (wid >> 2) * 64;
    int bx = blockIdx.x;
    int nt = bx & 1, mt = (bx >> 1) & 3, tb = bx >> 3;

    float scl[2][2], mean[2][2], beta[2][2], bias[2][2];
    #pragma unroll
    for (int i = 0; i < 2; i++)
        #pragma unroll
        for (int rh = 0; rh < 2; rh++) {
            int o = mt*128 + wm + i*16 + rh*8 + (lane >> 2);
            scl[i][rh]  = pg[o] / sqrtf(pv[o] + 1e-5f);
            mean[i][rh] = pm[o];
            beta[i][rh] = pb[o];
            bias[i][rh] = pbias[o];
        }

    float acc[2][8][4];
    #pragma unroll
    for (int i = 0; i < 2; i++)
        #pragma unroll
        for (int j = 0; j < 8; j++)
            #pragma unroll
            for (int p = 0; p < 4; p++) acc[i][j][p] = 0.f;

    int rowbase = tb * 256 + nt*128;
    gemm_pass(asb, bsb, acc, 3, mt, g_sT, rowbase, tid, wm, wn, lane);

    #pragma unroll
    for (int i = 0; i < 2; i++) {
        #pragma unroll
        for (int j = 0; j < 8; j++) {
            #pragma unroll
            for (int rh = 0; rh < 2; rh++) {
                float y0 = ((acc[i][j][rh*2+0] + bias[i][rh]) - mean[i][rh]) * scl[i][rh] + beta[i][rh];
                float y1 = ((acc[i][j][rh*2+1] + bias[i][rh]) - mean[i][rh]) * scl[i][rh] + beta[i][rh];
                int o = mt*128 + wm + i*16 + rh*8 + (lane >> 2);
                int n = nt*128 + wn + j*8 + 2*(lane & 3);
                *(float2*)(out + ((size_t)tb * C_ + o) * N_ + n) = make_float2(y0, y1);
            }
        }
    }
}

// ============================================================
extern "C" void kernel_launch(void* const* d_in, const int* in_sizes, int n_in,
                              void* d_out, int out_size) {
    (void)in_sizes; (void)n_in; (void)out_size;
    const float* x  = (const float*)d_in[0];
    const float* qw = (const float*)d_in[1];
    const float* qg = (const float*)d_in[2];
    const float* qb = (const float*)d_in[3];
    const float* qm = (const float*)d_in[4];
    const float* qv = (const float*)d_in[5];
    const float* kw = (const float*)d_in[6];
    const float* kg = (const float*)d_in[7];
    const float* kb = (const float*)d_in[8];
    const float* km = (const float*)d_in[9];
    const float* kvv= (const float*)d_in[10];
    const float* vw = (const float*)d_in[11];
    const float* vg = (const float*)d_in[12];
    const float* vb = (const float*)d_in[13];
    const float* vm = (const float*)d_in[14];
    const float* vv = (const float*)d_in[15];
    const float* pw    = (const float*)d_in[16];
    const float* pbias = (const float*)d_in[17];
    const float* pg    = (const float*)d_in[18];
    const float* pb    = (const float*)d_in[19];
    const float* pm    = (const float*)d_in[20];
    const float* pv    = (const float*)d_in[21];

    cudaFuncSetAttribute(qkv_mma_kernel, cudaFuncAttributeMaxDynamicSharedMemorySize, GEMM_SMEM);
    cudaFuncSetAttribute(proj_mma_kernel, cudaFuncAttributeMaxDynamicSharedMemorySize, GEMM_SMEM);

    wsplit_kernel<<<4096, 256>>>(qw, kw, vw, pw);
    lifx_kernel<<<1024, 256>>>(x);
    qkv_mma_kernel<<<dim3(256, 3), 256, GEMM_SMEM>>>(qg, qb, qm, qv, kg, kb, km, kvv, vg, vb, vm, vv);
    qtrans_kernel<<<4096, 256>>>();
    kvh_kernel<<<1024, 128>>>();
    attn_mma_kernel<<<512, 256>>>();
    proj_mma_kernel<<<1024, 256, GEMM_SMEM>>>(pbias, pg, pb, pm, pv, (float*)d_out);
}

// round 9
// speedup vs baseline: 2.6529x; 1.0306x over previous
#include <cuda_runtime.h>
#include <cuda_fp16.h>
#include <cstdint>

#define T_ 4
#define B_ 32
#define C_ 512
#define N_ 256
#define H_ 8
#define D_ 64
#define BCN_ (B_*C_*N_)
#define TBCN_ (T_*BCN_)

// ---- scratch ----
__device__ __half g_kh[TBCN_];         // [tb][c][n] fp16 spikes
__device__ __half g_vh[TBCN_];
__device__ __half g_qT[TBCN_];         // [tb][n][c] fp16 spikes (written directly by qkv)
__device__ __half g_xsT[TBCN_];        // [t][b][n][c] spikes fp16 (K-major)
__device__ __half g_sT[TBCN_];         // [tb][n][c] attn spikes fp16
__device__ __half g_kvT[T_*B_*H_*D_*D_]; // [tbh][e][d], pre-scaled by 0.125
__device__ __half g_wl[4*2*C_*C_];     // [mat][limb][o][c] fp16 weight limbs

// ================= helpers =================
__device__ __forceinline__ uint32_t smem_u32(const void* p) {
    uint32_t a;
    asm("{ .reg .u64 t; cvta.to.shared.u64 t, %1; cvt.u32.u64 %0, t; }" : "=r"(a) : "l"(p));
    return a;
}

#define CP16(dst, src) \
    asm volatile("cp.async.cg.shared.global [%0], [%1], 16;" :: "r"(dst), "l"(src))
#define CP_COMMIT() asm volatile("cp.async.commit_group;" ::: "memory")
#define CP_WAIT(n)  asm volatile("cp.async.wait_group %0;" :: "n"(n) : "memory")

__device__ __forceinline__ void ldm_x4(uint32_t r[4], uint32_t addr) {
    asm volatile("ldmatrix.sync.aligned.m8n8.x4.shared.b16 {%0,%1,%2,%3}, [%4];"
        : "=r"(r[0]), "=r"(r[1]), "=r"(r[2]), "=r"(r[3]) : "r"(addr));
}
__device__ __forceinline__ void mma16816(float c[4], const uint32_t a[4], const uint32_t* b) {
    asm volatile("mma.sync.aligned.m16n8k16.row.col.f32.f16.f16.f32 "
        "{%0,%1,%2,%3}, {%4,%5,%6,%7}, {%8,%9}, {%0,%1,%2,%3};"
        : "+f"(c[0]), "+f"(c[1]), "+f"(c[2]), "+f"(c[3])
        : "r"(a[0]), "r"(a[1]), "r"(a[2]), "r"(a[3]), "r"(b[0]), "r"(b[1]));
}

__device__ __forceinline__ float lif_step(float& v, float x, float vth) {
    v += (x - v) * 0.5f;
    float s = (v >= vth) ? 1.0f : 0.0f;
    if (s != 0.0f) v = 0.0f;
    return s;
}
__device__ __forceinline__ uint32_t hpair(float lo, float hi) {
    return (uint32_t)__half_as_ushort(__float2half_rn(lo)) |
           ((uint32_t)__half_as_ushort(__float2half_rn(hi)) << 16);
}

// ============================================================
// K0: fp32 weights -> 2 fp16 limbs, natural [mat][limb][o][c]
// ============================================================
__global__ void wsplit_kernel(const float* __restrict__ qw, const float* __restrict__ kw,
                              const float* __restrict__ vw, const float* __restrict__ pw) {
    int i = blockIdx.x * 256 + threadIdx.x;
    int mat = i >> 18, idx = i & 262143;
    const float* W = (mat == 0) ? qw : (mat == 1) ? kw : (mat == 2) ? vw : pw;
    float w = W[idx];
    __half h1 = __float2half_rn(w);
    float r1 = w - __half2float(h1);
    __half h2 = __float2half_rn(r1);
    size_t base = (size_t)(mat * 2) * 262144 + idx;
    g_wl[base] = h1;
    g_wl[base + 262144] = h2;
}

// ============================================================
// K1: LIF(x) -> fp16 spikes, transposed [t][b][n][c]
// ============================================================
__global__ __launch_bounds__(256) void lifx_kernel(const float* __restrict__ x) {
    __shared__ __half Sb[64][72];
    int bx = blockIdx.x;
    int ch = bx & 7, nt = (bx >> 3) & 3, b = bx >> 5;
    int tid = threadIdx.x;
    int c_l = tid >> 2, ng = tid & 3;
    int n_o = tid >> 2, u0 = tid & 3;
    float vm[16];
    #pragma unroll
    for (int j = 0; j < 16; j++) vm[j] = 0.f;

    for (int t = 0; t < T_; t++) {
        const float* xp = x + (((size_t)(t * B_ + b)) * C_ + ch * 64 + c_l) * N_ + nt * 64 + ng * 16;
        #pragma unroll
        for (int q = 0; q < 4; q++) {
            float4 xv = *(const float4*)(xp + q * 4);
            Sb[c_l][ng*16 + q*4 + 0] = __float2half_rn(lif_step(vm[q*4+0], xv.x, 1.0f));
            Sb[c_l][ng*16 + q*4 + 1] = __float2half_rn(lif_step(vm[q*4+1], xv.y, 1.0f));
            Sb[c_l][ng*16 + q*4 + 2] = __float2half_rn(lif_step(vm[q*4+2], xv.z, 1.0f));
            Sb[c_l][ng*16 + q*4 + 3] = __float2half_rn(lif_step(vm[q*4+3], xv.w, 1.0f));
        }
        __syncthreads();
        char* outb = (char*)(g_xsT + ((size_t)(t*B_ + b) * N_ + nt*64 + n_o) * C_ + ch*64);
        #pragma unroll
        for (int hf = 0; hf < 2; hf++) {
            int u = u0 + hf * 4;
            uint32_t rp[4];
            #pragma unroll
            for (int p = 0; p < 4; p++) {
                float lo = __half2float(Sb[u*8 + p*2][n_o]);
                float hi = __half2float(Sb[u*8 + p*2 + 1][n_o]);
                rp[p] = hpair(lo, hi);
            }
            *(uint4*)(outb + u*16) = make_uint4(rp[0], rp[1], rp[2], rp[3]);
        }
        __syncthreads();
    }
}

// ============================================================
// GEMM machinery (qkv/proj): 128x128 block, 8 warps, 4-stage
// cp.async pipeline, ONE __syncthreads per k16 chunk.
// Dyn smem: As[4][2][128][24] (49152B) + Bs[4][128][24] (24576B).
// ============================================================
#define A_STAGE_BYTES (2*128*24*2)
#define B_STAGE_BYTES (128*24*2)
#define NSTG 4
#define GEMM_SMEM (NSTG*A_STAGE_BYTES + NSTG*B_STAGE_BYTES)

__device__ __forceinline__ void load_stage_A(uint32_t asb, int s, int kc, int wmat, int mt, int tid) {
    #pragma unroll
    for (int r = 0; r < 2; r++) {
        int idx = tid + r * 256;
        int l = idx >> 8, rem = idx & 255;
        int o = rem >> 1, h = rem & 1;
        const __half* src = g_wl + ((size_t)(wmat*2 + l) * 512 + mt*128 + o) * 512 + kc + h*8;
        uint32_t dst = asb + (uint32_t)((((s*2 + l)*128 + o)*24 + h*8) * 2);
        CP16(dst, src);
    }
}
__device__ __forceinline__ void load_stage_B(uint32_t bsb, int s, int kc,
                                             const __half* srcT, int rowbase, int tid) {
    int n = tid >> 1, h = tid & 1;
    const __half* src = srcT + ((size_t)(rowbase + n)) * 512 + kc + h*8;
    uint32_t dst = bsb + (uint32_t)(((s*128 + n)*24 + h*8) * 2);
    CP16(dst, src);
}

__device__ __forceinline__ void gemm_pass(uint32_t asb, uint32_t bsb, float acc[2][8][4],
                                          int wmat, int mt, const __half* srcT, int rowbase,
                                          int tid, int wm, int wn, int lane) {
    #pragma unroll
    for (int p = 0; p < 3; p++) {
        load_stage_A(asb, p, p*16, wmat, mt, tid);
        load_stage_B(bsb, p, p*16, srcT, rowbase, tid);
        CP_COMMIT();
    }

    int a_row = lane & 15, a_col = (lane >> 4) * 8;
    int b_row = wn + (lane & 7) + ((lane >> 4) << 3), b_col = lane & 8;

    int s = 0;
    for (int c = 0; c < 32; c++) {
        CP_WAIT(2);              // stage c arrived (c+1,c+2 may be in flight)
        __syncthreads();         // all warps done with the stage about to be overwritten
        if (c + 3 < 32) {
            int ns = s + 3; if (ns >= NSTG) ns -= NSTG;
            load_stage_A(asb, ns, (c+3)*16, wmat, mt, tid);
            load_stage_B(bsb, ns, (c+3)*16, srcT, rowbase, tid);
        }
        CP_COMMIT();             // empty group in tail keeps numbering

        uint32_t bfr[8][2];
        #pragma unroll
        for (int jp = 0; jp < 4; jp++) {
            uint32_t r4[4];
            uint32_t addr = bsb + (uint32_t)((((s*128) + b_row + jp*16)*24 + b_col) * 2);
            ldm_x4(r4, addr);
            bfr[jp*2][0] = r4[0];   bfr[jp*2][1] = r4[1];
            bfr[jp*2+1][0] = r4[2]; bfr[jp*2+1][1] = r4[3];
        }
        #pragma unroll
        for (int l = 0; l < 2; l++) {
            #pragma unroll
            for (int i = 0; i < 2; i++) {
                uint32_t a4[4];
                uint32_t addr = asb + (uint32_t)(((((s*2 + l)*128) + wm + i*16 + a_row)*24 + a_col) * 2);
                ldm_x4(a4, addr);
                #pragma unroll
                for (int j = 0; j < 8; j++)
                    mma16816(acc[i][j], a4, bfr[j]);
            }
        }
        if (++s >= NSTG) s = 0;
    }
}

// ============================================================
// K2: qkv GEMM + BN + LIF.  q-branch writes g_qT [n][c] directly
// (smem-staged transpose); k/v write [c][n].
// grid.x = nt2*mt4*b32 = 256, grid.y = br3.
// ============================================================
__global__ __launch_bounds__(256, 1) void qkv_mma_kernel(
    const float* __restrict__ qg, const float* __restrict__ qb, const float* __restrict__ qm, const float* __restrict__ qv,
    const float* __restrict__ kg, const float* __restrict__ kb, const float* __restrict__ km, const float* __restrict__ kvv,
    const float* __restrict__ vg, const float* __restrict__ vb, const float* __restrict__ vmn, const float* __restrict__ vvv)
{
    extern __shared__ char dynsmem[];
    uint32_t asb = smem_u32(dynsmem), bsb = asb + NSTG*A_STAGE_BYTES;
    int tid = threadIdx.x, lane = tid & 31, wid = tid >> 5;
    int wm = (wid & 3) * 32, wn = (wid >> 2) * 64;
    int bx = blockIdx.x, br = blockIdx.y;
    int nt = bx & 1, mt = (bx >> 1) & 3, b = bx >> 3;

    const float* G  = (br == 0) ? qg : (br == 1) ? kg : vg;
    const float* Bt = (br == 0) ? qb : (br == 1) ? kb : vb;
    const float* M  = (br == 0) ? qm : (br == 1) ? km : vmn;
    const float* V  = (br == 0) ? qv : (br == 1) ? kvv : vvv;
    __half* outp = (br == 1) ? g_kh : g_vh;

    float scl[2][2], mean[2][2], beta[2][2];
    #pragma unroll
    for (int i = 0; i < 2; i++)
        #pragma unroll
        for (int rh = 0; rh < 2; rh++) {
            int o = mt*128 + wm + i*16 + rh*8 + (lane >> 2);
            scl[i][rh]  = G[o] / sqrtf(V[o] + 1e-5f);
            mean[i][rh] = M[o];
            beta[i][rh] = Bt[o];
        }

    float vm[2][2][8][2];
    #pragma unroll
    for (int i = 0; i < 2; i++)
        #pragma unroll
        for (int rh = 0; rh < 2; rh++)
            #pragma unroll
            for (int j = 0; j < 8; j++) { vm[i][rh][j][0] = 0.f; vm[i][rh][j][1] = 0.f; }

    for (int t = 0; t < T_; t++) {
        float acc[2][8][4];
        #pragma unroll
        for (int i = 0; i < 2; i++)
            #pragma unroll
            for (int j = 0; j < 8; j++)
                #pragma unroll
                for (int p = 0; p < 4; p++) acc[i][j][p] = 0.f;

        int rowbase = (t*B_ + b) * 256 + nt*128;
        gemm_pass(asb, bsb, acc, br, mt, g_xsT, rowbase, tid, wm, wn, lane);

        if (br == 0) {
            // stage spike tile [n_l][o_l] in smem, then write g_qT coalesced
            __syncthreads();   // gemm compute done in all warps; smem reusable
            __half* Sq = (__half*)dynsmem;
            #pragma unroll
            for (int i = 0; i < 2; i++) {
                #pragma unroll
                for (int j = 0; j < 8; j++) {
                    #pragma unroll
                    for (int rh = 0; rh < 2; rh++) {
                        float y0 = (acc[i][j][rh*2+0] - mean[i][rh]) * scl[i][rh] + beta[i][rh];
                        float y1 = (acc[i][j][rh*2+1] - mean[i][rh]) * scl[i][rh] + beta[i][rh];
                        float s0 = lif_step(vm[i][rh][j][0], y0, 1.0f);
                        float s1 = lif_step(vm[i][rh][j][1], y1, 1.0f);
                        int o_l = wm + i*16 + rh*8 + (lane >> 2);
                        int n_l = wn + j*8 + 2*(lane & 3);
                        Sq[n_l*136 + o_l]       = __float2half_rn(s0);
                        Sq[(n_l+1)*136 + o_l]   = __float2half_rn(s1);
                    }
                }
            }
            __syncthreads();
            #pragma unroll
            for (int r = 0; r < 8; r++) {
                int idx = tid + r * 256;           // 2048 uint4: 128 rows x 16 chunks
                int row = idx >> 4, chk = idx & 15;
                *(uint4*)(g_qT + ((size_t)(t*B_ + b) * N_ + nt*128 + row) * C_ + mt*128 + chk*8) =
                    *(const uint4*)(&Sq[row*136 + chk*8]);
            }
            __syncthreads();
        } else {
            #pragma unroll
            for (int i = 0; i < 2; i++) {
                #pragma unroll
                for (int j = 0; j < 8; j++) {
                    #pragma unroll
                    for (int rh = 0; rh < 2; rh++) {
                        float y0 = (acc[i][j][rh*2+0] - mean[i][rh]) * scl[i][rh] + beta[i][rh];
                        float y1 = (acc[i][j][rh*2+1] - mean[i][rh]) * scl[i][rh] + beta[i][rh];
                        float s0 = lif_step(vm[i][rh][j][0], y0, 1.0f);
                        float s1 = lif_step(vm[i][rh][j][1], y1, 1.0f);
                        int o = mt*128 + wm + i*16 + rh*8 + (lane >> 2);
                        int n = nt*128 + wn + j*8 + 2*(lane & 3);
                        *(uint32_t*)(outp + ((size_t)(t*B_ + b) * C_ + o) * N_ + n) = hpair(s0, s1);
                    }
                }
            }
            __syncthreads();
        }
    }
}

// ============================================================
// K3a: kvT[e][d] = 0.125 * sum_n v[n,e]*k[n,d], fp16 MMA, exact.
// ============================================================
__global__ __launch_bounds__(128) void kvh_kernel() {
    __shared__ __align__(16) __half Ah[64][136];
    __shared__ __align__(16) __half Bh[64][136];
    uint32_t ahb = smem_u32(Ah), bhb = smem_u32(Bh);
    int tbh = blockIdx.x;
    int tb = tbh >> 3, hh = tbh & 7;
    int tid = threadIdx.x, lane = tid & 31, wid = tid >> 5;
    int em = (wid & 1) * 32, dn = (wid >> 1) * 32;

    const __half* vsrc = g_vh + ((size_t)tb * C_ + hh*64) * N_;
    const __half* ksrc = g_kh + ((size_t)tb * C_ + hh*64) * N_;

    float acc[2][4][4];
    #pragma unroll
    for (int i = 0; i < 2; i++)
        #pragma unroll
        for (int j = 0; j < 4; j++)
            #pragma unroll
            for (int p = 0; p < 4; p++) acc[i][j][p] = 0.f;

    int a_row = lane & 15, a_col = (lane >> 4) * 8;
    int b_row0 = dn + (lane & 7) + ((lane >> 4) << 3), b_col = lane & 8;

    for (int ch = 0; ch < 2; ch++) {
        #pragma unroll
        for (int r = 0; r < 4; r++) {
            int idx = tid + r * 128;
            int row = idx >> 3, cchunk = idx & 7;
            CP16(ahb + (uint32_t)((row*136 + cchunk*8) * 2), vsrc + (size_t)row * N_ + ch*128 + cchunk*8);
            CP16(bhb + (uint32_t)((row*136 + cchunk*8) * 2), ksrc + (size_t)row * N_ + ch*128 + cchunk*8);
        }
        CP_COMMIT(); CP_WAIT(0);
        __syncthreads();
        #pragma unroll
        for (int ks = 0; ks < 8; ks++) {
            int kc = ks * 16;
            uint32_t bfr[4][2];
            #pragma unroll
            for (int jp = 0; jp < 2; jp++) {
                uint32_t r4[4];
                ldm_x4(r4, bhb + (uint32_t)(((b_row0 + jp*16)*136 + kc + b_col) * 2));
                bfr[jp*2][0] = r4[0];   bfr[jp*2][1] = r4[1];
                bfr[jp*2+1][0] = r4[2]; bfr[jp*2+1][1] = r4[3];
            }
            #pragma unroll
            for (int i = 0; i < 2; i++) {
                uint32_t a4[4];
                ldm_x4(a4, ahb + (uint32_t)(((em + i*16 + a_row)*136 + kc + a_col) * 2));
                #pragma unroll
                for (int j = 0; j < 4; j++)
                    mma16816(acc[i][j], a4, bfr[j]);
            }
        }
        __syncthreads();
    }

    #pragma unroll
    for (int i = 0; i < 2; i++) {
        #pragma unroll
        for (int j = 0; j < 4; j++) {
            int e0 = em + i*16 + (lane >> 2);
            int d0 = dn + j*8 + 2*(lane & 3);
            *(uint32_t*)(g_kvT + ((size_t)tbh*64 + e0) * 64 + d0) =
                hpair(acc[i][j][0] * 0.125f, acc[i][j][1] * 0.125f);
            *(uint32_t*)(g_kvT + ((size_t)tbh*64 + e0 + 8) * 64 + d0) =
                hpair(acc[i][j][2] * 0.125f, acc[i][j][3] * 0.125f);
        }
    }
}

// ============================================================
// K3b: a[n][e] = qT @ kvT^T (scale folded), LIF(0.5) over t,
// double-buffered across t; writes fp16 spikes g_sT [tb][n][c].
// Dyn smem: 2 stages x (Aq 128x72 + Bkv 64x72) halves = 55296B.
// ============================================================
#define ATTN_AQ_BYTES (128*72*2)
#define ATTN_BK_BYTES (64*72*2)
#define ATTN_STAGE (ATTN_AQ_BYTES + ATTN_BK_BYTES)
#define ATTN_SMEM (2*ATTN_STAGE)

__device__ __forceinline__ void attn_load_t(uint32_t base, int t, int b, int nt, int hh, int tid) {
    uint32_t aqb = base, bkb = base + ATTN_AQ_BYTES;
    int tb = t * B_ + b, tbh = tb * 8 + hh;
    #pragma unroll
    for (int r = 0; r < 4; r++) {
        int idx = tid + r * 256;
        int row = idx >> 3, cchunk = idx & 7;
        CP16(aqb + (uint32_t)((row*72 + cchunk*8) * 2),
             g_qT + ((size_t)tb * N_ + nt*128 + row) * C_ + hh*64 + cchunk*8);
    }
    #pragma unroll
    for (int r = 0; r < 2; r++) {
        int idx = tid + r * 256;
        int row = idx >> 3, cchunk = idx & 7;
        CP16(bkb + (uint32_t)((row*72 + cchunk*8) * 2),
             g_kvT + ((size_t)tbh*64 + row) * 64 + cchunk*8);
    }
}

__global__ __launch_bounds__(256) void attn_mma_kernel() {
    extern __shared__ char dynattn[];
    uint32_t sb = smem_u32(dynattn);
    int bx = blockIdx.x;
    int nt = bx & 1, hh = (bx >> 1) & 7, b = bx >> 4;
    int tid = threadIdx.x, lane = tid & 31, wid = tid >> 5;
    int nb = (wid & 3) * 32, eb = (wid >> 2) * 32;

    int a_row = lane & 15, a_col = (lane >> 4) * 8;
    int b_row0 = eb + (lane & 7) + ((lane >> 4) << 3), b_col = lane & 8;

    float vm[2][4][4];
    #pragma unroll
    for (int i = 0; i < 2; i++)
        #pragma unroll
        for (int j = 0; j < 4; j++)
            #pragma unroll
            for (int p = 0; p < 4; p++) vm[i][j][p] = 0.f;

    attn_load_t(sb, 0, b, nt, hh, tid);
    CP_COMMIT();

    for (int t = 0; t < T_; t++) {
        if (t < 3) {
            attn_load_t(sb + ((t+1) & 1) * ATTN_STAGE, t+1, b, nt, hh, tid);
            CP_COMMIT();
            CP_WAIT(1);
        } else {
            CP_WAIT(0);
        }
        __syncthreads();
        uint32_t aqb = sb + (t & 1) * ATTN_STAGE, bkb = aqb + ATTN_AQ_BYTES;
        int tb = t * B_ + b;

        float acc[2][4][4];
        #pragma unroll
        for (int i = 0; i < 2; i++)
            #pragma unroll
            for (int j = 0; j < 4; j++)
                #pragma unroll
                for (int p = 0; p < 4; p++) acc[i][j][p] = 0.f;

        #pragma unroll
        for (int ks = 0; ks < 4; ks++) {
            int kc = ks * 16;
            uint32_t bfr[4][2];
            #pragma unroll
            for (int jp = 0; jp < 2; jp++) {
                uint32_t r4[4];
                ldm_x4(r4, bkb + (uint32_t)(((b_row0 + jp*16)*72 + kc + b_col) * 2));
                bfr[jp*2][0] = r4[0];   bfr[jp*2][1] = r4[1];
                bfr[jp*2+1][0] = r4[2]; bfr[jp*2+1][1] = r4[3];
            }
            #pragma unroll
            for (int i = 0; i < 2; i++) {
                uint32_t a4[4];
                ldm_x4(a4, aqb + (uint32_t)(((nb + i*16 + a_row)*72 + kc + a_col) * 2));
                #pragma unroll
                for (int j = 0; j < 4; j++)
                    mma16816(acc[i][j], a4, bfr[j]);
            }
        }

        #pragma unroll
        for (int i = 0; i < 2; i++) {
            #pragma unroll
            for (int j = 0; j < 4; j++) {
                int n0 = nb + i*16 + (lane >> 2);
                int e0 = eb + j*8 + 2*(lane & 3);
                float s0 = lif_step(vm[i][j][0], acc[i][j][0], 0.5f);
                float s1 = lif_step(vm[i][j][1], acc[i][j][1], 0.5f);
                float s2 = lif_step(vm[i][j][2], acc[i][j][2], 0.5f);
                float s3 = lif_step(vm[i][j][3], acc[i][j][3], 0.5f);
                *(uint32_t*)(g_sT + ((size_t)tb * N_ + nt*128 + n0) * C_ + hh*64 + e0) = hpair(s0, s1);
                *(uint32_t*)(g_sT + ((size_t)tb * N_ + nt*128 + n0 + 8) * C_ + hh*64 + e0) = hpair(s2, s3);
            }
        }
        __syncthreads();
    }
}

// ============================================================
// K4: proj GEMM + bias + BN -> d_out.
// ============================================================
__global__ __launch_bounds__(256, 1) void proj_mma_kernel(
    const float* __restrict__ pbias, const float* __restrict__ pg, const float* __restrict__ pb,
    const float* __restrict__ pm, const float* __restrict__ pv, float* __restrict__ out)
{
    extern __shared__ char dynsmem[];
    uint32_t asb = smem_u32(dynsmem), bsb = asb + NSTG*A_STAGE_BYTES;
    int tid = threadIdx.x, lane = tid & 31, wid = tid >> 5;
    int wm = (wid & 3) * 32, wn = (wid >> 2) * 64;
    int bx = blockIdx.x;
    int nt = bx & 1, mt = (bx >> 1) & 3, tb = bx >> 3;

    float scl[2][2], mean[2][2], beta[2][2], bias[2][2];
    #pragma unroll
    for (int i = 0; i < 2; i++)
        #pragma unroll
        for (int rh = 0; rh < 2; rh++) {
            int o = mt*128 + wm + i*16 + rh*8 + (lane >> 2);
            scl[i][rh]  = pg[o] / sqrtf(pv[o] + 1e-5f);
            mean[i][rh] = pm[o];
            beta[i][rh] = pb[o];
            bias[i][rh] = pbias[o];
        }

    float acc[2][8][4];
    #pragma unroll
    for (int i = 0; i < 2; i++)
        #pragma unroll
        for (int j = 0; j < 8; j++)
            #pragma unroll
            for (int p = 0; p < 4; p++) acc[i][j][p] = 0.f;

    int rowbase = tb * 256 + nt*128;
    gemm_pass(asb, bsb, acc, 3, mt, g_sT, rowbase, tid, wm, wn, lane);

    #pragma unroll
    for (int i = 0; i < 2; i++) {
        #pragma unroll
        for (int j = 0; j < 8; j++) {
            #pragma unroll
            for (int rh = 0; rh < 2; rh++) {
                float y0 = ((acc[i][j][rh*2+0] + bias[i][rh]) - mean[i][rh]) * scl[i][rh] + beta[i][rh];
                float y1 = ((acc[i][j][rh*2+1] + bias[i][rh]) - mean[i][rh]) * scl[i][rh] + beta[i][rh];
                int o = mt*128 + wm + i*16 + rh*8 + (lane >> 2);
                int n = nt*128 + wn + j*8 + 2*(lane & 3);
                *(float2*)(out + ((size_t)tb * C_ + o) * N_ + n) = make_float2(y0, y1);
            }
        }
    }
}

// ============================================================
extern "C" void kernel_launch(void* const* d_in, const int* in_sizes, int n_in,
                              void* d_out, int out_size) {
    (void)in_sizes; (void)n_in; (void)out_size;
    const float* x  = (const float*)d_in[0];
    const float* qw = (const float*)d_in[1];
    const float* qg = (const float*)d_in[2];
    const float* qb = (const float*)d_in[3];
    const float* qm = (const float*)d_in[4];
    const float* qv = (const float*)d_in[5];
    const float* kw = (const float*)d_in[6];
    const float* kg = (const float*)d_in[7];
    const float* kb = (const float*)d_in[8];
    const float* km = (const float*)d_in[9];
    const float* kvv= (const float*)d_in[10];
    const float* vw = (const float*)d_in[11];
    const float* vg = (const float*)d_in[12];
    const float* vb = (const float*)d_in[13];
    const float* vm = (const float*)d_in[14];
    const float* vv = (const float*)d_in[15];
    const float* pw    = (const float*)d_in[16];
    const float* pbias = (const float*)d_in[17];
    const float* pg    = (const float*)d_in[18];
    const float* pb    = (const float*)d_in[19];
    const float* pm    = (const float*)d_in[20];
    const float* pv    = (const float*)d_in[21];

    cudaFuncSetAttribute(qkv_mma_kernel, cudaFuncAttributeMaxDynamicSharedMemorySize, GEMM_SMEM);
    cudaFuncSetAttribute(proj_mma_kernel, cudaFuncAttributeMaxDynamicSharedMemorySize, GEMM_SMEM);
    cudaFuncSetAttribute(attn_mma_kernel, cudaFuncAttributeMaxDynamicSharedMemorySize, ATTN_SMEM);

    wsplit_kernel<<<4096, 256>>>(qw, kw, vw, pw);
    lifx_kernel<<<1024, 256>>>(x);
    qkv_mma_kernel<<<dim3(256, 3), 256, GEMM_SMEM>>>(qg, qb, qm, qv, kg, kb, km, kvv, vg, vb, vm, vv);
    kvh_kernel<<<1024, 128>>>();
    attn_mma_kernel<<<512, 256, ATTN_SMEM>>>();
    proj_mma_kernel<<<1024, 256, GEMM_SMEM>>>(pbias, pg, pb, pm, pv, (float*)d_out);
}

// round 10
// speedup vs baseline: 2.7180x; 1.0245x over previous
#include <cuda_runtime.h>
#include <cuda_fp16.h>
#include <cstdint>

#define T_ 4
#define B_ 32
#define C_ 512
#define N_ 256
#define H_ 8
#define D_ 64
#define BCN_ (B_*C_*N_)
#define TBCN_ (T_*BCN_)

// ---- scratch ----
__device__ __half g_kh[TBCN_];         // [tb][c][n] fp16 spikes
__device__ __half g_vh[TBCN_];
__device__ __half g_qT[TBCN_];         // [tb][n][c] fp16 spikes (written directly by qkv)
__device__ __half g_xsT[TBCN_];        // [t][b][n][c] spikes fp16 (K-major)
__device__ __half g_sT[TBCN_];         // [tb][n][c] attn spikes fp16
__device__ __half g_kvT[T_*B_*H_*D_*D_]; // [tbh][e][d], pre-scaled by 0.125
__device__ __half g_wl[4*2*C_*C_];     // [mat][limb][o][c] fp16 weight limbs

// ================= helpers =================
__device__ __forceinline__ uint32_t smem_u32(const void* p) {
    uint32_t a;
    asm("{ .reg .u64 t; cvta.to.shared.u64 t, %1; cvt.u32.u64 %0, t; }" : "=r"(a) : "l"(p));
    return a;
}

#define CP16(dst, src) \
    asm volatile("cp.async.cg.shared.global [%0], [%1], 16;" :: "r"(dst), "l"(src))
#define CP_COMMIT() asm volatile("cp.async.commit_group;" ::: "memory")
#define CP_WAIT(n)  asm volatile("cp.async.wait_group %0;" :: "n"(n) : "memory")

__device__ __forceinline__ void ldm_x4(uint32_t r[4], uint32_t addr) {
    asm volatile("ldmatrix.sync.aligned.m8n8.x4.shared.b16 {%0,%1,%2,%3}, [%4];"
        : "=r"(r[0]), "=r"(r[1]), "=r"(r[2]), "=r"(r[3]) : "r"(addr));
}
__device__ __forceinline__ void mma16816(float c[4], const uint32_t a[4], const uint32_t* b) {
    asm volatile("mma.sync.aligned.m16n8k16.row.col.f32.f16.f16.f32 "
        "{%0,%1,%2,%3}, {%4,%5,%6,%7}, {%8,%9}, {%0,%1,%2,%3};"
        : "+f"(c[0]), "+f"(c[1]), "+f"(c[2]), "+f"(c[3])
        : "r"(a[0]), "r"(a[1]), "r"(a[2]), "r"(a[3]), "r"(b[0]), "r"(b[1]));
}

__device__ __forceinline__ float lif_step(float& v, float x, float vth) {
    v += (x - v) * 0.5f;
    float s = (v >= vth) ? 1.0f : 0.0f;
    if (s != 0.0f) v = 0.0f;
    return s;
}
__device__ __forceinline__ uint32_t hpair(float lo, float hi) {
    return (uint32_t)__half_as_ushort(__float2half_rn(lo)) |
           ((uint32_t)__half_as_ushort(__float2half_rn(hi)) << 16);
}

// ============================================================
// K0: fp32 weights -> 2 fp16 limbs, natural [mat][limb][o][c]
// ============================================================
__global__ void wsplit_kernel(const float* __restrict__ qw, const float* __restrict__ kw,
                              const float* __restrict__ vw, const float* __restrict__ pw) {
    int i = blockIdx.x * 256 + threadIdx.x;
    int mat = i >> 18, idx = i & 262143;
    const float* W = (mat == 0) ? qw : (mat == 1) ? kw : (mat == 2) ? vw : pw;
    float w = W[idx];
    __half h1 = __float2half_rn(w);
    float r1 = w - __half2float(h1);
    __half h2 = __float2half_rn(r1);
    size_t base = (size_t)(mat * 2) * 262144 + idx;
    g_wl[base] = h1;
    g_wl[base + 262144] = h2;
}

// ============================================================
// K1: LIF(x) -> fp16 spikes, transposed [t][b][n][c]
// ============================================================
__global__ __launch_bounds__(256) void lifx_kernel(const float* __restrict__ x) {
    __shared__ __half Sb[64][72];
    int bx = blockIdx.x;
    int ch = bx & 7, nt = (bx >> 3) & 3, b = bx >> 5;
    int tid = threadIdx.x;
    int c_l = tid >> 2, ng = tid & 3;
    int n_o = tid >> 2, u0 = tid & 3;
    float vm[16];
    #pragma unroll
    for (int j = 0; j < 16; j++) vm[j] = 0.f;

    for (int t = 0; t < T_; t++) {
        const float* xp = x + (((size_t)(t * B_ + b)) * C_ + ch * 64 + c_l) * N_ + nt * 64 + ng * 16;
        #pragma unroll
        for (int q = 0; q < 4; q++) {
            float4 xv = *(const float4*)(xp + q * 4);
            Sb[c_l][ng*16 + q*4 + 0] = __float2half_rn(lif_step(vm[q*4+0], xv.x, 1.0f));
            Sb[c_l][ng*16 + q*4 + 1] = __float2half_rn(lif_step(vm[q*4+1], xv.y, 1.0f));
            Sb[c_l][ng*16 + q*4 + 2] = __float2half_rn(lif_step(vm[q*4+2], xv.z, 1.0f));
            Sb[c_l][ng*16 + q*4 + 3] = __float2half_rn(lif_step(vm[q*4+3], xv.w, 1.0f));
        }
        __syncthreads();
        char* outb = (char*)(g_xsT + ((size_t)(t*B_ + b) * N_ + nt*64 + n_o) * C_ + ch*64);
        #pragma unroll
        for (int hf = 0; hf < 2; hf++) {
            int u = u0 + hf * 4;
            uint32_t rp[4];
            #pragma unroll
            for (int p = 0; p < 4; p++) {
                float lo = __half2float(Sb[u*8 + p*2][n_o]);
                float hi = __half2float(Sb[u*8 + p*2 + 1][n_o]);
                rp[p] = hpair(lo, hi);
            }
            *(uint4*)(outb + u*16) = make_uint4(rp[0], rp[1], rp[2], rp[3]);
        }
        __syncthreads();
    }
}

// ============================================================
// M128 GEMM machinery (proj): 128x128 block, 8 warps, 4-stage.
// ============================================================
#define A_STAGE_BYTES (2*128*24*2)
#define B_STAGE_BYTES (128*24*2)
#define NSTG 4
#define GEMM_SMEM (NSTG*A_STAGE_BYTES + NSTG*B_STAGE_BYTES)

__device__ __forceinline__ void load_stage_A(uint32_t asb, int s, int kc, int wmat, int mt, int tid) {
    #pragma unroll
    for (int r = 0; r < 2; r++) {
        int idx = tid + r * 256;
        int l = idx >> 8, rem = idx & 255;
        int o = rem >> 1, h = rem & 1;
        const __half* src = g_wl + ((size_t)(wmat*2 + l) * 512 + mt*128 + o) * 512 + kc + h*8;
        uint32_t dst = asb + (uint32_t)((((s*2 + l)*128 + o)*24 + h*8) * 2);
        CP16(dst, src);
    }
}
__device__ __forceinline__ void load_stage_B(uint32_t bsb, int s, int kc,
                                             const __half* srcT, int rowbase, int tid) {
    int n = tid >> 1, h = tid & 1;
    const __half* src = srcT + ((size_t)(rowbase + n)) * 512 + kc + h*8;
    uint32_t dst = bsb + (uint32_t)(((s*128 + n)*24 + h*8) * 2);
    CP16(dst, src);
}

__device__ __forceinline__ void gemm_pass(uint32_t asb, uint32_t bsb, float acc[2][8][4],
                                          int wmat, int mt, const __half* srcT, int rowbase,
                                          int tid, int wm, int wn, int lane) {
    #pragma unroll
    for (int p = 0; p < 3; p++) {
        load_stage_A(asb, p, p*16, wmat, mt, tid);
        load_stage_B(bsb, p, p*16, srcT, rowbase, tid);
        CP_COMMIT();
    }

    int a_row = lane & 15, a_col = (lane >> 4) * 8;
    int b_row = wn + (lane & 7) + ((lane >> 4) << 3), b_col = lane & 8;

    int s = 0;
    for (int c = 0; c < 32; c++) {
        CP_WAIT(2);
        __syncthreads();
        if (c + 3 < 32) {
            int ns = s + 3; if (ns >= NSTG) ns -= NSTG;
            load_stage_A(asb, ns, (c+3)*16, wmat, mt, tid);
            load_stage_B(bsb, ns, (c+3)*16, srcT, rowbase, tid);
        }
        CP_COMMIT();

        uint32_t bfr[8][2];
        #pragma unroll
        for (int jp = 0; jp < 4; jp++) {
            uint32_t r4[4];
            uint32_t addr = bsb + (uint32_t)((((s*128) + b_row + jp*16)*24 + b_col) * 2);
            ldm_x4(r4, addr);
            bfr[jp*2][0] = r4[0];   bfr[jp*2][1] = r4[1];
            bfr[jp*2+1][0] = r4[2]; bfr[jp*2+1][1] = r4[3];
        }
        #pragma unroll
        for (int l = 0; l < 2; l++) {
            #pragma unroll
            for (int i = 0; i < 2; i++) {
                uint32_t a4[4];
                uint32_t addr = asb + (uint32_t)(((((s*2 + l)*128) + wm + i*16 + a_row)*24 + a_col) * 2);
                ldm_x4(a4, addr);
                #pragma unroll
                for (int j = 0; j < 8; j++)
                    mma16816(acc[i][j], a4, bfr[j]);
            }
        }
        if (++s >= NSTG) s = 0;
    }
}

// ============================================================
// M64 GEMM machinery (qkv): 64x128 block, 8 warps (2m x 4n),
// warp 32x32, 4-stage pipeline.  Smem: A 4x6144 + B 4x6144 = 48KB.
// ============================================================
#define A64_STAGE_BYTES (2*64*24*2)
#define GEMM64_SMEM (NSTG*A64_STAGE_BYTES + NSTG*B_STAGE_BYTES)

__device__ __forceinline__ void load_stage_A64(uint32_t asb, int s, int kc, int wmat, int mt, int tid) {
    int l = tid >> 7, rem = tid & 127;
    int o = rem >> 1, h = rem & 1;
    const __half* src = g_wl + ((size_t)(wmat*2 + l) * 512 + mt*64 + o) * 512 + kc + h*8;
    uint32_t dst = asb + (uint32_t)((((s*2 + l)*64 + o)*24 + h*8) * 2);
    CP16(dst, src);
}

__device__ __forceinline__ void gemm_pass64(uint32_t asb, uint32_t bsb, float acc[2][4][4],
                                            int wmat, int mt, const __half* srcT, int rowbase,
                                            int tid, int wm, int wn, int lane) {
    #pragma unroll
    for (int p = 0; p < 3; p++) {
        load_stage_A64(asb, p, p*16, wmat, mt, tid);
        load_stage_B(bsb, p, p*16, srcT, rowbase, tid);
        CP_COMMIT();
    }

    int a_row = lane & 15, a_col = (lane >> 4) * 8;
    int b_row = wn + (lane & 7) + ((lane >> 4) << 3), b_col = lane & 8;

    int s = 0;
    for (int c = 0; c < 32; c++) {
        CP_WAIT(2);
        __syncthreads();
        if (c + 3 < 32) {
            int ns = s + 3; if (ns >= NSTG) ns -= NSTG;
            load_stage_A64(asb, ns, (c+3)*16, wmat, mt, tid);
            load_stage_B(bsb, ns, (c+3)*16, srcT, rowbase, tid);
        }
        CP_COMMIT();

        uint32_t bfr[4][2];
        #pragma unroll
        for (int jp = 0; jp < 2; jp++) {
            uint32_t r4[4];
            uint32_t addr = bsb + (uint32_t)((((s*128) + b_row + jp*16)*24 + b_col) * 2);
            ldm_x4(r4, addr);
            bfr[jp*2][0] = r4[0];   bfr[jp*2][1] = r4[1];
            bfr[jp*2+1][0] = r4[2]; bfr[jp*2+1][1] = r4[3];
        }
        #pragma unroll
        for (int l = 0; l < 2; l++) {
            #pragma unroll
            for (int i = 0; i < 2; i++) {
                uint32_t a4[4];
                uint32_t addr = asb + (uint32_t)(((((s*2 + l)*64) + wm + i*16 + a_row)*24 + a_col) * 2);
                ldm_x4(a4, addr);
                #pragma unroll
                for (int j = 0; j < 4; j++)
                    mma16816(acc[i][j], a4, bfr[j]);
            }
        }
        if (++s >= NSTG) s = 0;
    }
}

// ============================================================
// K2: qkv GEMM (M64 tiles) + BN + LIF.  q writes g_qT [n][c]
// via smem transpose; k/v write [c][n].
// grid.x = nt2*mt8*b32 = 512, grid.y = br3 -> 1536 blocks.
// ============================================================
__global__ __launch_bounds__(256, 2) void qkv_mma_kernel(
    const float* __restrict__ qg, const float* __restrict__ qb, const float* __restrict__ qm, const float* __restrict__ qv,
    const float* __restrict__ kg, const float* __restrict__ kb, const float* __restrict__ km, const float* __restrict__ kvv,
    const float* __restrict__ vg, const float* __restrict__ vb, const float* __restrict__ vmn, const float* __restrict__ vvv)
{
    extern __shared__ char dynsmem[];
    uint32_t asb = smem_u32(dynsmem), bsb = asb + NSTG*A64_STAGE_BYTES;
    int tid = threadIdx.x, lane = tid & 31, wid = tid >> 5;
    int wm = (wid & 1) * 32, wn = (wid >> 1) * 32;
    int bx = blockIdx.x, br = blockIdx.y;
    int nt = bx & 1, mt = (bx >> 1) & 7, b = bx >> 4;

    const float* G  = (br == 0) ? qg : (br == 1) ? kg : vg;
    const float* Bt = (br == 0) ? qb : (br == 1) ? kb : vb;
    const float* M  = (br == 0) ? qm : (br == 1) ? km : vmn;
    const float* V  = (br == 0) ? qv : (br == 1) ? kvv : vvv;
    __half* outp = (br == 1) ? g_kh : g_vh;

    float scl[2][2], mean[2][2], beta[2][2];
    #pragma unroll
    for (int i = 0; i < 2; i++)
        #pragma unroll
        for (int rh = 0; rh < 2; rh++) {
            int o = mt*64 + wm + i*16 + rh*8 + (lane >> 2);
            scl[i][rh]  = G[o] / sqrtf(V[o] + 1e-5f);
            mean[i][rh] = M[o];
            beta[i][rh] = Bt[o];
        }

    float vm[2][2][4][2];
    #pragma unroll
    for (int i = 0; i < 2; i++)
        #pragma unroll
        for (int rh = 0; rh < 2; rh++)
            #pragma unroll
            for (int j = 0; j < 4; j++) { vm[i][rh][j][0] = 0.f; vm[i][rh][j][1] = 0.f; }

    for (int t = 0; t < T_; t++) {
        float acc[2][4][4];
        #pragma unroll
        for (int i = 0; i < 2; i++)
            #pragma unroll
            for (int j = 0; j < 4; j++)
                #pragma unroll
                for (int p = 0; p < 4; p++) acc[i][j][p] = 0.f;

        int rowbase = (t*B_ + b) * 256 + nt*128;
        gemm_pass64(asb, bsb, acc, br, mt, g_xsT, rowbase, tid, wm, wn, lane);

        if (br == 0) {
            // stage spike tile [n_l][o_l] in smem, then write g_qT coalesced
            __syncthreads();
            __half* Sq = (__half*)dynsmem;
            #pragma unroll
            for (int i = 0; i < 2; i++) {
                #pragma unroll
                for (int j = 0; j < 4; j++) {
                    #pragma unroll
                    for (int rh = 0; rh < 2; rh++) {
                        float y0 = (acc[i][j][rh*2+0] - mean[i][rh]) * scl[i][rh] + beta[i][rh];
                        float y1 = (acc[i][j][rh*2+1] - mean[i][rh]) * scl[i][rh] + beta[i][rh];
                        float s0 = lif_step(vm[i][rh][j][0], y0, 1.0f);
                        float s1 = lif_step(vm[i][rh][j][1], y1, 1.0f);
                        int o_l = wm + i*16 + rh*8 + (lane >> 2);
                        int n_l = wn + j*8 + 2*(lane & 3);
                        Sq[n_l*72 + o_l]     = __float2half_rn(s0);
                        Sq[(n_l+1)*72 + o_l] = __float2half_rn(s1);
                    }
                }
            }
            __syncthreads();
            #pragma unroll
            for (int r = 0; r < 2; r++) {
                int idx = tid + r * 256;           // 512 uint4: 128 rows x 8 chunks
                int row = idx >> 3, chk = idx & 7;
                *(uint4*)(g_qT + ((size_t)(t*B_ + b) * N_ + nt*128 + row) * C_ + mt*64 + chk*8) =
                    *(const uint4*)(&Sq[row*72 + chk*8]);
            }
            __syncthreads();
        } else {
            #pragma unroll
            for (int i = 0; i < 2; i++) {
                #pragma unroll
                for (int j = 0; j < 4; j++) {
                    #pragma unroll
                    for (int rh = 0; rh < 2; rh++) {
                        float y0 = (acc[i][j][rh*2+0] - mean[i][rh]) * scl[i][rh] + beta[i][rh];
                        float y1 = (acc[i][j][rh*2+1] - mean[i][rh]) * scl[i][rh] + beta[i][rh];
                        float s0 = lif_step(vm[i][rh][j][0], y0, 1.0f);
                        float s1 = lif_step(vm[i][rh][j][1], y1, 1.0f);
                        int o = mt*64 + wm + i*16 + rh*8 + (lane >> 2);
                        int n = nt*128 + wn + j*8 + 2*(lane & 3);
                        *(uint32_t*)(outp + ((size_t)(t*B_ + b) * C_ + o) * N_ + n) = hpair(s0, s1);
                    }
                }
            }
            __syncthreads();
        }
    }
}

// ============================================================
// K3a: kvT[e][d] = 0.125 * sum_n v[n,e]*k[n,d], fp16 MMA, exact.
// ============================================================
__global__ __launch_bounds__(128) void kvh_kernel() {
    __shared__ __align__(16) __half Ah[64][136];
    __shared__ __align__(16) __half Bh[64][136];
    uint32_t ahb = smem_u32(Ah), bhb = smem_u32(Bh);
    int tbh = blockIdx.x;
    int tb = tbh >> 3, hh = tbh & 7;
    int tid = threadIdx.x, lane = tid & 31, wid = tid >> 5;
    int em = (wid & 1) * 32, dn = (wid >> 1) * 32;

    const __half* vsrc = g_vh + ((size_t)tb * C_ + hh*64) * N_;
    const __half* ksrc = g_kh + ((size_t)tb * C_ + hh*64) * N_;

    float acc[2][4][4];
    #pragma unroll
    for (int i = 0; i < 2; i++)
        #pragma unroll
        for (int j = 0; j < 4; j++)
            #pragma unroll
            for (int p = 0; p < 4; p++) acc[i][j][p] = 0.f;

    int a_row = lane & 15, a_col = (lane >> 4) * 8;
    int b_row0 = dn + (lane & 7) + ((lane >> 4) << 3), b_col = lane & 8;

    for (int ch = 0; ch < 2; ch++) {
        #pragma unroll
        for (int r = 0; r < 4; r++) {
            int idx = tid + r * 128;
            int row = idx >> 3, cchunk = idx & 7;
            CP16(ahb + (uint32_t)((row*136 + cchunk*8) * 2), vsrc + (size_t)row * N_ + ch*128 + cchunk*8);
            CP16(bhb + (uint32_t)((row*136 + cchunk*8) * 2), ksrc + (size_t)row * N_ + ch*128 + cchunk*8);
        }
        CP_COMMIT(); CP_WAIT(0);
        __syncthreads();
        #pragma unroll
        for (int ks = 0; ks < 8; ks++) {
            int kc = ks * 16;
            uint32_t bfr[4][2];
            #pragma unroll
            for (int jp = 0; jp < 2; jp++) {
                uint32_t r4[4];
                ldm_x4(r4, bhb + (uint32_t)(((b_row0 + jp*16)*136 + kc + b_col) * 2));
                bfr[jp*2][0] = r4[0];   bfr[jp*2][1] = r4[1];
                bfr[jp*2+1][0] = r4[2]; bfr[jp*2+1][1] = r4[3];
            }
            #pragma unroll
            for (int i = 0; i < 2; i++) {
                uint32_t a4[4];
                ldm_x4(a4, ahb + (uint32_t)(((em + i*16 + a_row)*136 + kc + a_col) * 2));
                #pragma unroll
                for (int j = 0; j < 4; j++)
                    mma16816(acc[i][j], a4, bfr[j]);
            }
        }
        __syncthreads();
    }

    #pragma unroll
    for (int i = 0; i < 2; i++) {
        #pragma unroll
        for (int j = 0; j < 4; j++) {
            int e0 = em + i*16 + (lane >> 2);
            int d0 = dn + j*8 + 2*(lane & 3);
            *(uint32_t*)(g_kvT + ((size_t)tbh*64 + e0) * 64 + d0) =
                hpair(acc[i][j][0] * 0.125f, acc[i][j][1] * 0.125f);
            *(uint32_t*)(g_kvT + ((size_t)tbh*64 + e0 + 8) * 64 + d0) =
                hpair(acc[i][j][2] * 0.125f, acc[i][j][3] * 0.125f);
        }
    }
}

// ============================================================
// K3b: a[n][e] = qT @ kvT^T (scale folded), LIF(0.5) over t,
// double-buffered across t; writes fp16 spikes g_sT [tb][n][c].
// ============================================================
#define ATTN_AQ_BYTES (128*72*2)
#define ATTN_BK_BYTES (64*72*2)
#define ATTN_STAGE (ATTN_AQ_BYTES + ATTN_BK_BYTES)
#define ATTN_SMEM (2*ATTN_STAGE)

__device__ __forceinline__ void attn_load_t(uint32_t base, int t, int b, int nt, int hh, int tid) {
    uint32_t aqb = base, bkb = base + ATTN_AQ_BYTES;
    int tb = t * B_ + b, tbh = tb * 8 + hh;
    #pragma unroll
    for (int r = 0; r < 4; r++) {
        int idx = tid + r * 256;
        int row = idx >> 3, cchunk = idx & 7;
        CP16(aqb + (uint32_t)((row*72 + cchunk*8) * 2),
             g_qT + ((size_t)tb * N_ + nt*128 + row) * C_ + hh*64 + cchunk*8);
    }
    #pragma unroll
    for (int r = 0; r < 2; r++) {
        int idx = tid + r * 256;
        int row = idx >> 3, cchunk = idx & 7;
        CP16(bkb + (uint32_t)((row*72 + cchunk*8) * 2),
             g_kvT + ((size_t)tbh*64 + row) * 64 + cchunk*8);
    }
}

__global__ __launch_bounds__(256) void attn_mma_kernel() {
    extern __shared__ char dynattn[];
    uint32_t sb = smem_u32(dynattn);
    int bx = blockIdx.x;
    int nt = bx & 1, hh = (bx >> 1) & 7, b = bx >> 4;
    int tid = threadIdx.x, lane = tid & 31, wid = tid >> 5;
    int nb = (wid & 3) * 32, eb = (wid >> 2) * 32;

    int a_row = lane & 15, a_col = (lane >> 4) * 8;
    int b_row0 = eb + (lane & 7) + ((lane >> 4) << 3), b_col = lane & 8;

    float vm[2][4][4];
    #pragma unroll
    for (int i = 0; i < 2; i++)
        #pragma unroll
        for (int j = 0; j < 4; j++)
            #pragma unroll
            for (int p = 0; p < 4; p++) vm[i][j][p] = 0.f;

    attn_load_t(sb, 0, b, nt, hh, tid);
    CP_COMMIT();

    for (int t = 0; t < T_; t++) {
        if (t < 3) {
            attn_load_t(sb + ((t+1) & 1) * ATTN_STAGE, t+1, b, nt, hh, tid);
            CP_COMMIT();
            CP_WAIT(1);
        } else {
            CP_WAIT(0);
        }
        __syncthreads();
        uint32_t aqb = sb + (t & 1) * ATTN_STAGE, bkb = aqb + ATTN_AQ_BYTES;
        int tb = t * B_ + b;

        float acc[2][4][4];
        #pragma unroll
        for (int i = 0; i < 2; i++)
            #pragma unroll
            for (int j = 0; j < 4; j++)
                #pragma unroll
                for (int p = 0; p < 4; p++) acc[i][j][p] = 0.f;

        #pragma unroll
        for (int ks = 0; ks < 4; ks++) {
            int kc = ks * 16;
            uint32_t bfr[4][2];
            #pragma unroll
            for (int jp = 0; jp < 2; jp++) {
                uint32_t r4[4];
                ldm_x4(r4, bkb + (uint32_t)(((b_row0 + jp*16)*72 + kc + b_col) * 2));
                bfr[jp*2][0] = r4[0];   bfr[jp*2][1] = r4[1];
                bfr[jp*2+1][0] = r4[2]; bfr[jp*2+1][1] = r4[3];
            }
            #pragma unroll
            for (int i = 0; i < 2; i++) {
                uint32_t a4[4];
                ldm_x4(a4, aqb + (uint32_t)(((nb + i*16 + a_row)*72 + kc + a_col) * 2));
                #pragma unroll
                for (int j = 0; j < 4; j++)
                    mma16816(acc[i][j], a4, bfr[j]);
            }
        }

        #pragma unroll
        for (int i = 0; i < 2; i++) {
            #pragma unroll
            for (int j = 0; j < 4; j++) {
                int n0 = nb + i*16 + (lane >> 2);
                int e0 = eb + j*8 + 2*(lane & 3);
                float s0 = lif_step(vm[i][j][0], acc[i][j][0], 0.5f);
                float s1 = lif_step(vm[i][j][1], acc[i][j][1], 0.5f);
                float s2 = lif_step(vm[i][j][2], acc[i][j][2], 0.5f);
                float s3 = lif_step(vm[i][j][3], acc[i][j][3], 0.5f);
                *(uint32_t*)(g_sT + ((size_t)tb * N_ + nt*128 + n0) * C_ + hh*64 + e0) = hpair(s0, s1);
                *(uint32_t*)(g_sT + ((size_t)tb * N_ + nt*128 + n0 + 8) * C_ + hh*64 + e0) = hpair(s2, s3);
            }
        }
        __syncthreads();
    }
}

// ============================================================
// K4: proj GEMM (M128) + bias + BN -> d_out.  grid = 1024.
// ============================================================
__global__ __launch_bounds__(256, 1) void proj_mma_kernel(
    const float* __restrict__ pbias, const float* __restrict__ pg, const float* __restrict__ pb,
    const float* __restrict__ pm, const float* __restrict__ pv, float* __restrict__ out)
{
    extern __shared__ char dynsmem[];
    uint32_t asb = smem_u32(dynsmem), bsb = asb + NSTG*A_STAGE_BYTES;
    int tid = threadIdx.x, lane = tid & 31, wid = tid >> 5;
    int wm = (wid & 3) * 32, wn = (wid >> 2) * 64;
    int bx = blockIdx.x;
    int nt = bx & 1, mt = (bx >> 1) & 3, tb = bx >> 3;

    float scl[2][2], mean[2][2], beta[2][2], bias[2][2];
    #pragma unroll
    for (int i = 0; i < 2; i++)
        #pragma unroll
        for (int rh = 0; rh < 2; rh++) {
            int o = mt*128 + wm + i*16 + rh*8 + (lane >> 2);
            scl[i][rh]  = pg[o] / sqrtf(pv[o] + 1e-5f);
            mean[i][rh] = pm[o];
            beta[i][rh] = pb[o];
            bias[i][rh] = pbias[o];
        }

    float acc[2][8][4];
    #pragma unroll
    for (int i = 0; i < 2; i++)
        #pragma unroll
        for (int j = 0; j < 8; j++)
            #pragma unroll
            for (int p = 0; p < 4; p++) acc[i][j][p] = 0.f;

    int rowbase = tb * 256 + nt*128;
    gemm_pass(asb, bsb, acc, 3, mt, g_sT, rowbase, tid, wm, wn, lane);

    #pragma unroll
    for (int i = 0; i < 2; i++) {
        #pragma unroll
        for (int j = 0; j < 8; j++) {
            #pragma unroll
            for (int rh = 0; rh < 2; rh++) {
                float y0 = ((acc[i][j][rh*2+0] + bias[i][rh]) - mean[i][rh]) * scl[i][rh] + beta[i][rh];
                float y1 = ((acc[i][j][rh*2+1] + bias[i][rh]) - mean[i][rh]) * scl[i][rh] + beta[i][rh];
                int o = mt*128 + wm + i*16 + rh*8 + (lane >> 2);
                int n = nt*128 + wn + j*8 + 2*(lane & 3);
                *(float2*)(out + ((size_t)tb * C_ + o) * N_ + n) = make_float2(y0, y1);
            }
        }
    }
}

// ============================================================
extern "C" void kernel_launch(void* const* d_in, const int* in_sizes, int n_in,
                              void* d_out, int out_size) {
    (void)in_sizes; (void)n_in; (void)out_size;
    const float* x  = (const float*)d_in[0];
    const float* qw = (const float*)d_in[1];
    const float* qg = (const float*)d_in[2];
    const float* qb = (const float*)d_in[3];
    const float* qm = (const float*)d_in[4];
    const float* qv = (const float*)d_in[5];
    const float* kw = (const float*)d_in[6];
    const float* kg = (const float*)d_in[7];
    const float* kb = (const float*)d_in[8];
    const float* km = (const float*)d_in[9];
    const float* kvv= (const float*)d_in[10];
    const float* vw = (const float*)d_in[11];
    const float* vg = (const float*)d_in[12];
    const float* vb = (const float*)d_in[13];
    const float* vm = (const float*)d_in[14];
    const float* vv = (const float*)d_in[15];
    const float* pw    = (const float*)d_in[16];
    const float* pbias = (const float*)d_in[17];
    const float* pg    = (const float*)d_in[18];
    const float* pb    = (const float*)d_in[19];
    const float* pm    = (const float*)d_in[20];
    const float* pv    = (const float*)d_in[21];

    cudaFuncSetAttribute(qkv_mma_kernel, cudaFuncAttributeMaxDynamicSharedMemorySize, GEMM64_SMEM);
    cudaFuncSetAttribute(proj_mma_kernel, cudaFuncAttributeMaxDynamicSharedMemorySize, GEMM_SMEM);
    cudaFuncSetAttribute(attn_mma_kernel, cudaFuncAttributeMaxDynamicSharedMemorySize, ATTN_SMEM);

    wsplit_kernel<<<4096, 256>>>(qw, kw, vw, pw);
    lifx_kernel<<<1024, 256>>>(x);
    qkv_mma_kernel<<<dim3(512, 3), 256, GEMM64_SMEM>>>(qg, qb, qm, qv, kg, kb, km, kvv, vg, vb, vm, vv);
    kvh_kernel<<<1024, 128>>>();
    attn_mma_kernel<<<512, 256, ATTN_SMEM>>>();
    proj_mma_kernel<<<1024, 256, GEMM_SMEM>>>(pbias, pg, pb, pm, pv, (float*)d_out);
}

// round 11
// speedup vs baseline: 2.7901x; 1.0266x over previous
#include <cuda_runtime.h>
#include <cuda_fp16.h>
#include <cstdint>

#define T_ 4
#define B_ 32
#define C_ 512
#define N_ 256
#define H_ 8
#define D_ 64
#define BCN_ (B_*C_*N_)
#define TBCN_ (T_*BCN_)

// ---- scratch ----
__device__ __half g_kh[TBCN_];         // [tb][c][n] fp16 spikes
__device__ __half g_vh[TBCN_];
__device__ __half g_qT[TBCN_];         // [tb][n][c] fp16 spikes
__device__ __half g_xsT[TBCN_];        // [t][b][n][c] spikes fp16 (K-major)
__device__ __half g_sT[TBCN_];         // [tb][n][c] attn spikes fp16
__device__ __half g_wl[4*2*C_*C_];     // [mat][limb][o][c] fp16 weight limbs

// ================= helpers =================
__device__ __forceinline__ uint32_t smem_u32(const void* p) {
    uint32_t a;
    asm("{ .reg .u64 t; cvta.to.shared.u64 t, %1; cvt.u32.u64 %0, t; }" : "=r"(a) : "l"(p));
    return a;
}

#define CP16(dst, src) \
    asm volatile("cp.async.cg.shared.global [%0], [%1], 16;" :: "r"(dst), "l"(src))
#define CP_COMMIT() asm volatile("cp.async.commit_group;" ::: "memory")
#define CP_WAIT(n)  asm volatile("cp.async.wait_group %0;" :: "n"(n) : "memory")

__device__ __forceinline__ void ldm_x4(uint32_t r[4], uint32_t addr) {
    asm volatile("ldmatrix.sync.aligned.m8n8.x4.shared.b16 {%0,%1,%2,%3}, [%4];"
        : "=r"(r[0]), "=r"(r[1]), "=r"(r[2]), "=r"(r[3]) : "r"(addr));
}
__device__ __forceinline__ void mma16816(float c[4], const uint32_t a[4], const uint32_t* b) {
    asm volatile("mma.sync.aligned.m16n8k16.row.col.f32.f16.f16.f32 "
        "{%0,%1,%2,%3}, {%4,%5,%6,%7}, {%8,%9}, {%0,%1,%2,%3};"
        : "+f"(c[0]), "+f"(c[1]), "+f"(c[2]), "+f"(c[3])
        : "r"(a[0]), "r"(a[1]), "r"(a[2]), "r"(a[3]), "r"(b[0]), "r"(b[1]));
}

__device__ __forceinline__ float lif_step(float& v, float x, float vth) {
    v += (x - v) * 0.5f;
    float s = (v >= vth) ? 1.0f : 0.0f;
    if (s != 0.0f) v = 0.0f;
    return s;
}
__device__ __forceinline__ uint32_t hpair(float lo, float hi) {
    return (uint32_t)__half_as_ushort(__float2half_rn(lo)) |
           ((uint32_t)__half_as_ushort(__float2half_rn(hi)) << 16);
}

// ============================================================
// K0+K1 merged prep: blocks [0,4096) = weight limb split,
// blocks [4096,5120) = LIF(x) -> fp16 spikes [t][b][n][c].
// ============================================================
__global__ __launch_bounds__(256) void prep_kernel(
    const float* __restrict__ x,
    const float* __restrict__ qw, const float* __restrict__ kw,
    const float* __restrict__ vw, const float* __restrict__ pw)
{
    __shared__ __half Sb[64][72];
    if (blockIdx.x < 4096) {
        int i = blockIdx.x * 256 + threadIdx.x;
        int mat = i >> 18, idx = i & 262143;
        const float* W = (mat == 0) ? qw : (mat == 1) ? kw : (mat == 2) ? vw : pw;
        float w = W[idx];
        __half h1 = __float2half_rn(w);
        float r1 = w - __half2float(h1);
        __half h2 = __float2half_rn(r1);
        size_t base = (size_t)(mat * 2) * 262144 + idx;
        g_wl[base] = h1;
        g_wl[base + 262144] = h2;
        return;
    }
    int bx = blockIdx.x - 4096;
    int ch = bx & 7, nt = (bx >> 3) & 3, b = bx >> 5;
    int tid = threadIdx.x;
    int c_l = tid >> 2, ng = tid & 3;
    int n_o = tid >> 2, u0 = tid & 3;
    float vm[16];
    #pragma unroll
    for (int j = 0; j < 16; j++) vm[j] = 0.f;

    for (int t = 0; t < T_; t++) {
        const float* xp = x + (((size_t)(t * B_ + b)) * C_ + ch * 64 + c_l) * N_ + nt * 64 + ng * 16;
        #pragma unroll
        for (int q = 0; q < 4; q++) {
            float4 xv = *(const float4*)(xp + q * 4);
            Sb[c_l][ng*16 + q*4 + 0] = __float2half_rn(lif_step(vm[q*4+0], xv.x, 1.0f));
            Sb[c_l][ng*16 + q*4 + 1] = __float2half_rn(lif_step(vm[q*4+1], xv.y, 1.0f));
            Sb[c_l][ng*16 + q*4 + 2] = __float2half_rn(lif_step(vm[q*4+2], xv.z, 1.0f));
            Sb[c_l][ng*16 + q*4 + 3] = __float2half_rn(lif_step(vm[q*4+3], xv.w, 1.0f));
        }
        __syncthreads();
        char* outb = (char*)(g_xsT + ((size_t)(t*B_ + b) * N_ + nt*64 + n_o) * C_ + ch*64);
        #pragma unroll
        for (int hf = 0; hf < 2; hf++) {
            int u = u0 + hf * 4;
            uint32_t rp[4];
            #pragma unroll
            for (int p = 0; p < 4; p++) {
                float lo = __half2float(Sb[u*8 + p*2][n_o]);
                float hi = __half2float(Sb[u*8 + p*2 + 1][n_o]);
                rp[p] = hpair(lo, hi);
            }
            *(uint4*)(outb + u*16) = make_uint4(rp[0], rp[1], rp[2], rp[3]);
        }
        __syncthreads();
    }
}

// ============================================================
// M64 GEMM machinery: 64x128 block, 8 warps (2m x 4n),
// warp 32x32, 4-stage pipeline.  Smem 48KB.
// ============================================================
#define B_STAGE_BYTES (128*24*2)
#define A64_STAGE_BYTES (2*64*24*2)
#define NSTG 4
#define GEMM64_SMEM (NSTG*A64_STAGE_BYTES + NSTG*B_STAGE_BYTES)

__device__ __forceinline__ void load_stage_B(uint32_t bsb, int s, int kc,
                                             const __half* srcT, int rowbase, int tid) {
    int n = tid >> 1, h = tid & 1;
    const __half* src = srcT + ((size_t)(rowbase + n)) * 512 + kc + h*8;
    uint32_t dst = bsb + (uint32_t)(((s*128 + n)*24 + h*8) * 2);
    CP16(dst, src);
}
__device__ __forceinline__ void load_stage_A64(uint32_t asb, int s, int kc, int wmat, int mt, int tid) {
    int l = tid >> 7, rem = tid & 127;
    int o = rem >> 1, h = rem & 1;
    const __half* src = g_wl + ((size_t)(wmat*2 + l) * 512 + mt*64 + o) * 512 + kc + h*8;
    uint32_t dst = asb + (uint32_t)((((s*2 + l)*64 + o)*24 + h*8) * 2);
    CP16(dst, src);
}

__device__ __forceinline__ void gemm_pass64(uint32_t asb, uint32_t bsb, float acc[2][4][4],
                                            int wmat, int mt, const __half* srcT, int rowbase,
                                            int tid, int wm, int wn, int lane) {
    #pragma unroll
    for (int p = 0; p < 3; p++) {
        load_stage_A64(asb, p, p*16, wmat, mt, tid);
        load_stage_B(bsb, p, p*16, srcT, rowbase, tid);
        CP_COMMIT();
    }

    int a_row = lane & 15, a_col = (lane >> 4) * 8;
    int b_row = wn + (lane & 7) + ((lane >> 4) << 3), b_col = lane & 8;

    int s = 0;
    for (int c = 0; c < 32; c++) {
        CP_WAIT(2);
        __syncthreads();
        if (c + 3 < 32) {
            int ns = s + 3; if (ns >= NSTG) ns -= NSTG;
            load_stage_A64(asb, ns, (c+3)*16, wmat, mt, tid);
            load_stage_B(bsb, ns, (c+3)*16, srcT, rowbase, tid);
        }
        CP_COMMIT();

        uint32_t bfr[4][2];
        #pragma unroll
        for (int jp = 0; jp < 2; jp++) {
            uint32_t r4[4];
            uint32_t addr = bsb + (uint32_t)((((s*128) + b_row + jp*16)*24 + b_col) * 2);
            ldm_x4(r4, addr);
            bfr[jp*2][0] = r4[0];   bfr[jp*2][1] = r4[1];
            bfr[jp*2+1][0] = r4[2]; bfr[jp*2+1][1] = r4[3];
        }
        #pragma unroll
        for (int l = 0; l < 2; l++) {
            #pragma unroll
            for (int i = 0; i < 2; i++) {
                uint32_t a4[4];
                uint32_t addr = asb + (uint32_t)(((((s*2 + l)*64) + wm + i*16 + a_row)*24 + a_col) * 2);
                ldm_x4(a4, addr);
                #pragma unroll
                for (int j = 0; j < 4; j++)
                    mma16816(acc[i][j], a4, bfr[j]);
            }
        }
        if (++s >= NSTG) s = 0;
    }
}

// ============================================================
// K2: qkv GEMM (M64) + BN + LIF.  q writes g_qT [n][c] via smem
// transpose; k/v write [c][n].  grid.x = 512, grid.y = 3.
// ============================================================
__global__ __launch_bounds__(256, 2) void qkv_mma_kernel(
    const float* __restrict__ qg, const float* __restrict__ qb, const float* __restrict__ qm, const float* __restrict__ qv,
    const float* __restrict__ kg, const float* __restrict__ kb, const float* __restrict__ km, const float* __restrict__ kvv,
    const float* __restrict__ vg, const float* __restrict__ vb, const float* __restrict__ vmn, const float* __restrict__ vvv)
{
    extern __shared__ char dynsmem[];
    uint32_t asb = smem_u32(dynsmem), bsb = asb + NSTG*A64_STAGE_BYTES;
    int tid = threadIdx.x, lane = tid & 31, wid = tid >> 5;
    int wm = (wid & 1) * 32, wn = (wid >> 1) * 32;
    int bx = blockIdx.x, br = blockIdx.y;
    int nt = bx & 1, mt = (bx >> 1) & 7, b = bx >> 4;

    const float* G  = (br == 0) ? qg : (br == 1) ? kg : vg;
    const float* Bt = (br == 0) ? qb : (br == 1) ? kb : vb;
    const float* M  = (br == 0) ? qm : (br == 1) ? km : vmn;
    const float* V  = (br == 0) ? qv : (br == 1) ? kvv : vvv;
    __half* outp = (br == 1) ? g_kh : g_vh;

    float scl[2][2], mean[2][2], beta[2][2];
    #pragma unroll
    for (int i = 0; i < 2; i++)
        #pragma unroll
        for (int rh = 0; rh < 2; rh++) {
            int o = mt*64 + wm + i*16 + rh*8 + (lane >> 2);
            scl[i][rh]  = G[o] / sqrtf(V[o] + 1e-5f);
            mean[i][rh] = M[o];
            beta[i][rh] = Bt[o];
        }

    float vm[2][2][4][2];
    #pragma unroll
    for (int i = 0; i < 2; i++)
        #pragma unroll
        for (int rh = 0; rh < 2; rh++)
            #pragma unroll
            for (int j = 0; j < 4; j++) { vm[i][rh][j][0] = 0.f; vm[i][rh][j][1] = 0.f; }

    for (int t = 0; t < T_; t++) {
        float acc[2][4][4];
        #pragma unroll
        for (int i = 0; i < 2; i++)
            #pragma unroll
            for (int j = 0; j < 4; j++)
                #pragma unroll
                for (int p = 0; p < 4; p++) acc[i][j][p] = 0.f;

        int rowbase = (t*B_ + b) * 256 + nt*128;
        gemm_pass64(asb, bsb, acc, br, mt, g_xsT, rowbase, tid, wm, wn, lane);

        if (br == 0) {
            __syncthreads();
            __half* Sq = (__half*)dynsmem;
            #pragma unroll
            for (int i = 0; i < 2; i++) {
                #pragma unroll
                for (int j = 0; j < 4; j++) {
                    #pragma unroll
                    for (int rh = 0; rh < 2; rh++) {
                        float y0 = (acc[i][j][rh*2+0] - mean[i][rh]) * scl[i][rh] + beta[i][rh];
                        float y1 = (acc[i][j][rh*2+1] - mean[i][rh]) * scl[i][rh] + beta[i][rh];
                        float s0 = lif_step(vm[i][rh][j][0], y0, 1.0f);
                        float s1 = lif_step(vm[i][rh][j][1], y1, 1.0f);
                        int o_l = wm + i*16 + rh*8 + (lane >> 2);
                        int n_l = wn + j*8 + 2*(lane & 3);
                        Sq[n_l*72 + o_l]     = __float2half_rn(s0);
                        Sq[(n_l+1)*72 + o_l] = __float2half_rn(s1);
                    }
                }
            }
            __syncthreads();
            #pragma unroll
            for (int r = 0; r < 2; r++) {
                int idx = tid + r * 256;
                int row = idx >> 3, chk = idx & 7;
                *(uint4*)(g_qT + ((size_t)(t*B_ + b) * N_ + nt*128 + row) * C_ + mt*64 + chk*8) =
                    *(const uint4*)(&Sq[row*72 + chk*8]);
            }
            __syncthreads();
        } else {
            #pragma unroll
            for (int i = 0; i < 2; i++) {
                #pragma unroll
                for (int j = 0; j < 4; j++) {
                    #pragma unroll
                    for (int rh = 0; rh < 2; rh++) {
                        float y0 = (acc[i][j][rh*2+0] - mean[i][rh]) * scl[i][rh] + beta[i][rh];
                        float y1 = (acc[i][j][rh*2+1] - mean[i][rh]) * scl[i][rh] + beta[i][rh];
                        float s0 = lif_step(vm[i][rh][j][0], y0, 1.0f);
                        float s1 = lif_step(vm[i][rh][j][1], y1, 1.0f);
                        int o = mt*64 + wm + i*16 + rh*8 + (lane >> 2);
                        int n = nt*128 + wn + j*8 + 2*(lane & 3);
                        *(uint32_t*)(outp + ((size_t)(t*B_ + b) * C_ + o) * N_ + n) = hpair(s0, s1);
                    }
                }
            }
            __syncthreads();
        }
    }
}

// ============================================================
// K3 fused: per (b,h) block: for each t, kv = 0.125*v@k^T via MMA
// (kept in smem), then a = q@kv^T via MMA, LIF(0.5), spikes -> g_sT.
// Dyn smem: Ah[2][64][136] + Bh[2][64][136] + Q[256][72] + KV[64][72].
// ============================================================
#define KA_AH 0
#define KA_BH (2*64*136*2)
#define KA_Q  (4*64*136*2)
#define KA_KV (KA_Q + 256*72*2)
#define KA_SMEM (KA_KV + 64*72*2)

__global__ __launch_bounds__(256, 1) void kvattn_kernel() {
    extern __shared__ char dynka[];
    uint32_t sb = smem_u32(dynka);
    uint32_t qbuf = sb + KA_Q, kvb = sb + KA_KV;
    int bh = blockIdx.x;
    int b = bh >> 3, hh = bh & 7;
    int tid = threadIdx.x, lane = tid & 31, wid = tid >> 5;

    // kv warp tiles: 16e x 32d, 4x2 warp grid
    int em = (wid & 3) * 16, dn = (wid >> 2) * 32;
    // attn warp tile: 32n x 64e
    int nb = wid * 32;

    int a_row = lane & 15, a_col8 = (lane >> 4) * 8;
    int kb_row0 = dn + (lane & 7) + ((lane >> 4) << 3), kb_col = lane & 8;
    int ab_row0 = (lane & 7) + ((lane >> 4) << 3), ab_col = lane & 8;

    float vmn[2][8][4];
    #pragma unroll
    for (int i = 0; i < 2; i++)
        #pragma unroll
        for (int j = 0; j < 8; j++)
            #pragma unroll
            for (int p = 0; p < 4; p++) vmn[i][j][p] = 0.f;

    for (int t = 0; t < T_; t++) {
        int tb = t * B_ + b;
        const __half* vsrc = g_vh + ((size_t)tb * C_ + hh*64) * N_;
        const __half* ksrc = g_kh + ((size_t)tb * C_ + hh*64) * N_;

        // group 1: q tile + kv chunk 0 ; group 2: kv chunk 1
        #pragma unroll
        for (int r = 0; r < 8; r++) {
            int idx = tid + r * 256;
            int row = idx >> 3, chk = idx & 7;
            CP16(qbuf + (uint32_t)((row*72 + chk*8) * 2),
                 g_qT + ((size_t)tb * N_ + row) * C_ + hh*64 + chk*8);
        }
        #pragma unroll
        for (int r = 0; r < 2; r++) {
            int idx = tid + r * 256;
            int row = idx >> 3, chk = idx & 7;
            CP16(sb + KA_AH + (uint32_t)((row*136 + chk*8) * 2), vsrc + (size_t)row * N_ + chk*8);
            CP16(sb + KA_BH + (uint32_t)((row*136 + chk*8) * 2), ksrc + (size_t)row * N_ + chk*8);
        }
        CP_COMMIT();
        #pragma unroll
        for (int r = 0; r < 2; r++) {
            int idx = tid + r * 256;
            int row = idx >> 3, chk = idx & 7;
            CP16(sb + KA_AH + (uint32_t)(((64 + row)*136 + chk*8) * 2), vsrc + (size_t)row * N_ + 128 + chk*8);
            CP16(sb + KA_BH + (uint32_t)(((64 + row)*136 + chk*8) * 2), ksrc + (size_t)row * N_ + 128 + chk*8);
        }
        CP_COMMIT();

        float kacc[4][4];
        #pragma unroll
        for (int j = 0; j < 4; j++)
            #pragma unroll
            for (int p = 0; p < 4; p++) kacc[j][p] = 0.f;

        #pragma unroll
        for (int ch = 0; ch < 2; ch++) {
            if (ch == 0) CP_WAIT(1); else CP_WAIT(0);
            __syncthreads();
            uint32_t ahb = sb + KA_AH + ch * (64*136*2);
            uint32_t bhb = sb + KA_BH + ch * (64*136*2);
            #pragma unroll
            for (int ks = 0; ks < 8; ks++) {
                int kc = ks * 16;
                uint32_t bfr[4][2];
                #pragma unroll
                for (int jp = 0; jp < 2; jp++) {
                    uint32_t r4[4];
                    ldm_x4(r4, bhb + (uint32_t)(((kb_row0 + jp*16)*136 + kc + kb_col) * 2));
                    bfr[jp*2][0] = r4[0];   bfr[jp*2][1] = r4[1];
                    bfr[jp*2+1][0] = r4[2]; bfr[jp*2+1][1] = r4[3];
                }
                uint32_t a4[4];
                ldm_x4(a4, ahb + (uint32_t)(((em + a_row)*136 + kc + a_col8) * 2));
                #pragma unroll
                for (int j = 0; j < 4; j++)
                    mma16816(kacc[j], a4, bfr[j]);
            }
        }

        // store scaled kv to smem kvT [e][d]
        __syncthreads();   // everyone done reading Ah/Bh (and q has arrived)
        #pragma unroll
        for (int j = 0; j < 4; j++) {
            int e0 = em + (lane >> 2);
            int d0 = dn + j*8 + 2*(lane & 3);
            *(uint32_t*)(dynka + KA_KV + ((e0)*72 + d0) * 2)     = hpair(kacc[j][0] * 0.125f, kacc[j][1] * 0.125f);
            *(uint32_t*)(dynka + KA_KV + ((e0 + 8)*72 + d0) * 2) = hpair(kacc[j][2] * 0.125f, kacc[j][3] * 0.125f);
        }
        __syncthreads();

        // attn: a[n][e] = q @ kvT^T, K = d = 64
        float acc[2][8][4];
        #pragma unroll
        for (int i = 0; i < 2; i++)
            #pragma unroll
            for (int j = 0; j < 8; j++)
                #pragma unroll
                for (int p = 0; p < 4; p++) acc[i][j][p] = 0.f;

        #pragma unroll
        for (int ks = 0; ks < 4; ks++) {
            int kc = ks * 16;
            uint32_t bfr[8][2];
            #pragma unroll
            for (int jp = 0; jp < 4; jp++) {
                uint32_t r4[4];
                ldm_x4(r4, kvb + (uint32_t)(((ab_row0 + jp*16)*72 + kc + ab_col) * 2));
                bfr[jp*2][0] = r4[0];   bfr[jp*2][1] = r4[1];
                bfr[jp*2+1][0] = r4[2]; bfr[jp*2+1][1] = r4[3];
            }
            #pragma unroll
            for (int i = 0; i < 2; i++) {
                uint32_t a4[4];
                ldm_x4(a4, qbuf + (uint32_t)(((nb + i*16 + a_row)*72 + kc + a_col8) * 2));
                #pragma unroll
                for (int j = 0; j < 8; j++)
                    mma16816(acc[i][j], a4, bfr[j]);
            }
        }

        #pragma unroll
        for (int i = 0; i < 2; i++) {
            #pragma unroll
            for (int j = 0; j < 8; j++) {
                int n0 = nb + i*16 + (lane >> 2);
                int e0 = j*8 + 2*(lane & 3);
                float s0 = lif_step(vmn[i][j][0], acc[i][j][0], 0.5f);
                float s1 = lif_step(vmn[i][j][1], acc[i][j][1], 0.5f);
                float s2 = lif_step(vmn[i][j][2], acc[i][j][2], 0.5f);
                float s3 = lif_step(vmn[i][j][3], acc[i][j][3], 0.5f);
                *(uint32_t*)(g_sT + ((size_t)tb * N_ + n0) * C_ + hh*64 + e0) = hpair(s0, s1);
                *(uint32_t*)(g_sT + ((size_t)tb * N_ + n0 + 8) * C_ + hh*64 + e0) = hpair(s2, s3);
            }
        }
        __syncthreads();   // smem reusable for next t
    }
}

// ============================================================
// K4: proj GEMM (M64) + bias + BN -> d_out.  grid = 2048.
// ============================================================
__global__ __launch_bounds__(256, 2) void proj_mma_kernel(
    const float* __restrict__ pbias, const float* __restrict__ pg, const float* __restrict__ pb,
    const float* __restrict__ pm, const float* __restrict__ pv, float* __restrict__ out)
{
    extern __shared__ char dynsmem[];
    uint32_t asb = smem_u32(dynsmem), bsb = asb + NSTG*A64_STAGE_BYTES;
    int tid = threadIdx.x, lane = tid & 31, wid = tid >> 5;
    int wm = (wid & 1) * 32, wn = (wid >> 1) * 32;
    int bx = blockIdx.x;
    int nt = bx & 1, mt = (bx >> 1) & 7, tb = bx >> 4;

    float scl[2][2], mean[2][2], beta[2][2], bias[2][2];
    #pragma unroll
    for (int i = 0; i < 2; i++)
        #pragma unroll
        for (int rh = 0; rh < 2; rh++) {
            int o = mt*64 + wm + i*16 + rh*8 + (lane >> 2);
            scl[i][rh]  = pg[o] / sqrtf(pv[o] + 1e-5f);
            mean[i][rh] = pm[o];
            beta[i][rh] = pb[o];
            bias[i][rh] = pbias[o];
        }

    float acc[2][4][4];
    #pragma unroll
    for (int i = 0; i < 2; i++)
        #pragma unroll
        for (int j = 0; j < 4; j++)
            #pragma unroll
            for (int p = 0; p < 4; p++) acc[i][j][p] = 0.f;

    int rowbase = tb * 256 + nt*128;
    gemm_pass64(asb, bsb, acc, 3, mt, g_sT, rowbase, tid, wm, wn, lane);

    #pragma unroll
    for (int i = 0; i < 2; i++) {
        #pragma unroll
        for (int j = 0; j < 4; j++) {
            #pragma unroll
            for (int rh = 0; rh < 2; rh++) {
                float y0 = ((acc[i][j][rh*2+0] + bias[i][rh]) - mean[i][rh]) * scl[i][rh] + beta[i][rh];
                float y1 = ((acc[i][j][rh*2+1] + bias[i][rh]) - mean[i][rh]) * scl[i][rh] + beta[i][rh];
                int o = mt*64 + wm + i*16 + rh*8 + (lane >> 2);
                int n = nt*128 + wn + j*8 + 2*(lane & 3);
                *(float2*)(out + ((size_t)tb * C_ + o) * N_ + n) = make_float2(y0, y1);
            }
        }
    }
}

// ============================================================
extern "C" void kernel_launch(void* const* d_in, const int* in_sizes, int n_in,
                              void* d_out, int out_size) {
    (void)in_sizes; (void)n_in; (void)out_size;
    const float* x  = (const float*)d_in[0];
    const float* qw = (const float*)d_in[1];
    const float* qg = (const float*)d_in[2];
    const float* qb = (const float*)d_in[3];
    const float* qm = (const float*)d_in[4];
    const float* qv = (const float*)d_in[5];
    const float* kw = (const float*)d_in[6];
    const float* kg = (const float*)d_in[7];
    const float* kb = (const float*)d_in[8];
    const float* km = (const float*)d_in[9];
    const float* kvv= (const float*)d_in[10];
    const float* vw = (const float*)d_in[11];
    const float* vg = (const float*)d_in[12];
    const float* vb = (const float*)d_in[13];
    const float* vm = (const float*)d_in[14];
    const float* vv = (const float*)d_in[15];
    const float* pw    = (const float*)d_in[16];
    const float* pbias = (const float*)d_in[17];
    const float* pg    = (const float*)d_in[18];
    const float* pb    = (const float*)d_in[19];
    const float* pm    = (const float*)d_in[20];
    const float* pv    = (const float*)d_in[21];

    cudaFuncSetAttribute(qkv_mma_kernel, cudaFuncAttributeMaxDynamicSharedMemorySize, GEMM64_SMEM);
    cudaFuncSetAttribute(proj_mma_kernel, cudaFuncAttributeMaxDynamicSharedMemorySize, GEMM64_SMEM);
    cudaFuncSetAttribute(kvattn_kernel, cudaFuncAttributeMaxDynamicSharedMemorySize, KA_SMEM);

    prep_kernel<<<5120, 256>>>(x, qw, kw, vw, pw);
    qkv_mma_kernel<<<dim3(512, 3), 256, GEMM64_SMEM>>>(qg, qb, qm, qv, kg, kb, km, kvv, vg, vb, vm, vv);
    kvattn_kernel<<<256, 256, KA_SMEM>>>();
    proj_mma_kernel<<<2048, 256, GEMM64_SMEM>>>(pbias, pg, pb, pm, pv, (float*)d_out);
}

// round 12
// speedup vs baseline: 2.9759x; 1.0666x over previous
#include <cuda_runtime.h>
#include <cuda_fp16.h>
#include <cstdint>

#define T_ 4
#define B_ 32
#define C_ 512
#define N_ 256
#define H_ 8
#define D_ 64
#define BCN_ (B_*C_*N_)
#define TBCN_ (T_*BCN_)

// ---- scratch ----
__device__ __half g_kh[TBCN_];         // [tb][c][n] fp16 spikes
__device__ __half g_vh[TBCN_];
__device__ __half g_qT[TBCN_];         // [tb][n][c] fp16 spikes
__device__ __half g_xsT[TBCN_];        // [t][b][n][c] spikes fp16 (K-major)
__device__ __half g_sT[TBCN_];         // [tb][n][c] attn spikes fp16
__device__ __half g_wl[4*2*C_*C_];     // [mat][limb][o][c] fp16 weight limbs

// ================= helpers =================
__device__ __forceinline__ uint32_t smem_u32(const void* p) {
    uint32_t a;
    asm("{ .reg .u64 t; cvta.to.shared.u64 t, %1; cvt.u32.u64 %0, t; }" : "=r"(a) : "l"(p));
    return a;
}

#define CP16(dst, src) \
    asm volatile("cp.async.cg.shared.global [%0], [%1], 16;" :: "r"(dst), "l"(src))
#define CP_COMMIT() asm volatile("cp.async.commit_group;" ::: "memory")
#define CP_WAIT(n)  asm volatile("cp.async.wait_group %0;" :: "n"(n) : "memory")

__device__ __forceinline__ void ldm_x4(uint32_t r[4], uint32_t addr) {
    asm volatile("ldmatrix.sync.aligned.m8n8.x4.shared.b16 {%0,%1,%2,%3}, [%4];"
        : "=r"(r[0]), "=r"(r[1]), "=r"(r[2]), "=r"(r[3]) : "r"(addr));
}
__device__ __forceinline__ void mma16816(float c[4], const uint32_t a[4], const uint32_t* b) {
    asm volatile("mma.sync.aligned.m16n8k16.row.col.f32.f16.f16.f32 "
        "{%0,%1,%2,%3}, {%4,%5,%6,%7}, {%8,%9}, {%0,%1,%2,%3};"
        : "+f"(c[0]), "+f"(c[1]), "+f"(c[2]), "+f"(c[3])
        : "r"(a[0]), "r"(a[1]), "r"(a[2]), "r"(a[3]), "r"(b[0]), "r"(b[1]));
}

__device__ __forceinline__ float lif_step(float& v, float x, float vth) {
    v += (x - v) * 0.5f;
    float s = (v >= vth) ? 1.0f : 0.0f;
    if (s != 0.0f) v = 0.0f;
    return s;
}
__device__ __forceinline__ uint32_t hpair(float lo, float hi) {
    return (uint32_t)__half_as_ushort(__float2half_rn(lo)) |
           ((uint32_t)__half_as_ushort(__float2half_rn(hi)) << 16);
}

// ============================================================
// K0+K1 merged prep: blocks [0,4096) = weight limb split,
// blocks [4096,5120) = LIF(x) -> fp16 spikes [t][b][n][c].
// ============================================================
__global__ __launch_bounds__(256) void prep_kernel(
    const float* __restrict__ x,
    const float* __restrict__ qw, const float* __restrict__ kw,
    const float* __restrict__ vw, const float* __restrict__ pw)
{
    __shared__ __half Sb[64][72];
    if (blockIdx.x < 4096) {
        int i = blockIdx.x * 256 + threadIdx.x;
        int mat = i >> 18, idx = i & 262143;
        const float* W = (mat == 0) ? qw : (mat == 1) ? kw : (mat == 2) ? vw : pw;
        float w = W[idx];
        __half h1 = __float2half_rn(w);
        float r1 = w - __half2float(h1);
        __half h2 = __float2half_rn(r1);
        size_t base = (size_t)(mat * 2) * 262144 + idx;
        g_wl[base] = h1;
        g_wl[base + 262144] = h2;
        return;
    }
    int bx = blockIdx.x - 4096;
    int ch = bx & 7, nt = (bx >> 3) & 3, b = bx >> 5;
    int tid = threadIdx.x;
    int c_l = tid >> 2, ng = tid & 3;
    int n_o = tid >> 2, u0 = tid & 3;
    float vm[16];
    #pragma unroll
    for (int j = 0; j < 16; j++) vm[j] = 0.f;

    for (int t = 0; t < T_; t++) {
        const float* xp = x + (((size_t)(t * B_ + b)) * C_ + ch * 64 + c_l) * N_ + nt * 64 + ng * 16;
        #pragma unroll
        for (int q = 0; q < 4; q++) {
            float4 xv = *(const float4*)(xp + q * 4);
            Sb[c_l][ng*16 + q*4 + 0] = __float2half_rn(lif_step(vm[q*4+0], xv.x, 1.0f));
            Sb[c_l][ng*16 + q*4 + 1] = __float2half_rn(lif_step(vm[q*4+1], xv.y, 1.0f));
            Sb[c_l][ng*16 + q*4 + 2] = __float2half_rn(lif_step(vm[q*4+2], xv.z, 1.0f));
            Sb[c_l][ng*16 + q*4 + 3] = __float2half_rn(lif_step(vm[q*4+3], xv.w, 1.0f));
        }
        __syncthreads();
        char* outb = (char*)(g_xsT + ((size_t)(t*B_ + b) * N_ + nt*64 + n_o) * C_ + ch*64);
        #pragma unroll
        for (int hf = 0; hf < 2; hf++) {
            int u = u0 + hf * 4;
            uint32_t rp[4];
            #pragma unroll
            for (int p = 0; p < 4; p++) {
                float lo = __half2float(Sb[u*8 + p*2][n_o]);
                float hi = __half2float(Sb[u*8 + p*2 + 1][n_o]);
                rp[p] = hpair(lo, hi);
            }
            *(uint4*)(outb + u*16) = make_uint4(rp[0], rp[1], rp[2], rp[3]);
        }
        __syncthreads();
    }
}

// ============================================================
// M64 GEMM machinery: 64x128 block, 8 warps (2m x 4n), warp 32x32.
// Single-t variant (proj) and t-paired variant (qkv).
// ============================================================
#define B_STAGE_BYTES (128*24*2)
#define B2_STAGE_BYTES (256*24*2)
#define A64_STAGE_BYTES (2*64*24*2)
#define NSTG 4
#define GEMM64_SMEM   (NSTG*A64_STAGE_BYTES + NSTG*B_STAGE_BYTES)
#define GEMM64T2_SMEM (NSTG*A64_STAGE_BYTES + NSTG*B2_STAGE_BYTES)

__device__ __forceinline__ void load_stage_B(uint32_t bsb, int s, int kc,
                                             const __half* srcT, int rowbase, int tid) {
    int n = tid >> 1, h = tid & 1;
    const __half* src = srcT + ((size_t)(rowbase + n)) * 512 + kc + h*8;
    uint32_t dst = bsb + (uint32_t)(((s*128 + n)*24 + h*8) * 2);
    CP16(dst, src);
}
__device__ __forceinline__ void load_stage_B2(uint32_t bsb, int s, int kc,
                                              const __half* srcT, int rb0, int rb1, int tid) {
    int n = tid >> 1, h = tid & 1;
    CP16(bsb + (uint32_t)(((s*256 + n)*24 + h*8) * 2),
         srcT + ((size_t)(rb0 + n)) * 512 + kc + h*8);
    CP16(bsb + (uint32_t)(((s*256 + 128 + n)*24 + h*8) * 2),
         srcT + ((size_t)(rb1 + n)) * 512 + kc + h*8);
}
__device__ __forceinline__ void load_stage_A64(uint32_t asb, int s, int kc, int wmat, int mt, int tid) {
    int l = tid >> 7, rem = tid & 127;
    int o = rem >> 1, h = rem & 1;
    const __half* src = g_wl + ((size_t)(wmat*2 + l) * 512 + mt*64 + o) * 512 + kc + h*8;
    uint32_t dst = asb + (uint32_t)((((s*2 + l)*64 + o)*24 + h*8) * 2);
    CP16(dst, src);
}

// single-t pass (proj)
__device__ __forceinline__ void gemm_pass64(uint32_t asb, uint32_t bsb, float acc[2][4][4],
                                            int wmat, int mt, const __half* srcT, int rowbase,
                                            int tid, int wm, int wn, int lane) {
    #pragma unroll
    for (int p = 0; p < 3; p++) {
        load_stage_A64(asb, p, p*16, wmat, mt, tid);
        load_stage_B(bsb, p, p*16, srcT, rowbase, tid);
        CP_COMMIT();
    }
    int a_row = lane & 15, a_col = (lane >> 4) * 8;
    int b_row = wn + (lane & 7) + ((lane >> 4) << 3), b_col = lane & 8;

    int s = 0;
    for (int c = 0; c < 32; c++) {
        CP_WAIT(2);
        __syncthreads();
        if (c + 3 < 32) {
            int ns = s + 3; if (ns >= NSTG) ns -= NSTG;
            load_stage_A64(asb, ns, (c+3)*16, wmat, mt, tid);
            load_stage_B(bsb, ns, (c+3)*16, srcT, rowbase, tid);
        }
        CP_COMMIT();

        uint32_t bfr[4][2];
        #pragma unroll
        for (int jp = 0; jp < 2; jp++) {
            uint32_t r4[4];
            ldm_x4(r4, bsb + (uint32_t)((((s*128) + b_row + jp*16)*24 + b_col) * 2));
            bfr[jp*2][0] = r4[0];   bfr[jp*2][1] = r4[1];
            bfr[jp*2+1][0] = r4[2]; bfr[jp*2+1][1] = r4[3];
        }
        #pragma unroll
        for (int l = 0; l < 2; l++) {
            #pragma unroll
            for (int i = 0; i < 2; i++) {
                uint32_t a4[4];
                ldm_x4(a4, asb + (uint32_t)(((((s*2 + l)*64) + wm + i*16 + a_row)*24 + a_col) * 2));
                #pragma unroll
                for (int j = 0; j < 4; j++)
                    mma16816(acc[i][j], a4, bfr[j]);
            }
        }
        if (++s >= NSTG) s = 0;
    }
}

// t-paired pass (qkv): acc[t][i][j][4], A frags reused for both t.
__device__ __forceinline__ void gemm_pass64_t2(uint32_t asb, uint32_t bsb, float acc[2][2][4][4],
                                               int wmat, int mt, const __half* srcT,
                                               int rb0, int rb1,
                                               int tid, int wm, int wn, int lane) {
    #pragma unroll
    for (int p = 0; p < 3; p++) {
        load_stage_A64(asb, p, p*16, wmat, mt, tid);
        load_stage_B2(bsb, p, p*16, srcT, rb0, rb1, tid);
        CP_COMMIT();
    }
    int a_row = lane & 15, a_col = (lane >> 4) * 8;
    int b_row = wn + (lane & 7) + ((lane >> 4) << 3), b_col = lane & 8;

    int s = 0;
    for (int c = 0; c < 32; c++) {
        CP_WAIT(2);
        __syncthreads();
        if (c + 3 < 32) {
            int ns = s + 3; if (ns >= NSTG) ns -= NSTG;
            load_stage_A64(asb, ns, (c+3)*16, wmat, mt, tid);
            load_stage_B2(bsb, ns, (c+3)*16, srcT, rb0, rb1, tid);
        }
        CP_COMMIT();

        uint32_t bfr[2][4][2];
        #pragma unroll
        for (int t = 0; t < 2; t++) {
            #pragma unroll
            for (int jp = 0; jp < 2; jp++) {
                uint32_t r4[4];
                ldm_x4(r4, bsb + (uint32_t)((((s*256 + t*128) + b_row + jp*16)*24 + b_col) * 2));
                bfr[t][jp*2][0] = r4[0];   bfr[t][jp*2][1] = r4[1];
                bfr[t][jp*2+1][0] = r4[2]; bfr[t][jp*2+1][1] = r4[3];
            }
        }
        #pragma unroll
        for (int l = 0; l < 2; l++) {
            #pragma unroll
            for (int i = 0; i < 2; i++) {
                uint32_t a4[4];
                ldm_x4(a4, asb + (uint32_t)(((((s*2 + l)*64) + wm + i*16 + a_row)*24 + a_col) * 2));
                #pragma unroll
                for (int t = 0; t < 2; t++)
                    #pragma unroll
                    for (int j = 0; j < 4; j++)
                        mma16816(acc[t][i][j], a4, bfr[t][j]);
            }
        }
        if (++s >= NSTG) s = 0;
    }
}

// ============================================================
// K2: qkv GEMM (M64, t-paired) + BN + LIF.  q writes g_qT [n][c]
// via smem transpose; k/v write [c][n].  grid.x=512, grid.y=3.
// ============================================================
__global__ __launch_bounds__(256, 2) void qkv_mma_kernel(
    const float* __restrict__ qg, const float* __restrict__ qb, const float* __restrict__ qm, const float* __restrict__ qv,
    const float* __restrict__ kg, const float* __restrict__ kb, const float* __restrict__ km, const float* __restrict__ kvv,
    const float* __restrict__ vg, const float* __restrict__ vb, const float* __restrict__ vmn, const float* __restrict__ vvv)
{
    extern __shared__ char dynsmem[];
    uint32_t asb = smem_u32(dynsmem), bsb = asb + NSTG*A64_STAGE_BYTES;
    int tid = threadIdx.x, lane = tid & 31, wid = tid >> 5;
    int wm = (wid & 1) * 32, wn = (wid >> 1) * 32;
    int bx = blockIdx.x, br = blockIdx.y;
    int nt = bx & 1, mt = (bx >> 1) & 7, b = bx >> 4;

    const float* G  = (br == 0) ? qg : (br == 1) ? kg : vg;
    const float* Bt = (br == 0) ? qb : (br == 1) ? kb : vb;
    const float* M  = (br == 0) ? qm : (br == 1) ? km : vmn;
    const float* V  = (br == 0) ? qv : (br == 1) ? kvv : vvv;
    __half* outp = (br == 1) ? g_kh : g_vh;

    float scl[2][2], mean[2][2], beta[2][2];
    #pragma unroll
    for (int i = 0; i < 2; i++)
        #pragma unroll
        for (int rh = 0; rh < 2; rh++) {
            int o = mt*64 + wm + i*16 + rh*8 + (lane >> 2);
            scl[i][rh]  = G[o] / sqrtf(V[o] + 1e-5f);
            mean[i][rh] = M[o];
            beta[i][rh] = Bt[o];
        }

    float vm[2][2][4][2];
    #pragma unroll
    for (int i = 0; i < 2; i++)
        #pragma unroll
        for (int rh = 0; rh < 2; rh++)
            #pragma unroll
            for (int j = 0; j < 4; j++) { vm[i][rh][j][0] = 0.f; vm[i][rh][j][1] = 0.f; }

    for (int tp = 0; tp < 2; tp++) {
        float acc[2][2][4][4];
        #pragma unroll
        for (int t = 0; t < 2; t++)
            #pragma unroll
            for (int i = 0; i < 2; i++)
                #pragma unroll
                for (int j = 0; j < 4; j++)
                    #pragma unroll
                    for (int p = 0; p < 4; p++) acc[t][i][j][p] = 0.f;

        int t0 = tp*2, t1 = tp*2 + 1;
        int rb0 = (t0*B_ + b) * 256 + nt*128;
        int rb1 = (t1*B_ + b) * 256 + nt*128;
        gemm_pass64_t2(asb, bsb, acc, br, mt, g_xsT, rb0, rb1, tid, wm, wn, lane);

        #pragma unroll
        for (int t01 = 0; t01 < 2; t01++) {
            int t = tp*2 + t01;
            if (br == 0) {
                __syncthreads();
                __half* Sq = (__half*)dynsmem;
                #pragma unroll
                for (int i = 0; i < 2; i++) {
                    #pragma unroll
                    for (int j = 0; j < 4; j++) {
                        #pragma unroll
                        for (int rh = 0; rh < 2; rh++) {
                            float y0 = (acc[t01][i][j][rh*2+0] - mean[i][rh]) * scl[i][rh] + beta[i][rh];
                            float y1 = (acc[t01][i][j][rh*2+1] - mean[i][rh]) * scl[i][rh] + beta[i][rh];
                            float s0 = lif_step(vm[i][rh][j][0], y0, 1.0f);
                            float s1 = lif_step(vm[i][rh][j][1], y1, 1.0f);
                            int o_l = wm + i*16 + rh*8 + (lane >> 2);
                            int n_l = wn + j*8 + 2*(lane & 3);
                            Sq[n_l*72 + o_l]     = __float2half_rn(s0);
                            Sq[(n_l+1)*72 + o_l] = __float2half_rn(s1);
                        }
                    }
                }
                __syncthreads();
                #pragma unroll
                for (int r = 0; r < 2; r++) {
                    int idx = tid + r * 256;
                    int row = idx >> 3, chk = idx & 7;
                    *(uint4*)(g_qT + ((size_t)(t*B_ + b) * N_ + nt*128 + row) * C_ + mt*64 + chk*8) =
                        *(const uint4*)(&Sq[row*72 + chk*8]);
                }
                __syncthreads();
            } else {
                #pragma unroll
                for (int i = 0; i < 2; i++) {
                    #pragma unroll
                    for (int j = 0; j < 4; j++) {
                        #pragma unroll
                        for (int rh = 0; rh < 2; rh++) {
                            float y0 = (acc[t01][i][j][rh*2+0] - mean[i][rh]) * scl[i][rh] + beta[i][rh];
                            float y1 = (acc[t01][i][j][rh*2+1] - mean[i][rh]) * scl[i][rh] + beta[i][rh];
                            float s0 = lif_step(vm[i][rh][j][0], y0, 1.0f);
                            float s1 = lif_step(vm[i][rh][j][1], y1, 1.0f);
                            int o = mt*64 + wm + i*16 + rh*8 + (lane >> 2);
                            int n = nt*128 + wn + j*8 + 2*(lane & 3);
                            *(uint32_t*)(outp + ((size_t)(t*B_ + b) * C_ + o) * N_ + n) = hpair(s0, s1);
                        }
                    }
                }
            }
        }
        if (br != 0) __syncthreads();
    }
}

// ============================================================
// K3 fused: per (b,h) block: for each t, kv = 0.125*v@k^T via MMA
// (kept in smem), then a = q@kv^T via MMA, LIF(0.5), spikes -> g_sT.
// ============================================================
#define KA_AH 0
#define KA_BH (2*64*136*2)
#define KA_Q  (4*64*136*2)
#define KA_KV (KA_Q + 256*72*2)
#define KA_SMEM (KA_KV + 64*72*2)

__global__ __launch_bounds__(256, 1) void kvattn_kernel() {
    extern __shared__ char dynka[];
    uint32_t sb = smem_u32(dynka);
    uint32_t qbuf = sb + KA_Q, kvb = sb + KA_KV;
    int bh = blockIdx.x;
    int b = bh >> 3, hh = bh & 7;
    int tid = threadIdx.x, lane = tid & 31, wid = tid >> 5;

    int em = (wid & 3) * 16, dn = (wid >> 2) * 32;
    int nb = wid * 32;

    int a_row = lane & 15, a_col8 = (lane >> 4) * 8;
    int kb_row0 = dn + (lane & 7) + ((lane >> 4) << 3), kb_col = lane & 8;
    int ab_row0 = (lane & 7) + ((lane >> 4) << 3), ab_col = lane & 8;

    float vmn[2][8][4];
    #pragma unroll
    for (int i = 0; i < 2; i++)
        #pragma unroll
        for (int j = 0; j < 8; j++)
            #pragma unroll
            for (int p = 0; p < 4; p++) vmn[i][j][p] = 0.f;

    for (int t = 0; t < T_; t++) {
        int tb = t * B_ + b;
        const __half* vsrc = g_vh + ((size_t)tb * C_ + hh*64) * N_;
        const __half* ksrc = g_kh + ((size_t)tb * C_ + hh*64) * N_;

        #pragma unroll
        for (int r = 0; r < 8; r++) {
            int idx = tid + r * 256;
            int row = idx >> 3, chk = idx & 7;
            CP16(qbuf + (uint32_t)((row*72 + chk*8) * 2),
                 g_qT + ((size_t)tb * N_ + row) * C_ + hh*64 + chk*8);
        }
        #pragma unroll
        for (int r = 0; r < 2; r++) {
            int idx = tid + r * 256;
            int row = idx >> 3, chk = idx & 7;
            CP16(sb + KA_AH + (uint32_t)((row*136 + chk*8) * 2), vsrc + (size_t)row * N_ + chk*8);
            CP16(sb + KA_BH + (uint32_t)((row*136 + chk*8) * 2), ksrc + (size_t)row * N_ + chk*8);
        }
        CP_COMMIT();
        #pragma unroll
        for (int r = 0; r < 2; r++) {
            int idx = tid + r * 256;
            int row = idx >> 3, chk = idx & 7;
            CP16(sb + KA_AH + (uint32_t)(((64 + row)*136 + chk*8) * 2), vsrc + (size_t)row * N_ + 128 + chk*8);
            CP16(sb + KA_BH + (uint32_t)(((64 + row)*136 + chk*8) * 2), ksrc + (size_t)row * N_ + 128 + chk*8);
        }
        CP_COMMIT();

        float kacc[4][4];
        #pragma unroll
        for (int j = 0; j < 4; j++)
            #pragma unroll
            for (int p = 0; p < 4; p++) kacc[j][p] = 0.f;

        #pragma unroll
        for (int ch = 0; ch < 2; ch++) {
            if (ch == 0) CP_WAIT(1); else CP_WAIT(0);
            __syncthreads();
            uint32_t ahb = sb + KA_AH + ch * (64*136*2);
            uint32_t bhb = sb + KA_BH + ch * (64*136*2);
            #pragma unroll
            for (int ks = 0; ks < 8; ks++) {
                int kc = ks * 16;
                uint32_t bfr[4][2];
                #pragma unroll
                for (int jp = 0; jp < 2; jp++) {
                    uint32_t r4[4];
                    ldm_x4(r4, bhb + (uint32_t)(((kb_row0 + jp*16)*136 + kc + kb_col) * 2));
                    bfr[jp*2][0] = r4[0];   bfr[jp*2][1] = r4[1];
                    bfr[jp*2+1][0] = r4[2]; bfr[jp*2+1][1] = r4[3];
                }
                uint32_t a4[4];
                ldm_x4(a4, ahb + (uint32_t)(((em + a_row)*136 + kc + a_col8) * 2));
                #pragma unroll
                for (int j = 0; j < 4; j++)
                    mma16816(kacc[j], a4, bfr[j]);
            }
        }

        __syncthreads();
        #pragma unroll
        for (int j = 0; j < 4; j++) {
            int e0 = em + (lane >> 2);
            int d0 = dn + j*8 + 2*(lane & 3);
            *(uint32_t*)(dynka + KA_KV + ((e0)*72 + d0) * 2)     = hpair(kacc[j][0] * 0.125f, kacc[j][1] * 0.125f);
            *(uint32_t*)(dynka + KA_KV + ((e0 + 8)*72 + d0) * 2) = hpair(kacc[j][2] * 0.125f, kacc[j][3] * 0.125f);
        }
        __syncthreads();

        float acc[2][8][4];
        #pragma unroll
        for (int i = 0; i < 2; i++)
            #pragma unroll
            for (int j = 0; j < 8; j++)
                #pragma unroll
                for (int p = 0; p < 4; p++) acc[i][j][p] = 0.f;

        #pragma unroll
        for (int ks = 0; ks < 4; ks++) {
            int kc = ks * 16;
            uint32_t bfr[8][2];
            #pragma unroll
            for (int jp = 0; jp < 4; jp++) {
                uint32_t r4[4];
                ldm_x4(r4, kvb + (uint32_t)(((ab_row0 + jp*16)*72 + kc + ab_col) * 2));
                bfr[jp*2][0] = r4[0];   bfr[jp*2][1] = r4[1];
                bfr[jp*2+1][0] = r4[2]; bfr[jp*2+1][1] = r4[3];
            }
            #pragma unroll
            for (int i = 0; i < 2; i++) {
                uint32_t a4[4];
                ldm_x4(a4, qbuf + (uint32_t)(((nb + i*16 + a_row)*72 + kc + a_col8) * 2));
                #pragma unroll
                for (int j = 0; j < 8; j++)
                    mma16816(acc[i][j], a4, bfr[j]);
            }
        }

        #pragma unroll
        for (int i = 0; i < 2; i++) {
            #pragma unroll
            for (int j = 0; j < 8; j++) {
                int n0 = nb + i*16 + (lane >> 2);
                int e0 = j*8 + 2*(lane & 3);
                float s0 = lif_step(vmn[i][j][0], acc[i][j][0], 0.5f);
                float s1 = lif_step(vmn[i][j][1], acc[i][j][1], 0.5f);
                float s2 = lif_step(vmn[i][j][2], acc[i][j][2], 0.5f);
                float s3 = lif_step(vmn[i][j][3], acc[i][j][3], 0.5f);
                *(uint32_t*)(g_sT + ((size_t)tb * N_ + n0) * C_ + hh*64 + e0) = hpair(s0, s1);
                *(uint32_t*)(g_sT + ((size_t)tb * N_ + n0 + 8) * C_ + hh*64 + e0) = hpair(s2, s3);
            }
        }
        __syncthreads();
    }
}

// ============================================================
// K4: proj GEMM (M64) + bias + BN -> d_out.  grid = 2048.
// ============================================================
__global__ __launch_bounds__(256, 2) void proj_mma_kernel(
    const float* __restrict__ pbias, const float* __restrict__ pg, const float* __restrict__ pb,
    const float* __restrict__ pm, const float* __restrict__ pv, float* __restrict__ out)
{
    extern __shared__ char dynsmem[];
    uint32_t asb = smem_u32(dynsmem), bsb = asb + NSTG*A64_STAGE_BYTES;
    int tid = threadIdx.x, lane = tid & 31, wid = tid >> 5;
    int wm = (wid & 1) * 32, wn = (wid >> 1) * 32;
    int bx = blockIdx.x;
    int nt = bx & 1, mt = (bx >> 1) & 7, tb = bx >> 4;

    float scl[2][2], mean[2][2], beta[2][2], bias[2][2];
    #pragma unroll
    for (int i = 0; i < 2; i++)
        #pragma unroll
        for (int rh = 0; rh < 2; rh++) {
            int o = mt*64 + wm + i*16 + rh*8 + (lane >> 2);
            scl[i][rh]  = pg[o] / sqrtf(pv[o] + 1e-5f);
            mean[i][rh] = pm[o];
            beta[i][rh] = pb[o];
            bias[i][rh] = pbias[o];
        }

    float acc[2][4][4];
    #pragma unroll
    for (int i = 0; i < 2; i++)
        #pragma unroll
        for (int j = 0; j < 4; j++)
            #pragma unroll
            for (int p = 0; p < 4; p++) acc[i][j][p] = 0.f;

    int rowbase = tb * 256 + nt*128;
    gemm_pass64(asb, bsb, acc, 3, mt, g_sT, rowbase, tid, wm, wn, lane);

    #pragma unroll
    for (int i = 0; i < 2; i++) {
        #pragma unroll
        for (int j = 0; j < 4; j++) {
            #pragma unroll
            for (int rh = 0; rh < 2; rh++) {
                float y0 = ((acc[i][j][rh*2+0] + bias[i][rh]) - mean[i][rh]) * scl[i][rh] + beta[i][rh];
                float y1 = ((acc[i][j][rh*2+1] + bias[i][rh]) - mean[i][rh]) * scl[i][rh] + beta[i][rh];
                int o = mt*64 + wm + i*16 + rh*8 + (lane >> 2);
                int n = nt*128 + wn + j*8 + 2*(lane & 3);
                *(float2*)(out + ((size_t)tb * C_ + o) * N_ + n) = make_float2(y0, y1);
            }
        }
    }
}

// ============================================================
extern "C" void kernel_launch(void* const* d_in, const int* in_sizes, int n_in,
                              void* d_out, int out_size) {
    (void)in_sizes; (void)n_in; (void)out_size;
    const float* x  = (const float*)d_in[0];
    const float* qw = (const float*)d_in[1];
    const float* qg = (const float*)d_in[2];
    const float* qb = (const float*)d_in[3];
    const float* qm = (const float*)d_in[4];
    const float* qv = (const float*)d_in[5];
    const float* kw = (const float*)d_in[6];
    const float* kg = (const float*)d_in[7];
    const float* kb = (const float*)d_in[8];
    const float* km = (const float*)d_in[9];
    const float* kvv= (const float*)d_in[10];
    const float* vw = (const float*)d_in[11];
    const float* vg = (const float*)d_in[12];
    const float* vb = (const float*)d_in[13];
    const float* vm = (const float*)d_in[14];
    const float* vv = (const float*)d_in[15];
    const float* pw    = (const float*)d_in[16];
    const float* pbias = (const float*)d_in[17];
    const float* pg    = (const float*)d_in[18];
    const float* pb    = (const float*)d_in[19];
    const float* pm    = (const float*)d_in[20];
    const float* pv    = (const float*)d_in[21];

    cudaFuncSetAttribute(qkv_mma_kernel, cudaFuncAttributeMaxDynamicSharedMemorySize, GEMM64T2_SMEM);
    cudaFuncSetAttribute(proj_mma_kernel, cudaFuncAttributeMaxDynamicSharedMemorySize, GEMM64_SMEM);
    cudaFuncSetAttribute(kvattn_kernel, cudaFuncAttributeMaxDynamicSharedMemorySize, KA_SMEM);

    prep_kernel<<<5120, 256>>>(x, qw, kw, vw, pw);
    qkv_mma_kernel<<<dim3(512, 3), 256, GEMM64T2_SMEM>>>(qg, qb, qm, qv, kg, kb, km, kvv, vg, vb, vm, vv);
    kvattn_kernel<<<256, 256, KA_SMEM>>>();
    proj_mma_kernel<<<2048, 256, GEMM64_SMEM>>>(pbias, pg, pb, pm, pv, (float*)d_out);
}

// round 13
// speedup vs baseline: 3.0017x; 1.0087x over previous
#include <cuda_runtime.h>
#include <cuda_fp16.h>
#include <cstdint>

#define T_ 4
#define B_ 32
#define C_ 512
#define N_ 256
#define H_ 8
#define D_ 64
#define BCN_ (B_*C_*N_)
#define TBCN_ (T_*BCN_)

// ---- scratch ----
__device__ __half g_kh[TBCN_];         // [tb][c][n] fp16 spikes
__device__ __half g_vh[TBCN_];
__device__ __half g_qT[TBCN_];         // [tb][n][c] fp16 spikes
__device__ __half g_xsT[TBCN_];        // [t][b][n][c] spikes fp16 (K-major)
__device__ __half g_sT[TBCN_];         // [tb][n][c] attn spikes fp16
__device__ __half g_wl[4*2*C_*C_];     // [mat][limb][o][c] fp16 weight limbs

// ================= helpers =================
__device__ __forceinline__ uint32_t smem_u32(const void* p) {
    uint32_t a;
    asm("{ .reg .u64 t; cvta.to.shared.u64 t, %1; cvt.u32.u64 %0, t; }" : "=r"(a) : "l"(p));
    return a;
}

#define CP16(dst, src) \
    asm volatile("cp.async.cg.shared.global [%0], [%1], 16;" :: "r"(dst), "l"(src))
#define CP_COMMIT() asm volatile("cp.async.commit_group;" ::: "memory")
#define CP_WAIT(n)  asm volatile("cp.async.wait_group %0;" :: "n"(n) : "memory")

__device__ __forceinline__ void ldm_x4(uint32_t r[4], uint32_t addr) {
    asm volatile("ldmatrix.sync.aligned.m8n8.x4.shared.b16 {%0,%1,%2,%3}, [%4];"
        : "=r"(r[0]), "=r"(r[1]), "=r"(r[2]), "=r"(r[3]) : "r"(addr));
}
__device__ __forceinline__ void mma16816(float c[4], const uint32_t a[4], const uint32_t* b) {
    asm volatile("mma.sync.aligned.m16n8k16.row.col.f32.f16.f16.f32 "
        "{%0,%1,%2,%3}, {%4,%5,%6,%7}, {%8,%9}, {%0,%1,%2,%3};"
        : "+f"(c[0]), "+f"(c[1]), "+f"(c[2]), "+f"(c[3])
        : "r"(a[0]), "r"(a[1]), "r"(a[2]), "r"(a[3]), "r"(b[0]), "r"(b[1]));
}

__device__ __forceinline__ float lif_step(float& v, float x, float vth) {
    v += (x - v) * 0.5f;
    float s = (v >= vth) ? 1.0f : 0.0f;
    if (s != 0.0f) v = 0.0f;
    return s;
}
__device__ __forceinline__ uint32_t hpair(float lo, float hi) {
    return (uint32_t)__half_as_ushort(__float2half_rn(lo)) |
           ((uint32_t)__half_as_ushort(__float2half_rn(hi)) << 16);
}

// ============================================================
// K0+K1 merged prep: blocks [0,4096) = weight limb split,
// blocks [4096,5120) = LIF(x) -> fp16 spikes [t][b][n][c].
// ============================================================
__global__ __launch_bounds__(256) void prep_kernel(
    const float* __restrict__ x,
    const float* __restrict__ qw, const float* __restrict__ kw,
    const float* __restrict__ vw, const float* __restrict__ pw)
{
    __shared__ __half Sb[64][72];
    if (blockIdx.x < 4096) {
        int i = blockIdx.x * 256 + threadIdx.x;
        int mat = i >> 18, idx = i & 262143;
        const float* W = (mat == 0) ? qw : (mat == 1) ? kw : (mat == 2) ? vw : pw;
        float w = W[idx];
        __half h1 = __float2half_rn(w);
        float r1 = w - __half2float(h1);
        __half h2 = __float2half_rn(r1);
        size_t base = (size_t)(mat * 2) * 262144 + idx;
        g_wl[base] = h1;
        g_wl[base + 262144] = h2;
        return;
    }
    int bx = blockIdx.x - 4096;
    int ch = bx & 7, nt = (bx >> 3) & 3, b = bx >> 5;
    int tid = threadIdx.x;
    int c_l = tid >> 2, ng = tid & 3;
    int n_o = tid >> 2, u0 = tid & 3;
    float vm[16];
    #pragma unroll
    for (int j = 0; j < 16; j++) vm[j] = 0.f;

    for (int t = 0; t < T_; t++) {
        const float* xp = x + (((size_t)(t * B_ + b)) * C_ + ch * 64 + c_l) * N_ + nt * 64 + ng * 16;
        #pragma unroll
        for (int q = 0; q < 4; q++) {
            float4 xv = *(const float4*)(xp + q * 4);
            Sb[c_l][ng*16 + q*4 + 0] = __float2half_rn(lif_step(vm[q*4+0], xv.x, 1.0f));
            Sb[c_l][ng*16 + q*4 + 1] = __float2half_rn(lif_step(vm[q*4+1], xv.y, 1.0f));
            Sb[c_l][ng*16 + q*4 + 2] = __float2half_rn(lif_step(vm[q*4+2], xv.z, 1.0f));
            Sb[c_l][ng*16 + q*4 + 3] = __float2half_rn(lif_step(vm[q*4+3], xv.w, 1.0f));
        }
        __syncthreads();
        char* outb = (char*)(g_xsT + ((size_t)(t*B_ + b) * N_ + nt*64 + n_o) * C_ + ch*64);
        #pragma unroll
        for (int hf = 0; hf < 2; hf++) {
            int u = u0 + hf * 4;
            uint32_t rp[4];
            #pragma unroll
            for (int p = 0; p < 4; p++) {
                float lo = __half2float(Sb[u*8 + p*2][n_o]);
                float hi = __half2float(Sb[u*8 + p*2 + 1][n_o]);
                rp[p] = hpair(lo, hi);
            }
            *(uint4*)(outb + u*16) = make_uint4(rp[0], rp[1], rp[2], rp[3]);
        }
        __syncthreads();
    }
}

// ============================================================
// M64 GEMM machinery: 64x128 block, 8 warps (2m x 4n), warp 32x32.
// Single-t variant (proj) and t-paired variant (qkv).
// ============================================================
#define B_STAGE_BYTES (128*24*2)
#define B2_STAGE_BYTES (256*24*2)
#define A64_STAGE_BYTES (2*64*24*2)
#define NSTG 4
#define GEMM64_SMEM   (NSTG*A64_STAGE_BYTES + NSTG*B_STAGE_BYTES)
#define GEMM64T2_SMEM (NSTG*A64_STAGE_BYTES + NSTG*B2_STAGE_BYTES)

__device__ __forceinline__ void load_stage_B(uint32_t bsb, int s, int kc,
                                             const __half* srcT, int rowbase, int tid) {
    int n = tid >> 1, h = tid & 1;
    const __half* src = srcT + ((size_t)(rowbase + n)) * 512 + kc + h*8;
    uint32_t dst = bsb + (uint32_t)(((s*128 + n)*24 + h*8) * 2);
    CP16(dst, src);
}
__device__ __forceinline__ void load_stage_B2(uint32_t bsb, int s, int kc,
                                              const __half* srcT, int rb0, int rb1, int tid) {
    int n = tid >> 1, h = tid & 1;
    CP16(bsb + (uint32_t)(((s*256 + n)*24 + h*8) * 2),
         srcT + ((size_t)(rb0 + n)) * 512 + kc + h*8);
    CP16(bsb + (uint32_t)(((s*256 + 128 + n)*24 + h*8) * 2),
         srcT + ((size_t)(rb1 + n)) * 512 + kc + h*8);
}
__device__ __forceinline__ void load_stage_A64(uint32_t asb, int s, int kc, int wmat, int mt, int tid) {
    int l = tid >> 7, rem = tid & 127;
    int o = rem >> 1, h = rem & 1;
    const __half* src = g_wl + ((size_t)(wmat*2 + l) * 512 + mt*64 + o) * 512 + kc + h*8;
    uint32_t dst = asb + (uint32_t)((((s*2 + l)*64 + o)*24 + h*8) * 2);
    CP16(dst, src);
}

// single-t pass (proj)
__device__ __forceinline__ void gemm_pass64(uint32_t asb, uint32_t bsb, float acc[2][4][4],
                                            int wmat, int mt, const __half* srcT, int rowbase,
                                            int tid, int wm, int wn, int lane) {
    #pragma unroll
    for (int p = 0; p < 3; p++) {
        load_stage_A64(asb, p, p*16, wmat, mt, tid);
        load_stage_B(bsb, p, p*16, srcT, rowbase, tid);
        CP_COMMIT();
    }
    int a_row = lane & 15, a_col = (lane >> 4) * 8;
    int b_row = wn + (lane & 7) + ((lane >> 4) << 3), b_col = lane & 8;

    int s = 0;
    for (int c = 0; c < 32; c++) {
        CP_WAIT(2);
        __syncthreads();
        if (c + 3 < 32) {
            int ns = s + 3; if (ns >= NSTG) ns -= NSTG;
            load_stage_A64(asb, ns, (c+3)*16, wmat, mt, tid);
            load_stage_B(bsb, ns, (c+3)*16, srcT, rowbase, tid);
        }
        CP_COMMIT();

        uint32_t bfr[4][2];
        #pragma unroll
        for (int jp = 0; jp < 2; jp++) {
            uint32_t r4[4];
            ldm_x4(r4, bsb + (uint32_t)((((s*128) + b_row + jp*16)*24 + b_col) * 2));
            bfr[jp*2][0] = r4[0];   bfr[jp*2][1] = r4[1];
            bfr[jp*2+1][0] = r4[2]; bfr[jp*2+1][1] = r4[3];
        }
        #pragma unroll
        for (int l = 0; l < 2; l++) {
            #pragma unroll
            for (int i = 0; i < 2; i++) {
                uint32_t a4[4];
                ldm_x4(a4, asb + (uint32_t)(((((s*2 + l)*64) + wm + i*16 + a_row)*24 + a_col) * 2));
                #pragma unroll
                for (int j = 0; j < 4; j++)
                    mma16816(acc[i][j], a4, bfr[j]);
            }
        }
        if (++s >= NSTG) s = 0;
    }
}

// t-paired pass (qkv): acc[t][i][j][4], A frags reused for both t.
__device__ __forceinline__ void gemm_pass64_t2(uint32_t asb, uint32_t bsb, float acc[2][2][4][4],
                                               int wmat, int mt, const __half* srcT,
                                               int rb0, int rb1,
                                               int tid, int wm, int wn, int lane) {
    #pragma unroll
    for (int p = 0; p < 3; p++) {
        load_stage_A64(asb, p, p*16, wmat, mt, tid);
        load_stage_B2(bsb, p, p*16, srcT, rb0, rb1, tid);
        CP_COMMIT();
    }
    int a_row = lane & 15, a_col = (lane >> 4) * 8;
    int b_row = wn + (lane & 7) + ((lane >> 4) << 3), b_col = lane & 8;

    int s = 0;
    for (int c = 0; c < 32; c++) {
        CP_WAIT(2);
        __syncthreads();
        if (c + 3 < 32) {
            int ns = s + 3; if (ns >= NSTG) ns -= NSTG;
            load_stage_A64(asb, ns, (c+3)*16, wmat, mt, tid);
            load_stage_B2(bsb, ns, (c+3)*16, srcT, rb0, rb1, tid);
        }
        CP_COMMIT();

        uint32_t bfr[2][4][2];
        #pragma unroll
        for (int t = 0; t < 2; t++) {
            #pragma unroll
            for (int jp = 0; jp < 2; jp++) {
                uint32_t r4[4];
                ldm_x4(r4, bsb + (uint32_t)((((s*256 + t*128) + b_row + jp*16)*24 + b_col) * 2));
                bfr[t][jp*2][0] = r4[0];   bfr[t][jp*2][1] = r4[1];
                bfr[t][jp*2+1][0] = r4[2]; bfr[t][jp*2+1][1] = r4[3];
            }
        }
        #pragma unroll
        for (int l = 0; l < 2; l++) {
            #pragma unroll
            for (int i = 0; i < 2; i++) {
                uint32_t a4[4];
                ldm_x4(a4, asb + (uint32_t)(((((s*2 + l)*64) + wm + i*16 + a_row)*24 + a_col) * 2));
                #pragma unroll
                for (int t = 0; t < 2; t++)
                    #pragma unroll
                    for (int j = 0; j < 4; j++)
                        mma16816(acc[t][i][j], a4, bfr[t][j]);
            }
        }
        if (++s >= NSTG) s = 0;
    }
}

// ============================================================
// K2: qkv GEMM (M64, t-paired) + BN + LIF.  q writes g_qT [n][c],
// k/v write [c][n]; ALL branches stage tiles in smem for coalesced
// uint4 stores.  grid.x=512, grid.y=3.
// ============================================================
__global__ __launch_bounds__(256, 2) void qkv_mma_kernel(
    const float* __restrict__ qg, const float* __restrict__ qb, const float* __restrict__ qm, const float* __restrict__ qv,
    const float* __restrict__ kg, const float* __restrict__ kb, const float* __restrict__ km, const float* __restrict__ kvv,
    const float* __restrict__ vg, const float* __restrict__ vb, const float* __restrict__ vmn, const float* __restrict__ vvv)
{
    extern __shared__ char dynsmem[];
    uint32_t asb = smem_u32(dynsmem), bsb = asb + NSTG*A64_STAGE_BYTES;
    int tid = threadIdx.x, lane = tid & 31, wid = tid >> 5;
    int wm = (wid & 1) * 32, wn = (wid >> 1) * 32;
    int bx = blockIdx.x, br = blockIdx.y;
    int nt = bx & 1, mt = (bx >> 1) & 7, b = bx >> 4;

    const float* G  = (br == 0) ? qg : (br == 1) ? kg : vg;
    const float* Bt = (br == 0) ? qb : (br == 1) ? kb : vb;
    const float* M  = (br == 0) ? qm : (br == 1) ? km : vmn;
    const float* V  = (br == 0) ? qv : (br == 1) ? kvv : vvv;
    __half* outp = (br == 1) ? g_kh : g_vh;

    float scl[2][2], mean[2][2], beta[2][2];
    #pragma unroll
    for (int i = 0; i < 2; i++)
        #pragma unroll
        for (int rh = 0; rh < 2; rh++) {
            int o = mt*64 + wm + i*16 + rh*8 + (lane >> 2);
            scl[i][rh]  = G[o] / sqrtf(V[o] + 1e-5f);
            mean[i][rh] = M[o];
            beta[i][rh] = Bt[o];
        }

    float vm[2][2][4][2];
    #pragma unroll
    for (int i = 0; i < 2; i++)
        #pragma unroll
        for (int rh = 0; rh < 2; rh++)
            #pragma unroll
            for (int j = 0; j < 4; j++) { vm[i][rh][j][0] = 0.f; vm[i][rh][j][1] = 0.f; }

    for (int tp = 0; tp < 2; tp++) {
        float acc[2][2][4][4];
        #pragma unroll
        for (int t = 0; t < 2; t++)
            #pragma unroll
            for (int i = 0; i < 2; i++)
                #pragma unroll
                for (int j = 0; j < 4; j++)
                    #pragma unroll
                    for (int p = 0; p < 4; p++) acc[t][i][j][p] = 0.f;

        int t0 = tp*2, t1 = tp*2 + 1;
        int rb0 = (t0*B_ + b) * 256 + nt*128;
        int rb1 = (t1*B_ + b) * 256 + nt*128;
        gemm_pass64_t2(asb, bsb, acc, br, mt, g_xsT, rb0, rb1, tid, wm, wn, lane);

        #pragma unroll
        for (int t01 = 0; t01 < 2; t01++) {
            int t = tp*2 + t01;
            if (br == 0) {
                __syncthreads();
                __half* Sq = (__half*)dynsmem;   // [n 128][o 64] stride 72
                #pragma unroll
                for (int i = 0; i < 2; i++) {
                    #pragma unroll
                    for (int j = 0; j < 4; j++) {
                        #pragma unroll
                        for (int rh = 0; rh < 2; rh++) {
                            float y0 = (acc[t01][i][j][rh*2+0] - mean[i][rh]) * scl[i][rh] + beta[i][rh];
                            float y1 = (acc[t01][i][j][rh*2+1] - mean[i][rh]) * scl[i][rh] + beta[i][rh];
                            float s0 = lif_step(vm[i][rh][j][0], y0, 1.0f);
                            float s1 = lif_step(vm[i][rh][j][1], y1, 1.0f);
                            int o_l = wm + i*16 + rh*8 + (lane >> 2);
                            int n_l = wn + j*8 + 2*(lane & 3);
                            Sq[n_l*72 + o_l]     = __float2half_rn(s0);
                            Sq[(n_l+1)*72 + o_l] = __float2half_rn(s1);
                        }
                    }
                }
                __syncthreads();
                #pragma unroll
                for (int r = 0; r < 2; r++) {
                    int idx = tid + r * 256;
                    int row = idx >> 3, chk = idx & 7;
                    *(uint4*)(g_qT + ((size_t)(t*B_ + b) * N_ + nt*128 + row) * C_ + mt*64 + chk*8) =
                        *(const uint4*)(&Sq[row*72 + chk*8]);
                }
                __syncthreads();
            } else {
                __syncthreads();
                __half* Sk = (__half*)dynsmem;   // [o 64][n 128] stride 136
                #pragma unroll
                for (int i = 0; i < 2; i++) {
                    #pragma unroll
                    for (int j = 0; j < 4; j++) {
                        #pragma unroll
                        for (int rh = 0; rh < 2; rh++) {
                            float y0 = (acc[t01][i][j][rh*2+0] - mean[i][rh]) * scl[i][rh] + beta[i][rh];
                            float y1 = (acc[t01][i][j][rh*2+1] - mean[i][rh]) * scl[i][rh] + beta[i][rh];
                            float s0 = lif_step(vm[i][rh][j][0], y0, 1.0f);
                            float s1 = lif_step(vm[i][rh][j][1], y1, 1.0f);
                            int o_l = wm + i*16 + rh*8 + (lane >> 2);
                            int n_l = wn + j*8 + 2*(lane & 3);
                            *(uint32_t*)(&Sk[o_l*136 + n_l]) = hpair(s0, s1);
                        }
                    }
                }
                __syncthreads();
                #pragma unroll
                for (int r = 0; r < 4; r++) {
                    int idx = tid + r * 256;           // 1024 uint4: 64 rows x 16 chunks
                    int row = idx >> 4, chk = idx & 15;
                    *(uint4*)(outp + ((size_t)(t*B_ + b) * C_ + mt*64 + row) * N_ + nt*128 + chk*8) =
                        *(const uint4*)(&Sk[row*136 + chk*8]);
                }
                __syncthreads();
            }
        }
    }
}

// ============================================================
// K3 fused: per (b,h) block: for each t, kv = 0.125*v@k^T via MMA
// (kept in smem), then a = q@kv^T via MMA, LIF(0.5), spikes -> g_sT.
// ============================================================
#define KA_AH 0
#define KA_BH (2*64*136*2)
#define KA_Q  (4*64*136*2)
#define KA_KV (KA_Q + 256*72*2)
#define KA_SMEM (KA_KV + 64*72*2)

__global__ __launch_bounds__(256, 1) void kvattn_kernel() {
    extern __shared__ char dynka[];
    uint32_t sb = smem_u32(dynka);
    uint32_t qbuf = sb + KA_Q, kvb = sb + KA_KV;
    int bh = blockIdx.x;
    int b = bh >> 3, hh = bh & 7;
    int tid = threadIdx.x, lane = tid & 31, wid = tid >> 5;

    int em = (wid & 3) * 16, dn = (wid >> 2) * 32;
    int nb = wid * 32;

    int a_row = lane & 15, a_col8 = (lane >> 4) * 8;
    int kb_row0 = dn + (lane & 7) + ((lane >> 4) << 3), kb_col = lane & 8;
    int ab_row0 = (lane & 7) + ((lane >> 4) << 3), ab_col = lane & 8;

    float vmn[2][8][4];
    #pragma unroll
    for (int i = 0; i < 2; i++)
        #pragma unroll
        for (int j = 0; j < 8; j++)
            #pragma unroll
            for (int p = 0; p < 4; p++) vmn[i][j][p] = 0.f;

    for (int t = 0; t < T_; t++) {
        int tb = t * B_ + b;
        const __half* vsrc = g_vh + ((size_t)tb * C_ + hh*64) * N_;
        const __half* ksrc = g_kh + ((size_t)tb * C_ + hh*64) * N_;

        #pragma unroll
        for (int r = 0; r < 8; r++) {
            int idx = tid + r * 256;
            int row = idx >> 3, chk = idx & 7;
            CP16(qbuf + (uint32_t)((row*72 + chk*8) * 2),
                 g_qT + ((size_t)tb * N_ + row) * C_ + hh*64 + chk*8);
        }
        #pragma unroll
        for (int r = 0; r < 2; r++) {
            int idx = tid + r * 256;
            int row = idx >> 3, chk = idx & 7;
            CP16(sb + KA_AH + (uint32_t)((row*136 + chk*8) * 2), vsrc + (size_t)row * N_ + chk*8);
            CP16(sb + KA_BH + (uint32_t)((row*136 + chk*8) * 2), ksrc + (size_t)row * N_ + chk*8);
        }
        CP_COMMIT();
        #pragma unroll
        for (int r = 0; r < 2; r++) {
            int idx = tid + r * 256;
            int row = idx >> 3, chk = idx & 7;
            CP16(sb + KA_AH + (uint32_t)(((64 + row)*136 + chk*8) * 2), vsrc + (size_t)row * N_ + 128 + chk*8);
            CP16(sb + KA_BH + (uint32_t)(((64 + row)*136 + chk*8) * 2), ksrc + (size_t)row * N_ + 128 + chk*8);
        }
        CP_COMMIT();

        float kacc[4][4];
        #pragma unroll
        for (int j = 0; j < 4; j++)
            #pragma unroll
            for (int p = 0; p < 4; p++) kacc[j][p] = 0.f;

        #pragma unroll
        for (int ch = 0; ch < 2; ch++) {
            if (ch == 0) CP_WAIT(1); else CP_WAIT(0);
            __syncthreads();
            uint32_t ahb = sb + KA_AH + ch * (64*136*2);
            uint32_t bhb = sb + KA_BH + ch * (64*136*2);
            #pragma unroll
            for (int ks = 0; ks < 8; ks++) {
                int kc = ks * 16;
                uint32_t bfr[4][2];
                #pragma unroll
                for (int jp = 0; jp < 2; jp++) {
                    uint32_t r4[4];
                    ldm_x4(r4, bhb + (uint32_t)(((kb_row0 + jp*16)*136 + kc + kb_col) * 2));
                    bfr[jp*2][0] = r4[0];   bfr[jp*2][1] = r4[1];
                    bfr[jp*2+1][0] = r4[2]; bfr[jp*2+1][1] = r4[3];
                }
                uint32_t a4[4];
                ldm_x4(a4, ahb + (uint32_t)(((em + a_row)*136 + kc + a_col8) * 2));
                #pragma unroll
                for (int j = 0; j < 4; j++)
                    mma16816(kacc[j], a4, bfr[j]);
            }
        }

        __syncthreads();
        #pragma unroll
        for (int j = 0; j < 4; j++) {
            int e0 = em + (lane >> 2);
            int d0 = dn + j*8 + 2*(lane & 3);
            *(uint32_t*)(dynka + KA_KV + ((e0)*72 + d0) * 2)     = hpair(kacc[j][0] * 0.125f, kacc[j][1] * 0.125f);
            *(uint32_t*)(dynka + KA_KV + ((e0 + 8)*72 + d0) * 2) = hpair(kacc[j][2] * 0.125f, kacc[j][3] * 0.125f);
        }
        __syncthreads();

        float acc[2][8][4];
        #pragma unroll
        for (int i = 0; i < 2; i++)
            #pragma unroll
            for (int j = 0; j < 8; j++)
                #pragma unroll
                for (int p = 0; p < 4; p++) acc[i][j][p] = 0.f;

        #pragma unroll
        for (int ks = 0; ks < 4; ks++) {
            int kc = ks * 16;
            uint32_t bfr[8][2];
            #pragma unroll
            for (int jp = 0; jp < 4; jp++) {
                uint32_t r4[4];
                ldm_x4(r4, kvb + (uint32_t)(((ab_row0 + jp*16)*72 + kc + ab_col) * 2));
                bfr[jp*2][0] = r4[0];   bfr[jp*2][1] = r4[1];
                bfr[jp*2+1][0] = r4[2]; bfr[jp*2+1][1] = r4[3];
            }
            #pragma unroll
            for (int i = 0; i < 2; i++) {
                uint32_t a4[4];
                ldm_x4(a4, qbuf + (uint32_t)(((nb + i*16 + a_row)*72 + kc + a_col8) * 2));
                #pragma unroll
                for (int j = 0; j < 8; j++)
                    mma16816(acc[i][j], a4, bfr[j]);
            }
        }

        #pragma unroll
        for (int i = 0; i < 2; i++) {
            #pragma unroll
            for (int j = 0; j < 8; j++) {
                int n0 = nb + i*16 + (lane >> 2);
                int e0 = j*8 + 2*(lane & 3);
                float s0 = lif_step(vmn[i][j][0], acc[i][j][0], 0.5f);
                float s1 = lif_step(vmn[i][j][1], acc[i][j][1], 0.5f);
                float s2 = lif_step(vmn[i][j][2], acc[i][j][2], 0.5f);
                float s3 = lif_step(vmn[i][j][3], acc[i][j][3], 0.5f);
                *(uint32_t*)(g_sT + ((size_t)tb * N_ + n0) * C_ + hh*64 + e0) = hpair(s0, s1);
                *(uint32_t*)(g_sT + ((size_t)tb * N_ + n0 + 8) * C_ + hh*64 + e0) = hpair(s2, s3);
            }
        }
        __syncthreads();
    }
}

// ============================================================
// K4: proj GEMM (M64) + bias + BN -> d_out.  grid = 2048.
// ============================================================
__global__ __launch_bounds__(256, 2) void proj_mma_kernel(
    const float* __restrict__ pbias, const float* __restrict__ pg, const float* __restrict__ pb,
    const float* __restrict__ pm, const float* __restrict__ pv, float* __restrict__ out)
{
    extern __shared__ char dynsmem[];
    uint32_t asb = smem_u32(dynsmem), bsb = asb + NSTG*A64_STAGE_BYTES;
    int tid = threadIdx.x, lane = tid & 31, wid = tid >> 5;
    int wm = (wid & 1) * 32, wn = (wid >> 1) * 32;
    int bx = blockIdx.x;
    int nt = bx & 1, mt = (bx >> 1) & 7, tb = bx >> 4;

    float scl[2][2], mean[2][2], beta[2][2], bias[2][2];
    #pragma unroll
    for (int i = 0; i < 2; i++)
        #pragma unroll
        for (int rh = 0; rh < 2; rh++) {
            int o = mt*64 + wm + i*16 + rh*8 + (lane >> 2);
            scl[i][rh]  = pg[o] / sqrtf(pv[o] + 1e-5f);
            mean[i][rh] = pm[o];
            beta[i][rh] = pb[o];
            bias[i][rh] = pbias[o];
        }

    float acc[2][4][4];
    #pragma unroll
    for (int i = 0; i < 2; i++)
        #pragma unroll
        for (int j = 0; j < 4; j++)
            #pragma unroll
            for (int p = 0; p < 4; p++) acc[i][j][p] = 0.f;

    int rowbase = tb * 256 + nt*128;
    gemm_pass64(asb, bsb, acc, 3, mt, g_sT, rowbase, tid, wm, wn, lane);

    #pragma unroll
    for (int i = 0; i < 2; i++) {
        #pragma unroll
        for (int j = 0; j < 4; j++) {
            #pragma unroll
            for (int rh = 0; rh < 2; rh++) {
                float y0 = ((acc[i][j][rh*2+0] + bias[i][rh]) - mean[i][rh]) * scl[i][rh] + beta[i][rh];
                float y1 = ((acc[i][j][rh*2+1] + bias[i][rh]) - mean[i][rh]) * scl[i][rh] + beta[i][rh];
                int o = mt*64 + wm + i*16 + rh*8 + (lane >> 2);
                int n = nt*128 + wn + j*8 + 2*(lane & 3);
                *(float2*)(out + ((size_t)tb * C_ + o) * N_ + n) = make_float2(y0, y1);
            }
        }
    }
}

// ============================================================
extern "C" void kernel_launch(void* const* d_in, const int* in_sizes, int n_in,
                              void* d_out, int out_size) {
    (void)in_sizes; (void)n_in; (void)out_size;
    const float* x  = (const float*)d_in[0];
    const float* qw = (const float*)d_in[1];
    const float* qg = (const float*)d_in[2];
    const float* qb = (const float*)d_in[3];
    const float* qm = (const float*)d_in[4];
    const float* qv = (const float*)d_in[5];
    const float* kw = (const float*)d_in[6];
    const float* kg = (const float*)d_in[7];
    const float* kb = (const float*)d_in[8];
    const float* km = (const float*)d_in[9];
    const float* kvv= (const float*)d_in[10];
    const float* vw = (const float*)d_in[11];
    const float* vg = (const float*)d_in[12];
    const float* vb = (const float*)d_in[13];
    const float* vm = (const float*)d_in[14];
    const float* vv = (const float*)d_in[15];
    const float* pw    = (const float*)d_in[16];
    const float* pbias = (const float*)d_in[17];
    const float* pg    = (const float*)d_in[18];
    const float* pb    = (const float*)d_in[19];
    const float* pm    = (const float*)d_in[20];
    const float* pv    = (const float*)d_in[21];

    cudaFuncSetAttribute(qkv_mma_kernel, cudaFuncAttributeMaxDynamicSharedMemorySize, GEMM64T2_SMEM);
    cudaFuncSetAttribute(proj_mma_kernel, cudaFuncAttributeMaxDynamicSharedMemorySize, GEMM64_SMEM);
    cudaFuncSetAttribute(kvattn_kernel, cudaFuncAttributeMaxDynamicSharedMemorySize, KA_SMEM);

    prep_kernel<<<5120, 256>>>(x, qw, kw, vw, pw);
    qkv_mma_kernel<<<dim3(512, 3), 256, GEMM64T2_SMEM>>>(qg, qb, qm, qv, kg, kb, km, kvv, vg, vb, vm, vv);
    kvattn_kernel<<<256, 256, KA_SMEM>>>();
    proj_mma_kernel<<<2048, 256, GEMM64_SMEM>>>(pbias, pg, pb, pm, pv, (float*)d_out);
}

// round 15
// speedup vs baseline: 3.0218x; 1.0067x over previous
#include <cuda_runtime.h>
#include <cuda_fp16.h>
#include <cstdint>

#define T_ 4
#define B_ 32
#define C_ 512
#define N_ 256
#define H_ 8
#define D_ 64
#define BCN_ (B_*C_*N_)
#define TBCN_ (T_*BCN_)

// ---- scratch ----
__device__ __half g_kh[TBCN_];         // [tb][c][n] fp16 spikes
__device__ __half g_vh[TBCN_];
__device__ __half g_qT[TBCN_];         // [tb][n][c] fp16 spikes
__device__ __half g_xsT[TBCN_];        // [t][b][n][c] spikes fp16 (K-major)
__device__ __half g_sT[TBCN_];         // [tb][n][c] attn spikes fp16
__device__ __half g_wl[4*2*C_*C_];     // [mat][limb][o][c] fp16 weight limbs

// ================= helpers =================
__device__ __forceinline__ uint32_t smem_u32(const void* p) {
    uint32_t a;
    asm("{ .reg .u64 t; cvta.to.shared.u64 t, %1; cvt.u32.u64 %0, t; }" : "=r"(a) : "l"(p));
    return a;
}

#define CP16(dst, src) \
    asm volatile("cp.async.cg.shared.global [%0], [%1], 16;" :: "r"(dst), "l"(src))
#define CP_COMMIT() asm volatile("cp.async.commit_group;" ::: "memory")
#define CP_WAIT(n)  asm volatile("cp.async.wait_group %0;" :: "n"(n) : "memory")

__device__ __forceinline__ void ldm_x4(uint32_t r[4], uint32_t addr) {
    asm volatile("ldmatrix.sync.aligned.m8n8.x4.shared.b16 {%0,%1,%2,%3}, [%4];"
        : "=r"(r[0]), "=r"(r[1]), "=r"(r[2]), "=r"(r[3]) : "r"(addr));
}
__device__ __forceinline__ void mma16816(float c[4], const uint32_t a[4], const uint32_t* b) {
    asm volatile("mma.sync.aligned.m16n8k16.row.col.f32.f16.f16.f32 "
        "{%0,%1,%2,%3}, {%4,%5,%6,%7}, {%8,%9}, {%0,%1,%2,%3};"
        : "+f"(c[0]), "+f"(c[1]), "+f"(c[2]), "+f"(c[3])
        : "r"(a[0]), "r"(a[1]), "r"(a[2]), "r"(a[3]), "r"(b[0]), "r"(b[1]));
}

__device__ __forceinline__ float lif_step(float& v, float x, float vth) {
    v += (x - v) * 0.5f;
    float s = (v >= vth) ? 1.0f : 0.0f;
    if (s != 0.0f) v = 0.0f;
    return s;
}
__device__ __forceinline__ uint32_t hpair(float lo, float hi) {
    return (uint32_t)__half_as_ushort(__float2half_rn(lo)) |
           ((uint32_t)__half_as_ushort(__float2half_rn(hi)) << 16);
}
__device__ __forceinline__ uint32_t hpack(__half lo, __half hi) {
    return (uint32_t)__half_as_ushort(lo) | ((uint32_t)__half_as_ushort(hi) << 16);
}

// ============================================================
// K0+K1 merged prep: blocks [0,1024) = weight limb split (x4 vec),
// blocks [1024,2048) = LIF(x) -> fp16 spikes [t][b][n][c].
// ============================================================
__global__ __launch_bounds__(256) void prep_kernel(
    const float* __restrict__ x,
    const float* __restrict__ qw, const float* __restrict__ kw,
    const float* __restrict__ vw, const float* __restrict__ pw)
{
    __shared__ __half Sb[64][72];
    if (blockIdx.x < 1024) {
        int i = blockIdx.x * 256 + threadIdx.x;      // 0..262143: float4 groups
        int mat = i >> 16, g = i & 65535;
        int idx = g * 4;
        const float* W = (mat == 0) ? qw : (mat == 1) ? kw : (mat == 2) ? vw : pw;
        float4 w4 = *(const float4*)(W + idx);
        float w[4] = {w4.x, w4.y, w4.z, w4.w};
        __half h1[4], h2[4];
        #pragma unroll
        for (int p = 0; p < 4; p++) {
            h1[p] = __float2half_rn(w[p]);
            float r1 = w[p] - __half2float(h1[p]);
            h2[p] = __float2half_rn(r1);
        }
        size_t base = (size_t)(mat * 2) * 262144 + idx;
        *(uint2*)(g_wl + base)          = make_uint2(hpack(h1[0], h1[1]), hpack(h1[2], h1[3]));
        *(uint2*)(g_wl + base + 262144) = make_uint2(hpack(h2[0], h2[1]), hpack(h2[2], h2[3]));
        return;
    }
    int bx = blockIdx.x - 1024;
    int ch = bx & 7, nt = (bx >> 3) & 3, b = bx >> 5;
    int tid = threadIdx.x;
    int c_l = tid >> 2, ng = tid & 3;
    int n_o = tid >> 2, u0 = tid & 3;
    float vm[16];
    #pragma unroll
    for (int j = 0; j < 16; j++) vm[j] = 0.f;

    for (int t = 0; t < T_; t++) {
        const float* xp = x + (((size_t)(t * B_ + b)) * C_ + ch * 64 + c_l) * N_ + nt * 64 + ng * 16;
        #pragma unroll
        for (int q = 0; q < 4; q++) {
            float4 xv = *(const float4*)(xp + q * 4);
            Sb[c_l][ng*16 + q*4 + 0] = __float2half_rn(lif_step(vm[q*4+0], xv.x, 1.0f));
            Sb[c_l][ng*16 + q*4 + 1] = __float2half_rn(lif_step(vm[q*4+1], xv.y, 1.0f));
            Sb[c_l][ng*16 + q*4 + 2] = __float2half_rn(lif_step(vm[q*4+2], xv.z, 1.0f));
            Sb[c_l][ng*16 + q*4 + 3] = __float2half_rn(lif_step(vm[q*4+3], xv.w, 1.0f));
        }
        __syncthreads();
        char* outb = (char*)(g_xsT + ((size_t)(t*B_ + b) * N_ + nt*64 + n_o) * C_ + ch*64);
        #pragma unroll
        for (int hf = 0; hf < 2; hf++) {
            int u = u0 + hf * 4;
            uint32_t rp[4];
            #pragma unroll
            for (int p = 0; p < 4; p++) {
                float lo = __half2float(Sb[u*8 + p*2][n_o]);
                float hi = __half2float(Sb[u*8 + p*2 + 1][n_o]);
                rp[p] = hpair(lo, hi);
            }
            *(uint4*)(outb + u*16) = make_uint4(rp[0], rp[1], rp[2], rp[3]);
        }
        __syncthreads();
    }
}

// ============================================================
// M64 GEMM machinery: 64x128 block, 8 warps (2m x 4n), warp 32x32.
// Single-t variant (proj) and t-paired variant (qkv).
// ============================================================
#define B_STAGE_BYTES (128*24*2)
#define B2_STAGE_BYTES (256*24*2)
#define A64_STAGE_BYTES (2*64*24*2)
#define NSTG 4
#define GEMM64_SMEM   (NSTG*A64_STAGE_BYTES + NSTG*B_STAGE_BYTES)
#define GEMM64T2_SMEM (NSTG*A64_STAGE_BYTES + NSTG*B2_STAGE_BYTES)

__device__ __forceinline__ void load_stage_B(uint32_t bsb, int s, int kc,
                                             const __half* srcT, int rowbase, int tid) {
    int n = tid >> 1, h = tid & 1;
    const __half* src = srcT + ((size_t)(rowbase + n)) * 512 + kc + h*8;
    uint32_t dst = bsb + (uint32_t)(((s*128 + n)*24 + h*8) * 2);
    CP16(dst, src);
}
__device__ __forceinline__ void load_stage_B2(uint32_t bsb, int s, int kc,
                                              const __half* srcT, int rb0, int rb1, int tid) {
    int n = tid >> 1, h = tid & 1;
    CP16(bsb + (uint32_t)(((s*256 + n)*24 + h*8) * 2),
         srcT + ((size_t)(rb0 + n)) * 512 + kc + h*8);
    CP16(bsb + (uint32_t)(((s*256 + 128 + n)*24 + h*8) * 2),
         srcT + ((size_t)(rb1 + n)) * 512 + kc + h*8);
}
__device__ __forceinline__ void load_stage_A64(uint32_t asb, int s, int kc, int wmat, int mt, int tid) {
    int l = tid >> 7, rem = tid & 127;
    int o = rem >> 1, h = rem & 1;
    const __half* src = g_wl + ((size_t)(wmat*2 + l) * 512 + mt*64 + o) * 512 + kc + h*8;
    uint32_t dst = asb + (uint32_t)((((s*2 + l)*64 + o)*24 + h*8) * 2);
    CP16(dst, src);
}

// single-t pass (proj)
__device__ __forceinline__ void gemm_pass64(uint32_t asb, uint32_t bsb, float acc[2][4][4],
                                            int wmat, int mt, const __half* srcT, int rowbase,
                                            int tid, int wm, int wn, int lane) {
    #pragma unroll
    for (int p = 0; p < 3; p++) {
        load_stage_A64(asb, p, p*16, wmat, mt, tid);
        load_stage_B(bsb, p, p*16, srcT, rowbase, tid);
        CP_COMMIT();
    }
    int a_row = lane & 15, a_col = (lane >> 4) * 8;
    int b_row = wn + (lane & 7) + ((lane >> 4) << 3), b_col = lane & 8;

    int s = 0;
    for (int c = 0; c < 32; c++) {
        CP_WAIT(2);
        __syncthreads();
        if (c + 3 < 32) {
            int ns = s + 3; if (ns >= NSTG) ns -= NSTG;
            load_stage_A64(asb, ns, (c+3)*16, wmat, mt, tid);
            load_stage_B(bsb, ns, (c+3)*16, srcT, rowbase, tid);
        }
        CP_COMMIT();

        uint32_t bfr[4][2];
        #pragma unroll
        for (int jp = 0; jp < 2; jp++) {
            uint32_t r4[4];
            ldm_x4(r4, bsb + (uint32_t)((((s*128) + b_row + jp*16)*24 + b_col) * 2));
            bfr[jp*2][0] = r4[0];   bfr[jp*2][1] = r4[1];
            bfr[jp*2+1][0] = r4[2]; bfr[jp*2+1][1] = r4[3];
        }
        #pragma unroll
        for (int l = 0; l < 2; l++) {
            #pragma unroll
            for (int i = 0; i < 2; i++) {
                uint32_t a4[4];
                ldm_x4(a4, asb + (uint32_t)(((((s*2 + l)*64) + wm + i*16 + a_row)*24 + a_col) * 2));
                #pragma unroll
                for (int j = 0; j < 4; j++)
                    mma16816(acc[i][j], a4, bfr[j]);
            }
        }
        if (++s >= NSTG) s = 0;
    }
}

// t-paired pass (qkv): acc[t][i][j][4], A frags reused for both t.
__device__ __forceinline__ void gemm_pass64_t2(uint32_t asb, uint32_t bsb, float acc[2][2][4][4],
                                               int wmat, int mt, const __half* srcT,
                                               int rb0, int rb1,
                                               int tid, int wm, int wn, int lane) {
    #pragma unroll
    for (int p = 0; p < 3; p++) {
        load_stage_A64(asb, p, p*16, wmat, mt, tid);
        load_stage_B2(bsb, p, p*16, srcT, rb0, rb1, tid);
        CP_COMMIT();
    }
    int a_row = lane & 15, a_col = (lane >> 4) * 8;
    int b_row = wn + (lane & 7) + ((lane >> 4) << 3), b_col = lane & 8;

    int s = 0;
    for (int c = 0; c < 32; c++) {
        CP_WAIT(2);
        __syncthreads();
        if (c + 3 < 32) {
            int ns = s + 3; if (ns >= NSTG) ns -= NSTG;
            load_stage_A64(asb, ns, (c+3)*16, wmat, mt, tid);
            load_stage_B2(bsb, ns, (c+3)*16, srcT, rb0, rb1, tid);
        }
        CP_COMMIT();

        uint32_t bfr[2][4][2];
        #pragma unroll
        for (int t = 0; t < 2; t++) {
            #pragma unroll
            for (int jp = 0; jp < 2; jp++) {
                uint32_t r4[4];
                ldm_x4(r4, bsb + (uint32_t)((((s*256 + t*128) + b_row + jp*16)*24 + b_col) * 2));
                bfr[t][jp*2][0] = r4[0];   bfr[t][jp*2][1] = r4[1];
                bfr[t][jp*2+1][0] = r4[2]; bfr[t][jp*2+1][1] = r4[3];
            }
        }
        #pragma unroll
        for (int l = 0; l < 2; l++) {
            #pragma unroll
            for (int i = 0; i < 2; i++) {
                uint32_t a4[4];
                ldm_x4(a4, asb + (uint32_t)(((((s*2 + l)*64) + wm + i*16 + a_row)*24 + a_col) * 2));
                #pragma unroll
                for (int t = 0; t < 2; t++)
                    #pragma unroll
                    for (int j = 0; j < 4; j++)
                        mma16816(acc[t][i][j], a4, bfr[t][j]);
            }
        }
        if (++s >= NSTG) s = 0;
    }
}

// ============================================================
// K2: qkv GEMM (M64, t-paired) + BN + LIF.  q writes g_qT [n][c],
// k/v write [c][n]; all branches stage tiles in smem for coalesced
// uint4 stores.  grid.x=512, grid.y=3.
// ============================================================
__global__ __launch_bounds__(256, 2) void qkv_mma_kernel(
    const float* __restrict__ qg, const float* __restrict__ qb, const float* __restrict__ qm, const float* __restrict__ qv,
    const float* __restrict__ kg, const float* __restrict__ kb, const float* __restrict__ km, const float* __restrict__ kvv,
    const float* __restrict__ vg, const float* __restrict__ vb, const float* __restrict__ vmn, const float* __restrict__ vvv)
{
    extern __shared__ char dynsmem[];
    uint32_t asb = smem_u32(dynsmem), bsb = asb + NSTG*A64_STAGE_BYTES;
    int tid = threadIdx.x, lane = tid & 31, wid = tid >> 5;
    int wm = (wid & 1) * 32, wn = (wid >> 1) * 32;
    int bx = blockIdx.x, br = blockIdx.y;
    int nt = bx & 1, mt = (bx >> 1) & 7, b = bx >> 4;

    const float* G  = (br == 0) ? qg : (br == 1) ? kg : vg;
    const float* Bt = (br == 0) ? qb : (br == 1) ? kb : vb;
    const float* M  = (br == 0) ? qm : (br == 1) ? km : vmn;
    const float* V  = (br == 0) ? qv : (br == 1) ? kvv : vvv;
    __half* outp = (br == 1) ? g_kh : g_vh;

    float scl[2][2], mean[2][2], beta[2][2];
    #pragma unroll
    for (int i = 0; i < 2; i++)
        #pragma unroll
        for (int rh = 0; rh < 2; rh++) {
            int o = mt*64 + wm + i*16 + rh*8 + (lane >> 2);
            scl[i][rh]  = G[o] / sqrtf(V[o] + 1e-5f);
            mean[i][rh] = M[o];
            beta[i][rh] = Bt[o];
        }

    float vm[2][2][4][2];
    #pragma unroll
    for (int i = 0; i < 2; i++)
        #pragma unroll
        for (int rh = 0; rh < 2; rh++)
            #pragma unroll
            for (int j = 0; j < 4; j++) { vm[i][rh][j][0] = 0.f; vm[i][rh][j][1] = 0.f; }

    for (int tp = 0; tp < 2; tp++) {
        float acc[2][2][4][4];
        #pragma unroll
        for (int t = 0; t < 2; t++)
            #pragma unroll
            for (int i = 0; i < 2; i++)
                #pragma unroll
                for (int j = 0; j < 4; j++)
                    #pragma unroll
                    for (int p = 0; p < 4; p++) acc[t][i][j][p] = 0.f;

        int t0 = tp*2, t1 = tp*2 + 1;
        int rb0 = (t0*B_ + b) * 256 + nt*128;
        int rb1 = (t1*B_ + b) * 256 + nt*128;
        gemm_pass64_t2(asb, bsb, acc, br, mt, g_xsT, rb0, rb1, tid, wm, wn, lane);

        #pragma unroll
        for (int t01 = 0; t01 < 2; t01++) {
            int t = tp*2 + t01;
            if (br == 0) {
                __syncthreads();
                __half* Sq = (__half*)dynsmem;   // [n 128][o 64] stride 72
                #pragma unroll
                for (int i = 0; i < 2; i++) {
                    #pragma unroll
                    for (int j = 0; j < 4; j++) {
                        #pragma unroll
                        for (int rh = 0; rh < 2; rh++) {
                            float y0 = (acc[t01][i][j][rh*2+0] - mean[i][rh]) * scl[i][rh] + beta[i][rh];
                            float y1 = (acc[t01][i][j][rh*2+1] - mean[i][rh]) * scl[i][rh] + beta[i][rh];
                            float s0 = lif_step(vm[i][rh][j][0], y0, 1.0f);
                            float s1 = lif_step(vm[i][rh][j][1], y1, 1.0f);
                            int o_l = wm + i*16 + rh*8 + (lane >> 2);
                            int n_l = wn + j*8 + 2*(lane & 3);
                            Sq[n_l*72 + o_l]     = __float2half_rn(s0);
                            Sq[(n_l+1)*72 + o_l] = __float2half_rn(s1);
                        }
                    }
                }
                __syncthreads();
                #pragma unroll
                for (int r = 0; r < 2; r++) {
                    int idx = tid + r * 256;
                    int row = idx >> 3, chk = idx & 7;
                    *(uint4*)(g_qT + ((size_t)(t*B_ + b) * N_ + nt*128 + row) * C_ + mt*64 + chk*8) =
                        *(const uint4*)(&Sq[row*72 + chk*8]);
                }
                __syncthreads();
            } else {
                __syncthreads();
                __half* Sk = (__half*)dynsmem;   // [o 64][n 128] stride 136
                #pragma unroll
                for (int i = 0; i < 2; i++) {
                    #pragma unroll
                    for (int j = 0; j < 4; j++) {
                        #pragma unroll
                        for (int rh = 0; rh < 2; rh++) {
                            float y0 = (acc[t01][i][j][rh*2+0] - mean[i][rh]) * scl[i][rh] + beta[i][rh];
                            float y1 = (acc[t01][i][j][rh*2+1] - mean[i][rh]) * scl[i][rh] + beta[i][rh];
                            float s0 = lif_step(vm[i][rh][j][0], y0, 1.0f);
                            float s1 = lif_step(vm[i][rh][j][1], y1, 1.0f);
                            int o_l = wm + i*16 + rh*8 + (lane >> 2);
                            int n_l = wn + j*8 + 2*(lane & 3);
                            *(uint32_t*)(&Sk[o_l*136 + n_l]) = hpair(s0, s1);
                        }
                    }
                }
                __syncthreads();
                #pragma unroll
                for (int r = 0; r < 4; r++) {
                    int idx = tid + r * 256;           // 1024 uint4: 64 rows x 16 chunks
                    int row = idx >> 4, chk = idx & 15;
                    *(uint4*)(outp + ((size_t)(t*B_ + b) * C_ + mt*64 + row) * N_ + nt*128 + chk*8) =
                        *(const uint4*)(&Sk[row*136 + chk*8]);
                }
                __syncthreads();
            }
        }
    }
}

// ============================================================
// K3 fused (round-13 verified version): per (b,h) block: for each
// t, kv = 0.125*v@k^T via MMA (kept in smem), then a = q@kv^T via
// MMA, LIF(0.5), spikes -> g_sT.
// ============================================================
#define KA_AH 0
#define KA_BH (2*64*136*2)
#define KA_Q  (4*64*136*2)
#define KA_KV (KA_Q + 256*72*2)
#define KA_SMEM (KA_KV + 64*72*2)

__global__ __launch_bounds__(256, 1) void kvattn_kernel() {
    extern __shared__ char dynka[];
    uint32_t sb = smem_u32(dynka);
    uint32_t qbuf = sb + KA_Q, kvb = sb + KA_KV;
    int bh = blockIdx.x;
    int b = bh >> 3, hh = bh & 7;
    int tid = threadIdx.x, lane = tid & 31, wid = tid >> 5;

    int em = (wid & 3) * 16, dn = (wid >> 2) * 32;
    int nb = wid * 32;

    int a_row = lane & 15, a_col8 = (lane >> 4) * 8;
    int kb_row0 = dn + (lane & 7) + ((lane >> 4) << 3), kb_col = lane & 8;
    int ab_row0 = (lane & 7) + ((lane >> 4) << 3), ab_col = lane & 8;

    float vmn[2][8][4];
    #pragma unroll
    for (int i = 0; i < 2; i++)
        #pragma unroll
        for (int j = 0; j < 8; j++)
            #pragma unroll
            for (int p = 0; p < 4; p++) vmn[i][j][p] = 0.f;

    for (int t = 0; t < T_; t++) {
        int tb = t * B_ + b;
        const __half* vsrc = g_vh + ((size_t)tb * C_ + hh*64) * N_;
        const __half* ksrc = g_kh + ((size_t)tb * C_ + hh*64) * N_;

        #pragma unroll
        for (int r = 0; r < 8; r++) {
            int idx = tid + r * 256;
            int row = idx >> 3, chk = idx & 7;
            CP16(qbuf + (uint32_t)((row*72 + chk*8) * 2),
                 g_qT + ((size_t)tb * N_ + row) * C_ + hh*64 + chk*8);
        }
        #pragma unroll
        for (int r = 0; r < 2; r++) {
            int idx = tid + r * 256;
            int row = idx >> 3, chk = idx & 7;
            CP16(sb + KA_AH + (uint32_t)((row*136 + chk*8) * 2), vsrc + (size_t)row * N_ + chk*8);
            CP16(sb + KA_BH + (uint32_t)((row*136 + chk*8) * 2), ksrc + (size_t)row * N_ + chk*8);
        }
        CP_COMMIT();
        #pragma unroll
        for (int r = 0; r < 2; r++) {
            int idx = tid + r * 256;
            int row = idx >> 3, chk = idx & 7;
            CP16(sb + KA_AH + (uint32_t)(((64 + row)*136 + chk*8) * 2), vsrc + (size_t)row * N_ + 128 + chk*8);
            CP16(sb + KA_BH + (uint32_t)(((64 + row)*136 + chk*8) * 2), ksrc + (size_t)row * N_ + 128 + chk*8);
        }
        CP_COMMIT();

        float kacc[4][4];
        #pragma unroll
        for (int j = 0; j < 4; j++)
            #pragma unroll
            for (int p = 0; p < 4; p++) kacc[j][p] = 0.f;

        #pragma unroll
        for (int ch = 0; ch < 2; ch++) {
            if (ch == 0) CP_WAIT(1); else CP_WAIT(0);
            __syncthreads();
            uint32_t ahb = sb + KA_AH + ch * (64*136*2);
            uint32_t bhb = sb + KA_BH + ch * (64*136*2);
            #pragma unroll
            for (int ks = 0; ks < 8; ks++) {
                int kc = ks * 16;
                uint32_t bfr[4][2];
                #pragma unroll
                for (int jp = 0; jp < 2; jp++) {
                    uint32_t r4[4];
                    ldm_x4(r4, bhb + (uint32_t)(((kb_row0 + jp*16)*136 + kc + kb_col) * 2));
                    bfr[jp*2][0] = r4[0];   bfr[jp*2][1] = r4[1];
                    bfr[jp*2+1][0] = r4[2]; bfr[jp*2+1][1] = r4[3];
                }
                uint32_t a4[4];
                ldm_x4(a4, ahb + (uint32_t)(((em + a_row)*136 + kc + a_col8) * 2));
                #pragma unroll
                for (int j = 0; j < 4; j++)
                    mma16816(kacc[j], a4, bfr[j]);
            }
        }

        __syncthreads();
        #pragma unroll
        for (int j = 0; j < 4; j++) {
            int e0 = em + (lane >> 2);
            int d0 = dn + j*8 + 2*(lane & 3);
            *(uint32_t*)(dynka + KA_KV + ((e0)*72 + d0) * 2)     = hpair(kacc[j][0] * 0.125f, kacc[j][1] * 0.125f);
            *(uint32_t*)(dynka + KA_KV + ((e0 + 8)*72 + d0) * 2) = hpair(kacc[j][2] * 0.125f, kacc[j][3] * 0.125f);
        }
        __syncthreads();

        float acc[2][8][4];
        #pragma unroll
        for (int i = 0; i < 2; i++)
            #pragma unroll
            for (int j = 0; j < 8; j++)
                #pragma unroll
                for (int p = 0; p < 4; p++) acc[i][j][p] = 0.f;

        #pragma unroll
        for (int ks = 0; ks < 4; ks++) {
            int kc = ks * 16;
            uint32_t bfr[8][2];
            #pragma unroll
            for (int jp = 0; jp < 4; jp++) {
                uint32_t r4[4];
                ldm_x4(r4, kvb + (uint32_t)(((ab_row0 + jp*16)*72 + kc + ab_col) * 2));
                bfr[jp*2][0] = r4[0];   bfr[jp*2][1] = r4[1];
                bfr[jp*2+1][0] = r4[2]; bfr[jp*2+1][1] = r4[3];
            }
            #pragma unroll
            for (int i = 0; i < 2; i++) {
                uint32_t a4[4];
                ldm_x4(a4, qbuf + (uint32_t)(((nb + i*16 + a_row)*72 + kc + a_col8) * 2));
                #pragma unroll
                for (int j = 0; j < 8; j++)
                    mma16816(acc[i][j], a4, bfr[j]);
            }
        }

        #pragma unroll
        for (int i = 0; i < 2; i++) {
            #pragma unroll
            for (int j = 0; j < 8; j++) {
                int n0 = nb + i*16 + (lane >> 2);
                int e0 = j*8 + 2*(lane & 3);
                float s0 = lif_step(vmn[i][j][0], acc[i][j][0], 0.5f);
                float s1 = lif_step(vmn[i][j][1], acc[i][j][1], 0.5f);
                float s2 = lif_step(vmn[i][j][2], acc[i][j][2], 0.5f);
                float s3 = lif_step(vmn[i][j][3], acc[i][j][3], 0.5f);
                *(uint32_t*)(g_sT + ((size_t)tb * N_ + n0) * C_ + hh*64 + e0) = hpair(s0, s1);
                *(uint32_t*)(g_sT + ((size_t)tb * N_ + n0 + 8) * C_ + hh*64 + e0) = hpair(s2, s3);
            }
        }
        __syncthreads();
    }
}

// ============================================================
// K4: proj GEMM (M64) + bias + BN -> d_out.  grid = 2048.
// ============================================================
__global__ __launch_bounds__(256, 2) void proj_mma_kernel(
    const float* __restrict__ pbias, const float* __restrict__ pg, const float* __restrict__ pb,
    const float* __restrict__ pm, const float* __restrict__ pv, float* __restrict__ out)
{
    extern __shared__ char dynsmem[];
    uint32_t asb = smem_u32(dynsmem), bsb = asb + NSTG*A64_STAGE_BYTES;
    int tid = threadIdx.x, lane = tid & 31, wid = tid >> 5;
    int wm = (wid & 1) * 32, wn = (wid >> 1) * 32;
    int bx = blockIdx.x;
    int nt = bx & 1, mt = (bx >> 1) & 7, tb = bx >> 4;

    float scl[2][2], mean[2][2], beta[2][2], bias[2][2];
    #pragma unroll
    for (int i = 0; i < 2; i++)
        #pragma unroll
        for (int rh = 0; rh < 2; rh++) {
            int o = mt*64 + wm + i*16 + rh*8 + (lane >> 2);
            scl[i][rh]  = pg[o] / sqrtf(pv[o] + 1e-5f);
            mean[i][rh] = pm[o];
            beta[i][rh] = pb[o];
            bias[i][rh] = pbias[o];
        }

    float acc[2][4][4];
    #pragma unroll
    for (int i = 0; i < 2; i++)
        #pragma unroll
        for (int j = 0; j < 4; j++)
            #pragma unroll
            for (int p = 0; p < 4; p++) acc[i][j][p] = 0.f;

    int rowbase = tb * 256 + nt*128;
    gemm_pass64(asb, bsb, acc, 3, mt, g_sT, rowbase, tid, wm, wn, lane);

    #pragma unroll
    for (int i = 0; i < 2; i++) {
        #pragma unroll
        for (int j = 0; j < 4; j++) {
            #pragma unroll
            for (int rh = 0; rh < 2; rh++) {
                float y0 = ((acc[i][j][rh*2+0] + bias[i][rh]) - mean[i][rh]) * scl[i][rh] + beta[i][rh];
                float y1 = ((acc[i][j][rh*2+1] + bias[i][rh]) - mean[i][rh]) * scl[i][rh] + beta[i][rh];
                int o = mt*64 + wm + i*16 + rh*8 + (lane >> 2);
                int n = nt*128 + wn + j*8 + 2*(lane & 3);
                *(float2*)(out + ((size_t)tb * C_ + o) * N_ + n) = make_float2(y0, y1);
            }
        }
    }
}

// ============================================================
extern "C" void kernel_launch(void* const* d_in, const int* in_sizes, int n_in,
                              void* d_out, int out_size) {
    (void)in_sizes; (void)n_in; (void)out_size;
    const float* x  = (const float*)d_in[0];
    const float* qw = (const float*)d_in[1];
    const float* qg = (const float*)d_in[2];
    const float* qb = (const float*)d_in[3];
    const float* qm = (const float*)d_in[4];
    const float* qv = (const float*)d_in[5];
    const float* kw = (const float*)d_in[6];
    const float* kg = (const float*)d_in[7];
    const float* kb = (const float*)d_in[8];
    const float* km = (const float*)d_in[9];
    const float* kvv= (const float*)d_in[10];
    const float* vw = (const float*)d_in[11];
    const float* vg = (const float*)d_in[12];
    const float* vb = (const float*)d_in[13];
    const float* vm = (const float*)d_in[14];
    const float* vv = (const float*)d_in[15];
    const float* pw    = (const float*)d_in[16];
    const float* pbias = (const float*)d_in[17];
    const float* pg    = (const float*)d_in[18];
    const float* pb    = (const float*)d_in[19];
    const float* pm    = (const float*)d_in[20];
    const float* pv    = (const float*)d_in[21];

    cudaFuncSetAttribute(qkv_mma_kernel, cudaFuncAttributeMaxDynamicSharedMemorySize, GEMM64T2_SMEM);
    cudaFuncSetAttribute(proj_mma_kernel, cudaFuncAttributeMaxDynamicSharedMemorySize, GEMM64_SMEM);
    cudaFuncSetAttribute(kvattn_kernel, cudaFuncAttributeMaxDynamicSharedMemorySize, KA_SMEM);

    prep_kernel<<<2048, 256>>>(x, qw, kw, vw, pw);
    qkv_mma_kernel<<<dim3(512, 3), 256, GEMM64T2_SMEM>>>(qg, qb, qm, qv, kg, kb, km, kvv, vg, vb, vm, vv);
    kvattn_kernel<<<256, 256, KA_SMEM>>>();
    proj_mma_kernel<<<2048, 256, GEMM64_SMEM>>>(pbias, pg, pb, pm, pv, (float*)d_out);
}